// round 3
// baseline (speedup 1.0000x reference)
#include <cuda_runtime.h>
#include <cuda_bf16.h>
#include <math.h>
#include <stdint.h>

// Problem constants
#define NATOM 50000
#define MNBR  12
#define AFEA  128
#define NBRF  64
#define NM    (NATOM*MNBR)     // 600000
#define C2A   256
#define EPSV  1e-5f
#define GTILES (NM/96)         // 6250 row tiles of 96 (= 8 atoms)

// ---------------- scratch (device globals) ----------------------------------
__device__ float g_P1[(size_t)NATOM*C2A];
__device__ float g_P2[(size_t)NATOM*C2A];
__device__ float g_psum[(size_t)GTILES*C2A];
__device__ float g_psq [(size_t)GTILES*C2A];
__device__ float g_ns[NATOM*AFEA];
__device__ float g_colsum[C2A];
__device__ float g_colsq[C2A];
__device__ float g_cnt;
__device__ float g_scale2[AFEA], g_shift2[AFEA];

// ---------------- bf16 split + mma helpers ----------------------------------
__device__ __forceinline__ void bsplit(float x, __nv_bfloat16& h, __nv_bfloat16& l) {
    h = __float2bfloat16(x);
    l = __float2bfloat16(x - __bfloat162float(h));
}

// D += A(16x16 bf16) * B(16x8 bf16), fp32 accumulate.
__device__ __forceinline__ void mma_bf16(float* c, const uint32_t* a,
                                         uint32_t b0, uint32_t b1) {
    asm volatile(
        "mma.sync.aligned.m16n8k16.row.col.f32.bf16.bf16.f32 "
        "{%0,%1,%2,%3}, {%4,%5,%6,%7}, {%8,%9}, {%0,%1,%2,%3};\n"
        : "+f"(c[0]), "+f"(c[1]), "+f"(c[2]), "+f"(c[3])
        : "r"(a[0]), "r"(a[1]), "r"(a[2]), "r"(a[3]), "r"(b0), "r"(b1));
}

__device__ __forceinline__ float fast_sigmoid(float x) {
    return __fdividef(1.f, 1.f + __expf(-x));
}
__device__ __forceinline__ float fast_softplus(float x) {
    return fmaxf(x, 0.f) + __logf(1.f + __expf(-fabsf(x)));
}

// ---------------- K1: [P1|P2] cols tile computed together (A read once) -----
#define PA2 40
__global__ __launch_bounds__(256) void gemm_p12_tc(const float* __restrict__ atom,
                                                   const float* __restrict__ W) {
    __shared__ __align__(16) __nv_bfloat16 Ahi[128*PA2], Alo[128*PA2];
    __shared__ __align__(16) __nv_bfloat16 Bhi[128*PA2], Blo[128*PA2];

    const int tid = threadIdx.x;
    const int bx = blockIdx.x, by = blockIdx.y;   // by: 64-col slice 0..3
    const int w = tid >> 5, lane = tid & 31, g = lane >> 2, tig = lane & 3;
    const int cb = by * 64;

    float acc[16][4];
    #pragma unroll
    for (int j = 0; j < 16; j++) { acc[j][0]=0.f; acc[j][1]=0.f; acc[j][2]=0.f; acc[j][3]=0.f; }

    for (int kc = 0; kc < 4; kc++) {
        __syncthreads();
        // A chunk 128x32
        for (int i = tid; i < 128*32; i += 256) {
            int r = i >> 5, c = i & 31;
            int gr = bx*128 + r;
            float x = (gr < NATOM) ? atom[(size_t)gr*128 + kc*32 + c] : 0.f;
            bsplit(x, Ahi[r*PA2 + c], Alo[r*PA2 + c]);
        }
        // B chunk 32x128: n<64 -> W1 col cb+n; n>=64 -> W2 col cb+n-64
        for (int i = tid; i < 32*128; i += 256) {
            int k = i >> 7, n = i & 127;
            int wrow = kc*32 + k + ((n >= 64) ? 128 : 0);
            float x = W[(size_t)wrow*C2A + cb + (n & 63)];
            bsplit(x, Bhi[n*PA2 + k], Blo[n*PA2 + k]);
        }
        __syncthreads();

        #pragma unroll
        for (int ks = 0; ks < 2; ks++) {
            const int k0 = ks * 16;
            const int r0 = (w*16 + g) * PA2, r1 = (w*16 + g + 8) * PA2;
            uint32_t ah[4], al[4];
            ah[0] = *(const uint32_t*)&Ahi[r0 + k0 + 2*tig];
            ah[1] = *(const uint32_t*)&Ahi[r1 + k0 + 2*tig];
            ah[2] = *(const uint32_t*)&Ahi[r0 + k0 + 8 + 2*tig];
            ah[3] = *(const uint32_t*)&Ahi[r1 + k0 + 8 + 2*tig];
            al[0] = *(const uint32_t*)&Alo[r0 + k0 + 2*tig];
            al[1] = *(const uint32_t*)&Alo[r1 + k0 + 2*tig];
            al[2] = *(const uint32_t*)&Alo[r0 + k0 + 8 + 2*tig];
            al[3] = *(const uint32_t*)&Alo[r1 + k0 + 8 + 2*tig];
            #pragma unroll
            for (int j = 0; j < 16; j++) {
                const int nb = (j*8 + g) * PA2;
                uint32_t bh0 = *(const uint32_t*)&Bhi[nb + k0 + 2*tig];
                uint32_t bh1 = *(const uint32_t*)&Bhi[nb + k0 + 8 + 2*tig];
                uint32_t bl0 = *(const uint32_t*)&Blo[nb + k0 + 2*tig];
                uint32_t bl1 = *(const uint32_t*)&Blo[nb + k0 + 8 + 2*tig];
                mma_bf16(acc[j], ah, bh0, bh1);
                mma_bf16(acc[j], ah, bl0, bl1);
                mma_bf16(acc[j], al, bh0, bh1);
            }
        }
    }

    const int gr0 = bx*128 + w*16 + g;
    const int gr1 = gr0 + 8;
    #pragma unroll
    for (int j = 0; j < 16; j++) {
        float* Cdst = (j < 8) ? g_P1 : g_P2;
        const int c = cb + (j & 7)*8 + 2*tig;
        if (gr0 < NATOM)
            *(float2*)&Cdst[(size_t)gr0*C2A + c] = make_float2(acc[j][0], acc[j][1]);
        if (gr1 < NATOM)
            *(float2*)&Cdst[(size_t)gr1*C2A + c] = make_float2(acc[j][2], acc[j][3]);
    }
}

// ---------------- K2: stats pass (no gated store) ---------------------------
#define PA 72
__global__ __launch_bounds__(192) void stats_pass(const float* __restrict__ nbr,
                                                  const float* __restrict__ W,
                                                  const float* __restrict__ bfc,
                                                  const int*   __restrict__ idx,
                                                  const float* __restrict__ mask) {
    __shared__ __align__(16) __nv_bfloat16 Ahi[96*PA], Alo[96*PA];
    __shared__ __align__(16) __nv_bfloat16 Bhi[64*PA], Blo[64*PA];
    __shared__ float SRed[6*64];

    const int tid = threadIdx.x;
    const int bx = blockIdx.x;
    const int w = tid >> 5, lane = tid & 31, g = lane >> 2, tig = lane & 3;
    const float* W3 = W + 256*C2A;

    for (int i = tid; i < 96*64/4; i += 192) {
        int r = i >> 4, c4 = (i & 15) * 4;
        float4 v = *(const float4*)&nbr[((size_t)bx*96 + r)*64 + c4];
        bsplit(v.x, Ahi[r*PA + c4 + 0], Alo[r*PA + c4 + 0]);
        bsplit(v.y, Ahi[r*PA + c4 + 1], Alo[r*PA + c4 + 1]);
        bsplit(v.z, Ahi[r*PA + c4 + 2], Alo[r*PA + c4 + 2]);
        bsplit(v.w, Ahi[r*PA + c4 + 3], Alo[r*PA + c4 + 3]);
    }

    const int gr0 = bx*96 + w*16 + g;
    const int gr1 = gr0 + 8;
    const int n0 = gr0 / MNBR, n1 = gr1 / MNBR;
    const int nb0 = idx[gr0], nb1 = idx[gr1];
    const float mk0 = mask[gr0], mk1 = mask[gr1];

    for (int by = 0; by < 4; by++) {
        __syncthreads();
        for (int i = tid; i < 64*64; i += 192) {
            int k = i >> 6, n = i & 63;
            float x = W3[(size_t)k*C2A + by*64 + n];
            bsplit(x, Bhi[n*PA + k], Blo[n*PA + k]);
        }
        __syncthreads();

        float acc[8][4];
        #pragma unroll
        for (int j = 0; j < 8; j++) { acc[j][0]=0.f; acc[j][1]=0.f; acc[j][2]=0.f; acc[j][3]=0.f; }

        #pragma unroll
        for (int ks = 0; ks < 4; ks++) {
            const int k0 = ks * 16;
            const int r0 = (w*16 + g) * PA, r1 = (w*16 + g + 8) * PA;
            uint32_t ah[4], al[4];
            ah[0] = *(const uint32_t*)&Ahi[r0 + k0 + 2*tig];
            ah[1] = *(const uint32_t*)&Ahi[r1 + k0 + 2*tig];
            ah[2] = *(const uint32_t*)&Ahi[r0 + k0 + 8 + 2*tig];
            ah[3] = *(const uint32_t*)&Ahi[r1 + k0 + 8 + 2*tig];
            al[0] = *(const uint32_t*)&Alo[r0 + k0 + 2*tig];
            al[1] = *(const uint32_t*)&Alo[r1 + k0 + 2*tig];
            al[2] = *(const uint32_t*)&Alo[r0 + k0 + 8 + 2*tig];
            al[3] = *(const uint32_t*)&Alo[r1 + k0 + 8 + 2*tig];
            #pragma unroll
            for (int j = 0; j < 8; j++) {
                const int nb = (j*8 + g) * PA;
                uint32_t bh0 = *(const uint32_t*)&Bhi[nb + k0 + 2*tig];
                uint32_t bh1 = *(const uint32_t*)&Bhi[nb + k0 + 8 + 2*tig];
                uint32_t bl0 = *(const uint32_t*)&Blo[nb + k0 + 2*tig];
                uint32_t bl1 = *(const uint32_t*)&Blo[nb + k0 + 8 + 2*tig];
                mma_bf16(acc[j], ah, bh0, bh1);
                mma_bf16(acc[j], ah, bl0, bl1);
                mma_bf16(acc[j], al, bh0, bh1);
            }
        }

        const int byc = by * 64;
        float s16[16], q16[16];
        #pragma unroll
        for (int t = 0; t < 16; t++) { s16[t] = 0.f; q16[t] = 0.f; }

        #pragma unroll
        for (int j = 0; j < 8; j++) {
            const int c = byc + j*8 + 2*tig;
            float2 bb  = *(const float2*)&bfc[c];
            float2 p10 = *(const float2*)&g_P1[(size_t)n0*C2A + c];
            float2 p20 = *(const float2*)&g_P2[(size_t)nb0*C2A + c];
            float v00 = acc[j][0] + bb.x + p10.x + p20.x;
            float v01 = acc[j][1] + bb.y + p10.y + p20.y;
            float2 p11 = *(const float2*)&g_P1[(size_t)n1*C2A + c];
            float2 p21 = *(const float2*)&g_P2[(size_t)nb1*C2A + c];
            float v10 = acc[j][2] + bb.x + p11.x + p21.x;
            float v11 = acc[j][3] + bb.y + p11.y + p21.y;
            s16[2*j]   += mk0*v00 + mk1*v10;
            s16[2*j+1] += mk0*v01 + mk1*v11;
            q16[2*j]   += mk0*v00*v00 + mk1*v10*v10;
            q16[2*j+1] += mk0*v01*v01 + mk1*v11*v11;
        }

        #pragma unroll
        for (int t = 0; t < 16; t++) {
            #pragma unroll
            for (int off = 4; off <= 16; off <<= 1) {
                s16[t] += __shfl_xor_sync(0xffffffffu, s16[t], off);
                q16[t] += __shfl_xor_sync(0xffffffffu, q16[t], off);
            }
        }
        if (lane < 4) {
            #pragma unroll
            for (int j = 0; j < 8; j++) {
                SRed[w*64 + j*8 + 2*lane + 0] = s16[2*j];
                SRed[w*64 + j*8 + 2*lane + 1] = s16[2*j+1];
            }
        }
        __syncthreads();
        if (tid < 64) {
            float t = 0.f;
            #pragma unroll
            for (int w2 = 0; w2 < 6; w2++) t += SRed[w2*64 + tid];
            g_psum[(size_t)bx*C2A + byc + tid] = t;
        }
        __syncthreads();
        if (lane < 4) {
            #pragma unroll
            for (int j = 0; j < 8; j++) {
                SRed[w*64 + j*8 + 2*lane + 0] = q16[2*j];
                SRed[w*64 + j*8 + 2*lane + 1] = q16[2*j+1];
            }
        }
        __syncthreads();
        if (tid < 64) {
            float t = 0.f;
            #pragma unroll
            for (int w2 = 0; w2 < 6; w2++) t += SRed[w2*64 + tid];
            g_psq[(size_t)bx*C2A + byc + tid] = t;
        }
    }
}

// ---------------- K3: reduce partials -> column sums; also cnt --------------
__global__ __launch_bounds__(256) void reduce1(const float* __restrict__ mask) {
    __shared__ float sm[256];
    const int b = blockIdx.x, tid = threadIdx.x;
    float s = 0.f;
    if (b < 256) {
        for (int i = tid; i < GTILES; i += 256) s += g_psum[(size_t)i * C2A + b];
    } else if (b < 512) {
        int c = b - 256;
        for (int i = tid; i < GTILES; i += 256) s += g_psq[(size_t)i * C2A + c];
    } else {
        for (int i = tid; i < NM; i += 256) s += mask[i];
    }
    sm[tid] = s; __syncthreads();
    for (int off = 128; off > 0; off >>= 1) {
        if (tid < off) sm[tid] += sm[tid + off];
        __syncthreads();
    }
    if (tid == 0) {
        if (b < 256)      g_colsum[b] = sm[0];
        else if (b < 512) g_colsq[b - 256] = sm[0];
        else              g_cnt = sm[0];
    }
}

// ---------------- K4: fused pass2: GEMM + BN1 + gate + per-atom sum ---------
// Dynamic smem layout (bytes):
//   Ahi 0..13824, Alo ..27648, Bhi(128xPA) ..46080, Blo ..64512,
//   Sg(96x65 f32) ..89472, s1s(256 f32) ..90496, s1b ..91520
__global__ __launch_bounds__(192) void gate_fused(const float* __restrict__ nbr,
                                                  const float* __restrict__ W,
                                                  const float* __restrict__ bfc,
                                                  const int*   __restrict__ idx,
                                                  const float* __restrict__ mask,
                                                  const float* __restrict__ gamma1,
                                                  const float* __restrict__ beta1) {
    extern __shared__ __align__(16) char smem[];
    __nv_bfloat16* Ahi = (__nv_bfloat16*)(smem);
    __nv_bfloat16* Alo = (__nv_bfloat16*)(smem + 13824);
    __nv_bfloat16* Bhi = (__nv_bfloat16*)(smem + 27648);
    __nv_bfloat16* Blo = (__nv_bfloat16*)(smem + 46080);
    float* Sg  = (float*)(smem + 64512);
    float* s1s = (float*)(smem + 89472);
    float* s1b = (float*)(smem + 90496);

    const int tid = threadIdx.x;
    const int bx = blockIdx.x;
    const int w = tid >> 5, lane = tid & 31, g = lane >> 2, tig = lane & 3;
    const float* W3 = W + 256*C2A;

    // BN1 affine coefficients (each block computes its own copy)
    {
        float cnt = g_cnt;
        for (int c = tid; c < C2A; c += 192) {
            float mean = g_colsum[c] / cnt;
            float var  = g_colsq[c] / cnt - mean * mean;
            float sc   = rsqrtf(var + EPSV) * gamma1[c];
            s1s[c] = sc;
            s1b[c] = beta1[c] - mean * sc;
        }
    }

    // A tile 96x64
    for (int i = tid; i < 96*64/4; i += 192) {
        int r = i >> 4, c4 = (i & 15) * 4;
        float4 v = *(const float4*)&nbr[((size_t)bx*96 + r)*64 + c4];
        bsplit(v.x, Ahi[r*PA + c4 + 0], Alo[r*PA + c4 + 0]);
        bsplit(v.y, Ahi[r*PA + c4 + 1], Alo[r*PA + c4 + 1]);
        bsplit(v.z, Ahi[r*PA + c4 + 2], Alo[r*PA + c4 + 2]);
        bsplit(v.w, Ahi[r*PA + c4 + 3], Alo[r*PA + c4 + 3]);
    }

    const int gr0 = bx*96 + w*16 + g;
    const int gr1 = gr0 + 8;
    const int n0 = gr0 / MNBR, n1 = gr1 / MNBR;
    const int nb0 = idx[gr0], nb1 = idx[gr1];
    const float mk0 = mask[gr0], mk1 = mask[gr1];
    const int rl0 = w*16 + g, rl1 = rl0 + 8;   // local rows

    for (int by = 0; by < 2; by++) {
        __syncthreads();
        // B tile 64k x 128n: n<64 -> filter col by*64+n; n>=64 -> core col 128+by*64+n-64
        for (int i = tid; i < 64*128; i += 192) {
            int k = i >> 7, n = i & 127;
            int col = (n < 64) ? (by*64 + n) : (128 + by*64 + (n - 64));
            float x = W3[(size_t)k*C2A + col];
            bsplit(x, Bhi[n*PA + k], Blo[n*PA + k]);
        }
        __syncthreads();

        float acc[16][4];
        #pragma unroll
        for (int j = 0; j < 16; j++) { acc[j][0]=0.f; acc[j][1]=0.f; acc[j][2]=0.f; acc[j][3]=0.f; }

        #pragma unroll
        for (int ks = 0; ks < 4; ks++) {
            const int k0 = ks * 16;
            const int r0 = rl0 * PA, r1 = rl1 * PA;
            uint32_t ah[4], al[4];
            ah[0] = *(const uint32_t*)&Ahi[r0 + k0 + 2*tig];
            ah[1] = *(const uint32_t*)&Ahi[r1 + k0 + 2*tig];
            ah[2] = *(const uint32_t*)&Ahi[r0 + k0 + 8 + 2*tig];
            ah[3] = *(const uint32_t*)&Ahi[r1 + k0 + 8 + 2*tig];
            al[0] = *(const uint32_t*)&Alo[r0 + k0 + 2*tig];
            al[1] = *(const uint32_t*)&Alo[r1 + k0 + 2*tig];
            al[2] = *(const uint32_t*)&Alo[r0 + k0 + 8 + 2*tig];
            al[3] = *(const uint32_t*)&Alo[r1 + k0 + 8 + 2*tig];
            #pragma unroll
            for (int j = 0; j < 16; j++) {
                const int nb = (j*8 + g) * PA;
                uint32_t bh0 = *(const uint32_t*)&Bhi[nb + k0 + 2*tig];
                uint32_t bh1 = *(const uint32_t*)&Bhi[nb + k0 + 8 + 2*tig];
                uint32_t bl0 = *(const uint32_t*)&Blo[nb + k0 + 2*tig];
                uint32_t bl1 = *(const uint32_t*)&Blo[nb + k0 + 8 + 2*tig];
                mma_bf16(acc[j], ah, bh0, bh1);
                mma_bf16(acc[j], ah, bl0, bl1);
                mma_bf16(acc[j], al, bh0, bh1);
            }
        }

        // Stage gate values (j: filter, j+8: core)
        #pragma unroll
        for (int j = 0; j < 8; j++) {
            const int cc = j*8 + 2*tig;
            const int fcol = by*64 + cc;
            const int ccol = 128 + by*64 + cc;
            float2 bbf = *(const float2*)&bfc[fcol];
            float2 bbc = *(const float2*)&bfc[ccol];
            float sf0 = s1s[fcol], sf1 = s1s[fcol+1], bf0 = s1b[fcol], bf1 = s1b[fcol+1];
            float sc0 = s1s[ccol], sc1 = s1s[ccol+1], bc0 = s1b[ccol], bc1 = s1b[ccol+1];

            // row 0
            {
                float2 p1f = *(const float2*)&g_P1[(size_t)n0*C2A + fcol];
                float2 p2f = *(const float2*)&g_P2[(size_t)nb0*C2A + fcol];
                float2 p1c = *(const float2*)&g_P1[(size_t)n0*C2A + ccol];
                float2 p2c = *(const float2*)&g_P2[(size_t)nb0*C2A + ccol];
                float f0 = (acc[j][0]   + bbf.x + p1f.x + p2f.x) * sf0 + bf0;
                float f1 = (acc[j][1]   + bbf.y + p1f.y + p2f.y) * sf1 + bf1;
                float c0 = (acc[j+8][0] + bbc.x + p1c.x + p2c.x) * sc0 + bc0;
                float c1 = (acc[j+8][1] + bbc.y + p1c.y + p2c.y) * sc1 + bc1;
                Sg[rl0*65 + cc + 0] = mk0 * fast_sigmoid(f0) * fast_softplus(c0);
                Sg[rl0*65 + cc + 1] = mk0 * fast_sigmoid(f1) * fast_softplus(c1);
            }
            // row 1
            {
                float2 p1f = *(const float2*)&g_P1[(size_t)n1*C2A + fcol];
                float2 p2f = *(const float2*)&g_P2[(size_t)nb1*C2A + fcol];
                float2 p1c = *(const float2*)&g_P1[(size_t)n1*C2A + ccol];
                float2 p2c = *(const float2*)&g_P2[(size_t)nb1*C2A + ccol];
                float f0 = (acc[j][2]   + bbf.x + p1f.x + p2f.x) * sf0 + bf0;
                float f1 = (acc[j][3]   + bbf.y + p1f.y + p2f.y) * sf1 + bf1;
                float c0 = (acc[j+8][2] + bbc.x + p1c.x + p2c.x) * sc0 + bc0;
                float c1 = (acc[j+8][3] + bbc.y + p1c.y + p2c.y) * sc1 + bc1;
                Sg[rl1*65 + cc + 0] = mk1 * fast_sigmoid(f0) * fast_softplus(c0);
                Sg[rl1*65 + cc + 1] = mk1 * fast_sigmoid(f1) * fast_softplus(c1);
            }
        }
        __syncthreads();

        // Per-atom reduction over 12 neighbors: 8 atoms x 64 cols
        for (int o = tid; o < 512; o += 192) {
            int a = o >> 6, col = o & 63;
            float s = 0.f;
            #pragma unroll
            for (int m = 0; m < MNBR; m++) s += Sg[(a*MNBR + m)*65 + col];
            g_ns[(size_t)(bx*8 + a)*AFEA + by*64 + col] = s;
        }
    }
}

// ---------------- K5: BN2 stats + affine ------------------------------------
__global__ __launch_bounds__(256) void reduce2(const float* __restrict__ gamma2,
                                               const float* __restrict__ beta2) {
    __shared__ float ss[256], sq[256];
    const int c = blockIdx.x, tid = threadIdx.x;
    float s = 0.f, q = 0.f;
    for (int r = tid; r < NATOM; r += 256) {
        float v = g_ns[(size_t)r * AFEA + c];
        s += v; q += v * v;
    }
    ss[tid] = s; sq[tid] = q; __syncthreads();
    for (int off = 128; off > 0; off >>= 1) {
        if (tid < off) { ss[tid] += ss[tid + off]; sq[tid] += sq[tid + off]; }
        __syncthreads();
    }
    if (tid == 0) {
        float mean = ss[0] / (float)NATOM;
        float var  = sq[0] / (float)NATOM - mean * mean;
        float sc   = rsqrtf(var + EPSV) * gamma2[c];
        g_scale2[c] = sc;
        g_shift2[c] = beta2[c] - mean * sc;
    }
}

// ---------------- K6: out = softplus(atom + BN2(nbr_sumed)) -----------------
__global__ __launch_bounds__(256) void out_k(const float* __restrict__ atom,
                                             float* __restrict__ out) {
    int i = blockIdx.x * 256 + threadIdx.x;
    if (i < NATOM * AFEA) {
        int c = i & 127;
        float v = atom[i] + g_ns[i] * g_scale2[c] + g_shift2[c];
        out[i] = fmaxf(v, 0.f) + __logf(1.f + __expf(-fabsf(v)));
    }
}

// ---------------- launch ----------------------------------------------------
extern "C" void kernel_launch(void* const* d_in, const int* in_sizes, int n_in,
                              void* d_out, int out_size) {
    const float* atom  = (const float*)d_in[0];
    const float* nbr   = (const float*)d_in[1];
    const int*   idx   = (const int*)  d_in[2];
    const float* mask  = (const float*)d_in[3];
    const float* W     = (const float*)d_in[4];
    const float* bfc   = (const float*)d_in[5];
    const float* g1    = (const float*)d_in[6];
    const float* b1    = (const float*)d_in[7];
    const float* g2    = (const float*)d_in[8];
    const float* b2    = (const float*)d_in[9];
    float* out = (float*)d_out;

    cudaFuncSetAttribute(gate_fused, cudaFuncAttributeMaxDynamicSharedMemorySize, 92160);

    gemm_p12_tc<<<dim3((NATOM + 127) / 128, 4), 256>>>(atom, W);      // idx 0
    stats_pass <<<GTILES, 192>>>(nbr, W, bfc, idx, mask);             // idx 1
    reduce1    <<<513, 256>>>(mask);                                  // idx 2
    gate_fused <<<GTILES, 192, 92160>>>(nbr, W, bfc, idx, mask, g1, b1); // idx 3 (profiled slot)
    reduce2    <<<AFEA, 256>>>(g2, b2);                               // idx 4
    out_k      <<<(NATOM * AFEA + 255) / 256, 256>>>(atom, out);      // idx 5
}

// round 4
// speedup vs baseline: 1.3092x; 1.3092x over previous
#include <cuda_runtime.h>
#include <cuda_bf16.h>
#include <math.h>
#include <stdint.h>

// Problem constants
#define NATOM 50000
#define MNBR  12
#define AFEA  128
#define NBRF  64
#define NM    (NATOM*MNBR)     // 600000
#define C2A   256
#define EPSV  1e-5f
#define GTILES (NM/96)         // 6250 row tiles of 96 (= 8 atoms)

// ---------------- scratch (device globals) ----------------------------------
__device__ float g_P1[(size_t)NATOM*C2A];
__device__ float g_P2[(size_t)NATOM*C2A];
__device__ float g_gated[(size_t)NM*C2A];
__device__ float g_psum[(size_t)GTILES*C2A];
__device__ float g_psq [(size_t)GTILES*C2A];
__device__ float g_ns[NATOM*AFEA];
__device__ float g_colsum[C2A];
__device__ float g_colsq[C2A];
__device__ float g_cnt;
__device__ float g_scale2[AFEA], g_shift2[AFEA];

// ---------------- helpers ----------------------------------------------------
__device__ __forceinline__ void bsplit(float x, __nv_bfloat16& h, __nv_bfloat16& l) {
    h = __float2bfloat16(x);
    l = __float2bfloat16(x - __bfloat162float(h));
}

__device__ __forceinline__ void mma_bf16(float* c, const uint32_t* a,
                                         uint32_t b0, uint32_t b1) {
    asm volatile(
        "mma.sync.aligned.m16n8k16.row.col.f32.bf16.bf16.f32 "
        "{%0,%1,%2,%3}, {%4,%5,%6,%7}, {%8,%9}, {%0,%1,%2,%3};\n"
        : "+f"(c[0]), "+f"(c[1]), "+f"(c[2]), "+f"(c[3])
        : "r"(a[0]), "r"(a[1]), "r"(a[2]), "r"(a[3]), "r"(b0), "r"(b1));
}

__device__ __forceinline__ void ldsm_x4(uint32_t addr, uint32_t& r0, uint32_t& r1,
                                        uint32_t& r2, uint32_t& r3) {
    asm volatile("ldmatrix.sync.aligned.m8n8.x4.shared.b16 {%0,%1,%2,%3}, [%4];"
                 : "=r"(r0), "=r"(r1), "=r"(r2), "=r"(r3) : "r"(addr));
}

__device__ __forceinline__ float fast_sigmoid(float x) {
    return __fdividef(1.f, 1.f + __expf(-x));
}
__device__ __forceinline__ float fast_softplus(float x) {
    return fmaxf(x, 0.f) + __logf(1.f + __expf(-fabsf(x)));
}

// ---------------- K1: [P1|P2] via tensor cores + ldmatrix -------------------
#define PA2 40
__global__ __launch_bounds__(256) void gemm_p12_tc(const float* __restrict__ atom,
                                                   const float* __restrict__ W) {
    __shared__ __align__(16) __nv_bfloat16 Ahi[128*PA2], Alo[128*PA2];
    __shared__ __align__(16) __nv_bfloat16 Bhi[128*PA2], Blo[128*PA2];

    const int tid = threadIdx.x;
    const int bx = blockIdx.x, by = blockIdx.y;   // by: 64-col slice 0..3
    const int w = tid >> 5, lane = tid & 31, g = lane >> 2, tig = lane & 3;
    const int cb = by * 64;
    const int m4 = lane >> 3, lr = lane & 7;

    // ldmatrix per-lane base offsets
    const uint32_t aHi0 = (uint32_t)__cvta_generic_to_shared(Ahi)
                        + ((w*16 + (m4 & 1)*8 + lr) * PA2 + (m4 >> 1)*8) * 2;
    const uint32_t aLo0 = (uint32_t)__cvta_generic_to_shared(Alo)
                        + ((w*16 + (m4 & 1)*8 + lr) * PA2 + (m4 >> 1)*8) * 2;
    const uint32_t bHi0 = (uint32_t)__cvta_generic_to_shared(Bhi)
                        + (((m4 >> 1)*8 + lr) * PA2 + (m4 & 1)*8) * 2;
    const uint32_t bLo0 = (uint32_t)__cvta_generic_to_shared(Blo)
                        + (((m4 >> 1)*8 + lr) * PA2 + (m4 & 1)*8) * 2;

    float acc[16][4];
    #pragma unroll
    for (int j = 0; j < 16; j++) { acc[j][0]=0.f; acc[j][1]=0.f; acc[j][2]=0.f; acc[j][3]=0.f; }

    for (int kc = 0; kc < 4; kc++) {
        __syncthreads();
        for (int i = tid; i < 128*32; i += 256) {          // A chunk 128x32
            int r = i >> 5, c = i & 31;
            int gr = bx*128 + r;
            float x = (gr < NATOM) ? atom[(size_t)gr*128 + kc*32 + c] : 0.f;
            bsplit(x, Ahi[r*PA2 + c], Alo[r*PA2 + c]);
        }
        for (int i = tid; i < 32*128; i += 256) {          // B chunk 32x128
            int k = i >> 7, n = i & 127;
            int wrow = kc*32 + k + ((n >= 64) ? 128 : 0);
            float x = W[(size_t)wrow*C2A + cb + (n & 63)];
            bsplit(x, Bhi[n*PA2 + k], Blo[n*PA2 + k]);
        }
        __syncthreads();

        #pragma unroll
        for (int ks = 0; ks < 2; ks++) {
            const uint32_t koff = ks * 16 * 2;
            uint32_t ah[4], al[4];
            ldsm_x4(aHi0 + koff, ah[0], ah[1], ah[2], ah[3]);
            ldsm_x4(aLo0 + koff, al[0], al[1], al[2], al[3]);
            #pragma unroll
            for (int jp = 0; jp < 8; jp++) {
                const uint32_t boff = (uint32_t)(jp*16*PA2*2) + koff;
                uint32_t bh0, bh1, bh2, bh3, bl0, bl1, bl2, bl3;
                ldsm_x4(bHi0 + boff, bh0, bh1, bh2, bh3);
                ldsm_x4(bLo0 + boff, bl0, bl1, bl2, bl3);
                mma_bf16(acc[2*jp],   ah, bh0, bh1);
                mma_bf16(acc[2*jp],   ah, bl0, bl1);
                mma_bf16(acc[2*jp],   al, bh0, bh1);
                mma_bf16(acc[2*jp+1], ah, bh2, bh3);
                mma_bf16(acc[2*jp+1], ah, bl2, bl3);
                mma_bf16(acc[2*jp+1], al, bh2, bh3);
            }
        }
    }

    const int gr0 = bx*128 + w*16 + g;
    const int gr1 = gr0 + 8;
    #pragma unroll
    for (int j = 0; j < 16; j++) {
        float* Cdst = (j < 8) ? g_P1 : g_P2;
        const int c = cb + (j & 7)*8 + 2*tig;
        if (gr0 < NATOM)
            *(float2*)&Cdst[(size_t)gr0*C2A + c] = make_float2(acc[j][0], acc[j][1]);
        if (gr1 < NATOM)
            *(float2*)&Cdst[(size_t)gr1*C2A + c] = make_float2(acc[j][2], acc[j][3]);
    }
}

// ---------------- K2: gated = nbr@W3 + b + P1 + P2[idx]; store+stats --------
#define PA 72
__global__ __launch_bounds__(192) void gemm_gated_tc(const float* __restrict__ nbr,
                                                     const float* __restrict__ W,
                                                     const float* __restrict__ bfc,
                                                     const int*   __restrict__ idx,
                                                     const float* __restrict__ mask,
                                                     int bx0) {
    __shared__ __align__(16) __nv_bfloat16 Ahi[96*PA], Alo[96*PA];
    __shared__ __align__(16) __nv_bfloat16 Bhi[64*PA], Blo[64*PA];
    __shared__ float SRed[6*64];

    const int tid = threadIdx.x;
    const int bx = blockIdx.x + bx0;
    const int w = tid >> 5, lane = tid & 31, g = lane >> 2, tig = lane & 3;
    const float* W3 = W + 256*C2A;
    const int m4 = lane >> 3, lr = lane & 7;

    const uint32_t aHi0 = (uint32_t)__cvta_generic_to_shared(Ahi)
                        + ((w*16 + (m4 & 1)*8 + lr) * PA + (m4 >> 1)*8) * 2;
    const uint32_t aLo0 = (uint32_t)__cvta_generic_to_shared(Alo)
                        + ((w*16 + (m4 & 1)*8 + lr) * PA + (m4 >> 1)*8) * 2;
    const uint32_t bHi0 = (uint32_t)__cvta_generic_to_shared(Bhi)
                        + (((m4 >> 1)*8 + lr) * PA + (m4 & 1)*8) * 2;
    const uint32_t bLo0 = (uint32_t)__cvta_generic_to_shared(Blo)
                        + (((m4 >> 1)*8 + lr) * PA + (m4 & 1)*8) * 2;

    for (int i = tid; i < 96*64/4; i += 192) {
        int r = i >> 4, c4 = (i & 15) * 4;
        float4 v = *(const float4*)&nbr[((size_t)bx*96 + r)*64 + c4];
        bsplit(v.x, Ahi[r*PA + c4 + 0], Alo[r*PA + c4 + 0]);
        bsplit(v.y, Ahi[r*PA + c4 + 1], Alo[r*PA + c4 + 1]);
        bsplit(v.z, Ahi[r*PA + c4 + 2], Alo[r*PA + c4 + 2]);
        bsplit(v.w, Ahi[r*PA + c4 + 3], Alo[r*PA + c4 + 3]);
    }

    const int gr0 = bx*96 + w*16 + g;
    const int gr1 = gr0 + 8;
    const int n0 = gr0 / MNBR, n1 = gr1 / MNBR;
    const int nb0 = idx[gr0], nb1 = idx[gr1];
    const float mk0 = mask[gr0], mk1 = mask[gr1];

    for (int by = 0; by < 4; by++) {
        __syncthreads();
        for (int i = tid; i < 64*64; i += 192) {
            int k = i >> 6, n = i & 63;
            float x = W3[(size_t)k*C2A + by*64 + n];
            bsplit(x, Bhi[n*PA + k], Blo[n*PA + k]);
        }
        __syncthreads();

        float acc[8][4];
        #pragma unroll
        for (int j = 0; j < 8; j++) { acc[j][0]=0.f; acc[j][1]=0.f; acc[j][2]=0.f; acc[j][3]=0.f; }

        #pragma unroll
        for (int ks = 0; ks < 4; ks++) {
            const uint32_t koff = ks * 16 * 2;
            uint32_t ah[4], al[4];
            ldsm_x4(aHi0 + koff, ah[0], ah[1], ah[2], ah[3]);
            ldsm_x4(aLo0 + koff, al[0], al[1], al[2], al[3]);
            #pragma unroll
            for (int jp = 0; jp < 4; jp++) {
                const uint32_t boff = (uint32_t)(jp*16*PA*2) + koff;
                uint32_t bh0, bh1, bh2, bh3, bl0, bl1, bl2, bl3;
                ldsm_x4(bHi0 + boff, bh0, bh1, bh2, bh3);
                ldsm_x4(bLo0 + boff, bl0, bl1, bl2, bl3);
                mma_bf16(acc[2*jp],   ah, bh0, bh1);
                mma_bf16(acc[2*jp],   ah, bl0, bl1);
                mma_bf16(acc[2*jp],   al, bh0, bh1);
                mma_bf16(acc[2*jp+1], ah, bh2, bh3);
                mma_bf16(acc[2*jp+1], ah, bl2, bl3);
                mma_bf16(acc[2*jp+1], al, bh2, bh3);
            }
        }

        // Epilogue: only live (mask!=0) rows are gathered/stored.
        const int byc = by * 64;
        float s16[16], q16[16];
        #pragma unroll
        for (int t = 0; t < 16; t++) { s16[t] = 0.f; q16[t] = 0.f; }

        if (mk0 != 0.f) {
            #pragma unroll
            for (int j = 0; j < 8; j++) {
                const int c = byc + j*8 + 2*tig;
                float2 bb  = *(const float2*)&bfc[c];
                float2 p10 = *(const float2*)&g_P1[(size_t)n0*C2A + c];
                float2 p20 = *(const float2*)&g_P2[(size_t)nb0*C2A + c];
                float v00 = acc[j][0] + bb.x + p10.x + p20.x;
                float v01 = acc[j][1] + bb.y + p10.y + p20.y;
                *(float2*)&g_gated[(size_t)gr0*C2A + c] = make_float2(v00, v01);
                s16[2*j]   += v00;  s16[2*j+1] += v01;
                q16[2*j]   += v00*v00;  q16[2*j+1] += v01*v01;
            }
        }
        if (mk1 != 0.f) {
            #pragma unroll
            for (int j = 0; j < 8; j++) {
                const int c = byc + j*8 + 2*tig;
                float2 bb  = *(const float2*)&bfc[c];
                float2 p11 = *(const float2*)&g_P1[(size_t)n1*C2A + c];
                float2 p21 = *(const float2*)&g_P2[(size_t)nb1*C2A + c];
                float v10 = acc[j][2] + bb.x + p11.x + p21.x;
                float v11 = acc[j][3] + bb.y + p11.y + p21.y;
                *(float2*)&g_gated[(size_t)gr1*C2A + c] = make_float2(v10, v11);
                s16[2*j]   += v10;  s16[2*j+1] += v11;
                q16[2*j]   += v10*v10;  q16[2*j+1] += v11*v11;
            }
        }

        #pragma unroll
        for (int t = 0; t < 16; t++) {
            #pragma unroll
            for (int off = 4; off <= 16; off <<= 1) {
                s16[t] += __shfl_xor_sync(0xffffffffu, s16[t], off);
                q16[t] += __shfl_xor_sync(0xffffffffu, q16[t], off);
            }
        }
        if (lane < 4) {
            #pragma unroll
            for (int j = 0; j < 8; j++) {
                SRed[w*64 + j*8 + 2*lane + 0] = s16[2*j];
                SRed[w*64 + j*8 + 2*lane + 1] = s16[2*j+1];
            }
        }
        __syncthreads();
        if (tid < 64) {
            float t = 0.f;
            #pragma unroll
            for (int w2 = 0; w2 < 6; w2++) t += SRed[w2*64 + tid];
            g_psum[(size_t)bx*C2A + byc + tid] = t;
        }
        __syncthreads();
        if (lane < 4) {
            #pragma unroll
            for (int j = 0; j < 8; j++) {
                SRed[w*64 + j*8 + 2*lane + 0] = q16[2*j];
                SRed[w*64 + j*8 + 2*lane + 1] = q16[2*j+1];
            }
        }
        __syncthreads();
        if (tid < 64) {
            float t = 0.f;
            #pragma unroll
            for (int w2 = 0; w2 < 6; w2++) t += SRed[w2*64 + tid];
            g_psq[(size_t)bx*C2A + byc + tid] = t;
        }
    }
}

// ---------------- K: mask count (independent of GEMM) -----------------------
__global__ __launch_bounds__(256) void reduce_mask(const float* __restrict__ mask) {
    __shared__ float sm[256];
    const int tid = threadIdx.x;
    float s = 0.f;
    for (int i = tid; i < NM; i += 256) s += mask[i];
    sm[tid] = s; __syncthreads();
    for (int off = 128; off > 0; off >>= 1) {
        if (tid < off) sm[tid] += sm[tid + off];
        __syncthreads();
    }
    if (tid == 0) g_cnt = sm[0];
}

// ---------------- K: reduce partials -> column sums -------------------------
__global__ __launch_bounds__(256) void reduce_cols() {
    __shared__ float sm[256];
    const int b = blockIdx.x, tid = threadIdx.x;
    float s = 0.f;
    if (b < 256) {
        for (int i = tid; i < GTILES; i += 256) s += g_psum[(size_t)i * C2A + b];
    } else {
        int c = b - 256;
        for (int i = tid; i < GTILES; i += 256) s += g_psq[(size_t)i * C2A + c];
    }
    sm[tid] = s; __syncthreads();
    for (int off = 128; off > 0; off >>= 1) {
        if (tid < off) sm[tid] += sm[tid + off];
        __syncthreads();
    }
    if (tid == 0) {
        if (b < 256) g_colsum[b] = sm[0];
        else         g_colsq[b - 256] = sm[0];
    }
}

// ---------------- K: BN1-apply + gate + per-atom sum ------------------------
// Block = 8 atoms. Thread owns (atom-pair, col-pair); no reduction needed.
__global__ __launch_bounds__(256) void gate_apply(const float* __restrict__ mask,
                                                  const float* __restrict__ gamma1,
                                                  const float* __restrict__ beta1) {
    __shared__ float s1s[C2A], s1b[C2A], smk[96];
    const int tid = threadIdx.x;
    const int bx = blockIdx.x;

    {
        float cnt = g_cnt;
        float mean = g_colsum[tid] / cnt;
        float var  = g_colsq[tid] / cnt - mean * mean;
        float sc   = rsqrtf(var + EPSV) * gamma1[tid];
        s1s[tid] = sc;
        s1b[tid] = beta1[tid] - mean * sc;
    }
    if (tid < 96) smk[tid] = mask[bx*96 + tid];
    __syncthreads();

    const int c2 = (tid & 63) * 2;          // col pair
    const int ag = tid >> 6;                // 0..3
    const float sf0 = s1s[c2],     sf1 = s1s[c2+1];
    const float bf0 = s1b[c2],     bf1 = s1b[c2+1];
    const float sc0 = s1s[128+c2], sc1 = s1s[128+c2+1];
    const float bc0 = s1b[128+c2], bc1 = s1b[128+c2+1];

    #pragma unroll
    for (int aa = 0; aa < 2; aa++) {
        const int a = ag + aa*4;
        const int atom = bx*8 + a;
        float sx = 0.f, sy = 0.f;
        #pragma unroll
        for (int m = 0; m < MNBR; m++) {
            float mk = smk[a*MNBR + m];
            if (mk != 0.f) {
                size_t row = ((size_t)bx*96 + a*MNBR + m) * C2A;
                float2 f = *(const float2*)&g_gated[row + c2];
                float2 c = *(const float2*)&g_gated[row + 128 + c2];
                float fx = f.x * sf0 + bf0, fy = f.y * sf1 + bf1;
                float cx = c.x * sc0 + bc0, cy = c.y * sc1 + bc1;
                sx += fast_sigmoid(fx) * fast_softplus(cx);
                sy += fast_sigmoid(fy) * fast_softplus(cy);
            }
        }
        *(float2*)&g_ns[(size_t)atom*AFEA + c2] = make_float2(sx, sy);
    }
}

// ---------------- K: BN2 stats + affine -------------------------------------
__global__ __launch_bounds__(256) void reduce2(const float* __restrict__ gamma2,
                                               const float* __restrict__ beta2) {
    __shared__ float ss[256], sq[256];
    const int c = blockIdx.x, tid = threadIdx.x;
    float s = 0.f, q = 0.f;
    for (int r = tid; r < NATOM; r += 256) {
        float v = g_ns[(size_t)r * AFEA + c];
        s += v; q += v * v;
    }
    ss[tid] = s; sq[tid] = q; __syncthreads();
    for (int off = 128; off > 0; off >>= 1) {
        if (tid < off) { ss[tid] += ss[tid + off]; sq[tid] += sq[tid + off]; }
        __syncthreads();
    }
    if (tid == 0) {
        float mean = ss[0] / (float)NATOM;
        float var  = sq[0] / (float)NATOM - mean * mean;
        float sc   = rsqrtf(var + EPSV) * gamma2[c];
        g_scale2[c] = sc;
        g_shift2[c] = beta2[c] - mean * sc;
    }
}

// ---------------- K: out = softplus(atom + BN2(nbr_sumed)) ------------------
__global__ __launch_bounds__(256) void out_k(const float* __restrict__ atom,
                                             float* __restrict__ out) {
    int i = blockIdx.x * 256 + threadIdx.x;
    if (i < NATOM * AFEA) {
        int c = i & 127;
        float v = atom[i] + g_ns[i] * g_scale2[c] + g_shift2[c];
        out[i] = fmaxf(v, 0.f) + __logf(1.f + __expf(-fabsf(v)));
    }
}

// ---------------- launch ----------------------------------------------------
extern "C" void kernel_launch(void* const* d_in, const int* in_sizes, int n_in,
                              void* d_out, int out_size) {
    const float* atom  = (const float*)d_in[0];
    const float* nbr   = (const float*)d_in[1];
    const int*   idx   = (const int*)  d_in[2];
    const float* mask  = (const float*)d_in[3];
    const float* W     = (const float*)d_in[4];
    const float* bfc   = (const float*)d_in[5];
    const float* g1    = (const float*)d_in[6];
    const float* b1    = (const float*)d_in[7];
    const float* g2    = (const float*)d_in[8];
    const float* b2    = (const float*)d_in[9];
    float* out = (float*)d_out;

    gemm_p12_tc  <<<dim3((NATOM + 127) / 128, 4), 256>>>(atom, W);        // 0
    reduce_mask  <<<1, 256>>>(mask);                                      // 1
    gemm_gated_tc<<<GTILES/2, 192>>>(nbr, W, bfc, idx, mask, 0);          // 2
    gemm_gated_tc<<<GTILES/2, 192>>>(nbr, W, bfc, idx, mask, GTILES/2);   // 3 (profiled)
    reduce_cols  <<<512, 256>>>();                                        // 4
    gate_apply   <<<GTILES, 256>>>(mask, g1, b1);                         // 5
    reduce2      <<<AFEA, 256>>>(g2, b2);                                 // 6
    out_k        <<<(NATOM * AFEA + 255) / 256, 256>>>(atom, out);        // 7
}

// round 5
// speedup vs baseline: 1.3497x; 1.0310x over previous
#include <cuda_runtime.h>
#include <cuda_bf16.h>
#include <math.h>
#include <stdint.h>

// Problem constants
#define NATOM 50000
#define MNBR  12
#define AFEA  128
#define NBRF  64
#define NM    (NATOM*MNBR)     // 600000
#define C2A   256
#define EPSV  1e-5f
#define GTILES (NM/96)         // 6250 row tiles of 96 (= 8 atoms)

// ---------------- scratch (device globals) ----------------------------------
__device__ float g_P1[(size_t)NATOM*C2A];
__device__ float g_P2[(size_t)NATOM*C2A];
__device__ float g_gated[(size_t)NM*C2A];
__device__ float g_psum[(size_t)GTILES*C2A];
__device__ float g_psq [(size_t)GTILES*C2A];
__device__ float g_ns[NATOM*AFEA];
__device__ float g_colsum[C2A];
__device__ float g_colsq[C2A];
__device__ float g_cnt;
__device__ float g_scale2[AFEA], g_shift2[AFEA];

// ---------------- helpers ----------------------------------------------------
__device__ __forceinline__ void bsplit(float x, __nv_bfloat16& h, __nv_bfloat16& l) {
    h = __float2bfloat16(x);
    l = __float2bfloat16(x - __bfloat162float(h));
}

__device__ __forceinline__ void mma_bf16(float* c, const uint32_t* a,
                                         uint32_t b0, uint32_t b1) {
    asm volatile(
        "mma.sync.aligned.m16n8k16.row.col.f32.bf16.bf16.f32 "
        "{%0,%1,%2,%3}, {%4,%5,%6,%7}, {%8,%9}, {%0,%1,%2,%3};\n"
        : "+f"(c[0]), "+f"(c[1]), "+f"(c[2]), "+f"(c[3])
        : "r"(a[0]), "r"(a[1]), "r"(a[2]), "r"(a[3]), "r"(b0), "r"(b1));
}

__device__ __forceinline__ void ldsm_x4(uint32_t addr, uint32_t& r0, uint32_t& r1,
                                        uint32_t& r2, uint32_t& r3) {
    asm volatile("ldmatrix.sync.aligned.m8n8.x4.shared.b16 {%0,%1,%2,%3}, [%4];"
                 : "=r"(r0), "=r"(r1), "=r"(r2), "=r"(r3) : "r"(addr));
}

__device__ __forceinline__ float fast_sigmoid(float x) {
    return __fdividef(1.f, 1.f + __expf(-x));
}
__device__ __forceinline__ float fast_softplus(float x) {
    return fmaxf(x, 0.f) + __logf(1.f + __expf(-fabsf(x)));
}

// ---------------- K1: [P1|P2] via tensor cores + ldmatrix -------------------
#define PA2 40
__global__ __launch_bounds__(256) void gemm_p12_tc(const float* __restrict__ atom,
                                                   const float* __restrict__ W) {
    __shared__ __align__(16) __nv_bfloat16 Ahi[128*PA2], Alo[128*PA2];
    __shared__ __align__(16) __nv_bfloat16 Bhi[128*PA2], Blo[128*PA2];

    const int tid = threadIdx.x;
    const int bx = blockIdx.x, by = blockIdx.y;
    const int w = tid >> 5, lane = tid & 31, g = lane >> 2, tig = lane & 3;
    const int cb = by * 64;
    const int m4 = lane >> 3, lr = lane & 7;

    const uint32_t aHi0 = (uint32_t)__cvta_generic_to_shared(Ahi)
                        + ((w*16 + (m4 & 1)*8 + lr) * PA2 + (m4 >> 1)*8) * 2;
    const uint32_t aLo0 = (uint32_t)__cvta_generic_to_shared(Alo)
                        + ((w*16 + (m4 & 1)*8 + lr) * PA2 + (m4 >> 1)*8) * 2;
    const uint32_t bHi0 = (uint32_t)__cvta_generic_to_shared(Bhi)
                        + (((m4 >> 1)*8 + lr) * PA2 + (m4 & 1)*8) * 2;
    const uint32_t bLo0 = (uint32_t)__cvta_generic_to_shared(Blo)
                        + (((m4 >> 1)*8 + lr) * PA2 + (m4 & 1)*8) * 2;

    float acc[16][4];
    #pragma unroll
    for (int j = 0; j < 16; j++) { acc[j][0]=0.f; acc[j][1]=0.f; acc[j][2]=0.f; acc[j][3]=0.f; }

    for (int kc = 0; kc < 4; kc++) {
        __syncthreads();
        for (int i = tid; i < 128*32; i += 256) {
            int r = i >> 5, c = i & 31;
            int gr = bx*128 + r;
            float x = (gr < NATOM) ? atom[(size_t)gr*128 + kc*32 + c] : 0.f;
            bsplit(x, Ahi[r*PA2 + c], Alo[r*PA2 + c]);
        }
        for (int i = tid; i < 32*128; i += 256) {
            int k = i >> 7, n = i & 127;
            int wrow = kc*32 + k + ((n >= 64) ? 128 : 0);
            float x = W[(size_t)wrow*C2A + cb + (n & 63)];
            bsplit(x, Bhi[n*PA2 + k], Blo[n*PA2 + k]);
        }
        __syncthreads();

        #pragma unroll
        for (int ks = 0; ks < 2; ks++) {
            const uint32_t koff = ks * 16 * 2;
            uint32_t ah[4], al[4];
            ldsm_x4(aHi0 + koff, ah[0], ah[1], ah[2], ah[3]);
            ldsm_x4(aLo0 + koff, al[0], al[1], al[2], al[3]);
            #pragma unroll
            for (int jp = 0; jp < 8; jp++) {
                const uint32_t boff = (uint32_t)(jp*16*PA2*2) + koff;
                uint32_t bh0, bh1, bh2, bh3, bl0, bl1, bl2, bl3;
                ldsm_x4(bHi0 + boff, bh0, bh1, bh2, bh3);
                ldsm_x4(bLo0 + boff, bl0, bl1, bl2, bl3);
                mma_bf16(acc[2*jp],   ah, bh0, bh1);
                mma_bf16(acc[2*jp],   ah, bl0, bl1);
                mma_bf16(acc[2*jp],   al, bh0, bh1);
                mma_bf16(acc[2*jp+1], ah, bh2, bh3);
                mma_bf16(acc[2*jp+1], ah, bl2, bl3);
                mma_bf16(acc[2*jp+1], al, bh2, bh3);
            }
        }
    }

    const int gr0 = bx*128 + w*16 + g;
    const int gr1 = gr0 + 8;
    #pragma unroll
    for (int j = 0; j < 16; j++) {
        float* Cdst = (j < 8) ? g_P1 : g_P2;
        const int c = cb + (j & 7)*8 + 2*tig;
        if (gr0 < NATOM)
            *(float2*)&Cdst[(size_t)gr0*C2A + c] = make_float2(acc[j][0], acc[j][1]);
        if (gr1 < NATOM)
            *(float2*)&Cdst[(size_t)gr1*C2A + c] = make_float2(acc[j][2], acc[j][3]);
    }
}

// ---------------- K2: gated GEMM, C staged in smem, coalesced epilogue ------
#define PA 72
#define PC 68
// dyn smem layout (bytes):
//  0      : Ahi (96*72*2 = 13824)
//  13824  : Alo (13824)                        -> 27648
//  27648  : union { Bhi(9216)+Blo(9216)=18432 ; Cs 96*68*4=26112 } -> 53760
//  53760  : union { P1s 8*64*4=2048 ; Red 6*128*4=3072 }           -> 56832
//  56832  : bias 64*4=256                                           -> 57088
//  57088  : nbS 96*4                                                -> 57472
//  57472  : mkS 96*4                                                -> 57856
#define SM_TOTAL 57856
__global__ __launch_bounds__(192) void gemm_gated_tc(const float* __restrict__ nbr,
                                                     const float* __restrict__ W,
                                                     const float* __restrict__ bfc,
                                                     const int*   __restrict__ idx,
                                                     const float* __restrict__ mask,
                                                     int bx0) {
    extern __shared__ __align__(16) char smraw[];
    __nv_bfloat16* Ahi = (__nv_bfloat16*)(smraw);
    __nv_bfloat16* Alo = (__nv_bfloat16*)(smraw + 13824);
    __nv_bfloat16* Bhi = (__nv_bfloat16*)(smraw + 27648);
    __nv_bfloat16* Blo = (__nv_bfloat16*)(smraw + 27648 + 9216);
    float* Cs   = (float*)(smraw + 27648);
    float* P1s  = (float*)(smraw + 53760);
    float* Red  = (float*)(smraw + 53760);
    float* biasS= (float*)(smraw + 56832);
    int*   nbS  = (int*)  (smraw + 57088);
    float* mkS  = (float*)(smraw + 57472);

    const int tid = threadIdx.x;
    const int bx = blockIdx.x + bx0;
    const int w = tid >> 5, lane = tid & 31, g = lane >> 2, tig = lane & 3;
    const float* W3 = W + 256*C2A;
    const int m4 = lane >> 3, lr = lane & 7;

    const uint32_t aHi0 = (uint32_t)__cvta_generic_to_shared(Ahi)
                        + ((w*16 + (m4 & 1)*8 + lr) * PA + (m4 >> 1)*8) * 2;
    const uint32_t aLo0 = (uint32_t)__cvta_generic_to_shared(Alo)
                        + ((w*16 + (m4 & 1)*8 + lr) * PA + (m4 >> 1)*8) * 2;
    const uint32_t bHi0 = (uint32_t)__cvta_generic_to_shared(Bhi)
                        + (((m4 >> 1)*8 + lr) * PA + (m4 & 1)*8) * 2;
    const uint32_t bLo0 = (uint32_t)__cvta_generic_to_shared(Blo)
                        + (((m4 >> 1)*8 + lr) * PA + (m4 & 1)*8) * 2;

    // A tile 96x64, packed bf16x2 split stores
    for (int i = tid; i < 96*16; i += 192) {
        int r = i >> 4, c4 = (i & 15) * 4;
        float4 v = *(const float4*)&nbr[((size_t)bx*96 + r)*64 + c4];
        __nv_bfloat16 h0,l0,h1,l1,h2,l2,h3,l3;
        bsplit(v.x, h0, l0); bsplit(v.y, h1, l1);
        bsplit(v.z, h2, l2); bsplit(v.w, h3, l3);
        *(__nv_bfloat162*)&Ahi[r*PA + c4]     = __nv_bfloat162(h0, h1);
        *(__nv_bfloat162*)&Ahi[r*PA + c4 + 2] = __nv_bfloat162(h2, h3);
        *(__nv_bfloat162*)&Alo[r*PA + c4]     = __nv_bfloat162(l0, l1);
        *(__nv_bfloat162*)&Alo[r*PA + c4 + 2] = __nv_bfloat162(l2, l3);
    }
    // Row metadata
    if (tid < 96) {
        nbS[tid] = idx[bx*96 + tid];
        mkS[tid] = mask[bx*96 + tid];
    }

    const int q = tid & 15;          // col quad owned in epilogue
    const int rsub = tid >> 4;       // 0..11

    for (int by = 0; by < 4; by++) {
        __syncthreads();
        // B slice 64x64 -> [n][k], packed bf16x2; coalesced gmem reads
        for (int i = tid; i < 64*32; i += 192) {
            int k2 = i >> 6, n = i & 63;
            float x0 = W3[(size_t)(2*k2)  *C2A + by*64 + n];
            float x1 = W3[(size_t)(2*k2+1)*C2A + by*64 + n];
            __nv_bfloat16 h0,l0,h1,l1;
            bsplit(x0, h0, l0); bsplit(x1, h1, l1);
            *(__nv_bfloat162*)&Bhi[n*PA + 2*k2] = __nv_bfloat162(h0, h1);
            *(__nv_bfloat162*)&Blo[n*PA + 2*k2] = __nv_bfloat162(l0, l1);
        }
        // P1 tile (8 atoms x 64 cols) + bias
        if (tid < 128) {
            *(float4*)&P1s[tid*4] =
                *(const float4*)&g_P1[(size_t)(bx*8 + (tid >> 4))*C2A + by*64 + (tid & 15)*4];
        }
        if (tid < 16)
            *(float4*)&biasS[tid*4] = *(const float4*)&bfc[by*64 + tid*4];
        __syncthreads();

        float acc[8][4];
        #pragma unroll
        for (int j = 0; j < 8; j++) { acc[j][0]=0.f; acc[j][1]=0.f; acc[j][2]=0.f; acc[j][3]=0.f; }

        #pragma unroll
        for (int ks = 0; ks < 4; ks++) {
            const uint32_t koff = ks * 16 * 2;
            uint32_t ah[4], al[4];
            ldsm_x4(aHi0 + koff, ah[0], ah[1], ah[2], ah[3]);
            ldsm_x4(aLo0 + koff, al[0], al[1], al[2], al[3]);
            #pragma unroll
            for (int jp = 0; jp < 4; jp++) {
                const uint32_t boff = (uint32_t)(jp*16*PA*2) + koff;
                uint32_t bh0, bh1, bh2, bh3, bl0, bl1, bl2, bl3;
                ldsm_x4(bHi0 + boff, bh0, bh1, bh2, bh3);
                ldsm_x4(bLo0 + boff, bl0, bl1, bl2, bl3);
                mma_bf16(acc[2*jp],   ah, bh0, bh1);
                mma_bf16(acc[2*jp],   ah, bl0, bl1);
                mma_bf16(acc[2*jp],   al, bh0, bh1);
                mma_bf16(acc[2*jp+1], ah, bh2, bh3);
                mma_bf16(acc[2*jp+1], ah, bl2, bl3);
                mma_bf16(acc[2*jp+1], al, bh2, bh3);
            }
        }

        __syncthreads();   // B reads done; region becomes Cs
        {
            const int rl0 = w*16 + g, rl1 = rl0 + 8;
            #pragma unroll
            for (int j = 0; j < 8; j++) {
                const int c = j*8 + 2*tig;
                *(float2*)&Cs[rl0*PC + c] = make_float2(acc[j][0], acc[j][1]);
                *(float2*)&Cs[rl1*PC + c] = make_float2(acc[j][2], acc[j][3]);
            }
        }
        __syncthreads();

        // Coalesced epilogue: thread = (row rsub + 12*it, col quad q)
        float s0=0.f,s1=0.f,s2=0.f,s3=0.f, q0=0.f,q1=0.f,q2=0.f,q3=0.f;
        #pragma unroll
        for (int it = 0; it < 8; it++) {
            const int r = it*12 + rsub;
            const float mk = mkS[r];
            if (mk != 0.f) {
                const int la = r / MNBR;
                float4 cv = *(const float4*)&Cs[r*PC + q*4];
                float4 p1 = *(const float4*)&P1s[la*64 + q*4];
                float4 p2 = *(const float4*)&g_P2[(size_t)nbS[r]*C2A + by*64 + q*4];
                float4 bb = *(const float4*)&biasS[q*4];
                float4 v;
                v.x = cv.x + p1.x + p2.x + bb.x;
                v.y = cv.y + p1.y + p2.y + bb.y;
                v.z = cv.z + p1.z + p2.z + bb.z;
                v.w = cv.w + p1.w + p2.w + bb.w;
                *(float4*)&g_gated[((size_t)(bx*96 + r))*C2A + by*64 + q*4] = v;
                s0 += v.x; s1 += v.y; s2 += v.z; s3 += v.w;
                q0 += v.x*v.x; q1 += v.y*v.y; q2 += v.z*v.z; q3 += v.w*v.w;
            }
        }
        __syncthreads();   // P1s reads done; region becomes Red

        // lanes l and l+16 share q -> combine, then cross-warp via Red
        s0 += __shfl_xor_sync(0xffffffffu, s0, 16);
        s1 += __shfl_xor_sync(0xffffffffu, s1, 16);
        s2 += __shfl_xor_sync(0xffffffffu, s2, 16);
        s3 += __shfl_xor_sync(0xffffffffu, s3, 16);
        q0 += __shfl_xor_sync(0xffffffffu, q0, 16);
        q1 += __shfl_xor_sync(0xffffffffu, q1, 16);
        q2 += __shfl_xor_sync(0xffffffffu, q2, 16);
        q3 += __shfl_xor_sync(0xffffffffu, q3, 16);
        if (lane < 16) {
            float* d = &Red[w*128 + lane*8];
            d[0]=s0; d[1]=s1; d[2]=s2; d[3]=s3;
            d[4]=q0; d[5]=q1; d[6]=q2; d[7]=q3;
        }
        __syncthreads();
        if (tid < 64) {
            float ts = 0.f, tq = 0.f;
            const int o = (tid >> 2)*8 + (tid & 3);
            #pragma unroll
            for (int w2 = 0; w2 < 6; w2++) {
                ts += Red[w2*128 + o];
                tq += Red[w2*128 + o + 4];
            }
            g_psum[(size_t)bx*C2A + by*64 + tid] = ts;
            g_psq [(size_t)bx*C2A + by*64 + tid] = tq;
        }
    }
}

// ---------------- K: mask count ---------------------------------------------
__global__ __launch_bounds__(256) void reduce_mask(const float* __restrict__ mask) {
    __shared__ float sm[256];
    const int tid = threadIdx.x;
    float s = 0.f;
    for (int i = tid; i < NM; i += 256) s += mask[i];
    sm[tid] = s; __syncthreads();
    for (int off = 128; off > 0; off >>= 1) {
        if (tid < off) sm[tid] += sm[tid + off];
        __syncthreads();
    }
    if (tid == 0) g_cnt = sm[0];
}

// ---------------- K: reduce partials -> column sums -------------------------
__global__ __launch_bounds__(256) void reduce_cols() {
    __shared__ float sm[256];
    const int b = blockIdx.x, tid = threadIdx.x;
    float s = 0.f;
    if (b < 256) {
        for (int i = tid; i < GTILES; i += 256) s += g_psum[(size_t)i * C2A + b];
    } else {
        int c = b - 256;
        for (int i = tid; i < GTILES; i += 256) s += g_psq[(size_t)i * C2A + c];
    }
    sm[tid] = s; __syncthreads();
    for (int off = 128; off > 0; off >>= 1) {
        if (tid < off) sm[tid] += sm[tid + off];
        __syncthreads();
    }
    if (tid == 0) {
        if (b < 256) g_colsum[b] = sm[0];
        else         g_colsq[b - 256] = sm[0];
    }
}

// ---------------- K: BN1-apply + gate + per-atom sum ------------------------
__global__ __launch_bounds__(256) void gate_apply(const float* __restrict__ mask,
                                                  const float* __restrict__ gamma1,
                                                  const float* __restrict__ beta1) {
    __shared__ float s1s[C2A], s1b[C2A], smk[96];
    const int tid = threadIdx.x;
    const int bx = blockIdx.x;

    {
        float cnt = g_cnt;
        float mean = g_colsum[tid] / cnt;
        float var  = g_colsq[tid] / cnt - mean * mean;
        float sc   = rsqrtf(var + EPSV) * gamma1[tid];
        s1s[tid] = sc;
        s1b[tid] = beta1[tid] - mean * sc;
    }
    if (tid < 96) smk[tid] = mask[bx*96 + tid];
    __syncthreads();

    const int c2 = (tid & 63) * 2;
    const int ag = tid >> 6;
    const float sf0 = s1s[c2],     sf1 = s1s[c2+1];
    const float bf0 = s1b[c2],     bf1 = s1b[c2+1];
    const float sc0 = s1s[128+c2], sc1 = s1s[128+c2+1];
    const float bc0 = s1b[128+c2], bc1 = s1b[128+c2+1];

    #pragma unroll
    for (int aa = 0; aa < 2; aa++) {
        const int a = ag + aa*4;
        const int atom = bx*8 + a;
        float sx = 0.f, sy = 0.f;
        #pragma unroll
        for (int m = 0; m < MNBR; m++) {
            float mk = smk[a*MNBR + m];
            if (mk != 0.f) {
                size_t row = ((size_t)bx*96 + a*MNBR + m) * C2A;
                float2 f = *(const float2*)&g_gated[row + c2];
                float2 c = *(const float2*)&g_gated[row + 128 + c2];
                float fx = f.x * sf0 + bf0, fy = f.y * sf1 + bf1;
                float cx = c.x * sc0 + bc0, cy = c.y * sc1 + bc1;
                sx += fast_sigmoid(fx) * fast_softplus(cx);
                sy += fast_sigmoid(fy) * fast_softplus(cy);
            }
        }
        *(float2*)&g_ns[(size_t)atom*AFEA + c2] = make_float2(sx, sy);
    }
}

// ---------------- K: BN2 stats + affine -------------------------------------
__global__ __launch_bounds__(256) void reduce2(const float* __restrict__ gamma2,
                                               const float* __restrict__ beta2) {
    __shared__ float ss[256], sq[256];
    const int c = blockIdx.x, tid = threadIdx.x;
    float s = 0.f, q = 0.f;
    for (int r = tid; r < NATOM; r += 256) {
        float v = g_ns[(size_t)r * AFEA + c];
        s += v; q += v * v;
    }
    ss[tid] = s; sq[tid] = q; __syncthreads();
    for (int off = 128; off > 0; off >>= 1) {
        if (tid < off) { ss[tid] += ss[tid + off]; sq[tid] += sq[tid + off]; }
        __syncthreads();
    }
    if (tid == 0) {
        float mean = ss[0] / (float)NATOM;
        float var  = sq[0] / (float)NATOM - mean * mean;
        float sc   = rsqrtf(var + EPSV) * gamma2[c];
        g_scale2[c] = sc;
        g_shift2[c] = beta2[c] - mean * sc;
    }
}

// ---------------- K: out = softplus(atom + BN2(nbr_sumed)) ------------------
__global__ __launch_bounds__(256) void out_k(const float* __restrict__ atom,
                                             float* __restrict__ out) {
    int i = blockIdx.x * 256 + threadIdx.x;
    if (i < NATOM * AFEA) {
        int c = i & 127;
        float v = atom[i] + g_ns[i] * g_scale2[c] + g_shift2[c];
        out[i] = fmaxf(v, 0.f) + __logf(1.f + __expf(-fabsf(v)));
    }
}

// ---------------- launch ----------------------------------------------------
extern "C" void kernel_launch(void* const* d_in, const int* in_sizes, int n_in,
                              void* d_out, int out_size) {
    const float* atom  = (const float*)d_in[0];
    const float* nbr   = (const float*)d_in[1];
    const int*   idx   = (const int*)  d_in[2];
    const float* mask  = (const float*)d_in[3];
    const float* W     = (const float*)d_in[4];
    const float* bfc   = (const float*)d_in[5];
    const float* g1    = (const float*)d_in[6];
    const float* b1    = (const float*)d_in[7];
    const float* g2    = (const float*)d_in[8];
    const float* b2    = (const float*)d_in[9];
    float* out = (float*)d_out;

    cudaFuncSetAttribute(gemm_gated_tc, cudaFuncAttributeMaxDynamicSharedMemorySize, SM_TOTAL);

    gemm_p12_tc  <<<dim3((NATOM + 127) / 128, 4), 256>>>(atom, W);              // 0
    reduce_mask  <<<1, 256>>>(mask);                                            // 1
    gemm_gated_tc<<<GTILES/2, 192, SM_TOTAL>>>(nbr, W, bfc, idx, mask, 0);      // 2
    gemm_gated_tc<<<GTILES/2, 192, SM_TOTAL>>>(nbr, W, bfc, idx, mask, GTILES/2); // 3 (profiled)
    reduce_cols  <<<512, 256>>>();                                              // 4
    gate_apply   <<<GTILES, 256>>>(mask, g1, b1);                               // 5
    reduce2      <<<AFEA, 256>>>(g2, b2);                                       // 6
    out_k        <<<(NATOM * AFEA + 255) / 256, 256>>>(atom, out);              // 7
}

// round 6
// speedup vs baseline: 1.9177x; 1.4208x over previous
#include <cuda_runtime.h>
#include <cuda_bf16.h>
#include <math.h>
#include <stdint.h>

// Problem constants
#define NATOM 50000
#define MNBR  12
#define AFEA  128
#define NBRF  64
#define NM    (NATOM*MNBR)     // 600000
#define C2A   256
#define EPSV  1e-5f
#define GTILES (NM/96)         // 6250 worst-case row tiles of 96
#define SCB   1024
#define NSC   ((NM + SCB - 1) / SCB)   // 586

// ---------------- scratch (device globals) ----------------------------------
__device__ float g_P1[(size_t)NATOM*C2A];
__device__ float g_P2[(size_t)NATOM*C2A];
__device__ float g_gated[(size_t)NM*C2A];     // compact rows used: [0, nlive)
__device__ float g_psum[(size_t)GTILES*C2A];
__device__ float g_psq [(size_t)GTILES*C2A];
__device__ float g_ns[NATOM*AFEA];
__device__ float g_colsum[C2A];
__device__ float g_colsq[C2A];
__device__ float g_cntf;
__device__ int   g_nlive;
__device__ int   g_bcnt[NSC];
__device__ int   g_boff[NSC];
__device__ int   g_pos[NM];                   // exclusive live-count before item i
__device__ int   g_live[NM];                  // compact -> original row
__device__ float g_scale2[AFEA], g_shift2[AFEA];

// ---------------- helpers ----------------------------------------------------
__device__ __forceinline__ void bsplit(float x, __nv_bfloat16& h, __nv_bfloat16& l) {
    h = __float2bfloat16(x);
    l = __float2bfloat16(x - __bfloat162float(h));
}

__device__ __forceinline__ void mma_bf16(float* c, const uint32_t* a,
                                         uint32_t b0, uint32_t b1) {
    asm volatile(
        "mma.sync.aligned.m16n8k16.row.col.f32.bf16.bf16.f32 "
        "{%0,%1,%2,%3}, {%4,%5,%6,%7}, {%8,%9}, {%0,%1,%2,%3};\n"
        : "+f"(c[0]), "+f"(c[1]), "+f"(c[2]), "+f"(c[3])
        : "r"(a[0]), "r"(a[1]), "r"(a[2]), "r"(a[3]), "r"(b0), "r"(b1));
}

__device__ __forceinline__ void ldsm_x4(uint32_t addr, uint32_t& r0, uint32_t& r1,
                                        uint32_t& r2, uint32_t& r3) {
    asm volatile("ldmatrix.sync.aligned.m8n8.x4.shared.b16 {%0,%1,%2,%3}, [%4];"
                 : "=r"(r0), "=r"(r1), "=r"(r2), "=r"(r3) : "r"(addr));
}

__device__ __forceinline__ float fast_sigmoid(float x) {
    return __fdividef(1.f, 1.f + __expf(-x));
}
__device__ __forceinline__ float fast_softplus(float x) {
    return fmaxf(x, 0.f) + __logf(1.f + __expf(-fabsf(x)));
}

// ---------------- scan kernels (deterministic int compaction) ---------------
__global__ __launch_bounds__(256) void scan1(const float* __restrict__ mask) {
    __shared__ int sw[8];
    const int b = blockIdx.x, tid = threadIdx.x;
    const int base = b * SCB;
    int c = 0;
    #pragma unroll
    for (int k = 0; k < 4; k++) {
        int i = base + tid*4 + k;
        if (i < NM) c += (mask[i] != 0.f);
    }
    int v = c;
    #pragma unroll
    for (int off = 16; off > 0; off >>= 1) v += __shfl_xor_sync(0xffffffffu, v, off);
    if ((tid & 31) == 0) sw[tid >> 5] = v;
    __syncthreads();
    if (tid == 0) {
        int t = 0;
        #pragma unroll
        for (int i = 0; i < 8; i++) t += sw[i];
        g_bcnt[b] = t;
    }
}

__global__ __launch_bounds__(1024) void scan2() {
    __shared__ int s[1024];
    const int tid = threadIdx.x;
    int v = (tid < NSC) ? g_bcnt[tid] : 0;
    s[tid] = v;
    __syncthreads();
    for (int off = 1; off < 1024; off <<= 1) {
        int t = (tid >= off) ? s[tid - off] : 0;
        __syncthreads();
        s[tid] += t;
        __syncthreads();
    }
    if (tid < NSC) g_boff[tid] = s[tid] - v;   // exclusive
    if (tid == 1023) {
        g_nlive = s[1023];
        g_cntf  = (float)s[1023];
    }
}

__global__ __launch_bounds__(256) void scan3(const float* __restrict__ mask) {
    __shared__ int s[256];
    const int b = blockIdx.x, tid = threadIdx.x;
    const int base = b * SCB;
    int c = 0;
    #pragma unroll
    for (int k = 0; k < 4; k++) {
        int i = base + tid*4 + k;
        if (i < NM) c += (mask[i] != 0.f);
    }
    s[tid] = c;
    __syncthreads();
    for (int off = 1; off < 256; off <<= 1) {
        int t = (tid >= off) ? s[tid - off] : 0;
        __syncthreads();
        s[tid] += t;
        __syncthreads();
    }
    int p = g_boff[b] + s[tid] - c;   // exclusive position for first item
    #pragma unroll
    for (int k = 0; k < 4; k++) {
        int i = base + tid*4 + k;
        if (i < NM) {
            g_pos[i] = p;
            if (mask[i] != 0.f) { g_live[p] = i; p++; }
        }
    }
}

// ---------------- K: [P1|P2] via tensor cores + ldmatrix --------------------
#define PA2 40
__global__ __launch_bounds__(256) void gemm_p12_tc(const float* __restrict__ atom,
                                                   const float* __restrict__ W) {
    __shared__ __align__(16) __nv_bfloat16 Ahi[128*PA2], Alo[128*PA2];
    __shared__ __align__(16) __nv_bfloat16 Bhi[128*PA2], Blo[128*PA2];

    const int tid = threadIdx.x;
    const int bx = blockIdx.x, by = blockIdx.y;
    const int w = tid >> 5, lane = tid & 31, g = lane >> 2, tig = lane & 3;
    const int cb = by * 64;
    const int m4 = lane >> 3, lr = lane & 7;

    const uint32_t aHi0 = (uint32_t)__cvta_generic_to_shared(Ahi)
                        + ((w*16 + (m4 & 1)*8 + lr) * PA2 + (m4 >> 1)*8) * 2;
    const uint32_t aLo0 = (uint32_t)__cvta_generic_to_shared(Alo)
                        + ((w*16 + (m4 & 1)*8 + lr) * PA2 + (m4 >> 1)*8) * 2;
    const uint32_t bHi0 = (uint32_t)__cvta_generic_to_shared(Bhi)
                        + (((m4 >> 1)*8 + lr) * PA2 + (m4 & 1)*8) * 2;
    const uint32_t bLo0 = (uint32_t)__cvta_generic_to_shared(Blo)
                        + (((m4 >> 1)*8 + lr) * PA2 + (m4 & 1)*8) * 2;

    float acc[16][4];
    #pragma unroll
    for (int j = 0; j < 16; j++) { acc[j][0]=0.f; acc[j][1]=0.f; acc[j][2]=0.f; acc[j][3]=0.f; }

    for (int kc = 0; kc < 4; kc++) {
        __syncthreads();
        for (int i = tid; i < 128*32; i += 256) {
            int r = i >> 5, c = i & 31;
            int gr = bx*128 + r;
            float x = (gr < NATOM) ? atom[(size_t)gr*128 + kc*32 + c] : 0.f;
            bsplit(x, Ahi[r*PA2 + c], Alo[r*PA2 + c]);
        }
        for (int i = tid; i < 32*128; i += 256) {
            int k = i >> 7, n = i & 127;
            int wrow = kc*32 + k + ((n >= 64) ? 128 : 0);
            float x = W[(size_t)wrow*C2A + cb + (n & 63)];
            bsplit(x, Bhi[n*PA2 + k], Blo[n*PA2 + k]);
        }
        __syncthreads();

        #pragma unroll
        for (int ks = 0; ks < 2; ks++) {
            const uint32_t koff = ks * 16 * 2;
            uint32_t ah[4], al[4];
            ldsm_x4(aHi0 + koff, ah[0], ah[1], ah[2], ah[3]);
            ldsm_x4(aLo0 + koff, al[0], al[1], al[2], al[3]);
            #pragma unroll
            for (int jp = 0; jp < 8; jp++) {
                const uint32_t boff = (uint32_t)(jp*16*PA2*2) + koff;
                uint32_t bh0, bh1, bh2, bh3, bl0, bl1, bl2, bl3;
                ldsm_x4(bHi0 + boff, bh0, bh1, bh2, bh3);
                ldsm_x4(bLo0 + boff, bl0, bl1, bl2, bl3);
                mma_bf16(acc[2*jp],   ah, bh0, bh1);
                mma_bf16(acc[2*jp],   ah, bl0, bl1);
                mma_bf16(acc[2*jp],   al, bh0, bh1);
                mma_bf16(acc[2*jp+1], ah, bh2, bh3);
                mma_bf16(acc[2*jp+1], ah, bl2, bl3);
                mma_bf16(acc[2*jp+1], al, bh2, bh3);
            }
        }
    }

    const int gr0 = bx*128 + w*16 + g;
    const int gr1 = gr0 + 8;
    #pragma unroll
    for (int j = 0; j < 16; j++) {
        float* Cdst = (j < 8) ? g_P1 : g_P2;
        const int c = cb + (j & 7)*8 + 2*tig;
        if (gr0 < NATOM)
            *(float2*)&Cdst[(size_t)gr0*C2A + c] = make_float2(acc[j][0], acc[j][1]);
        if (gr1 < NATOM)
            *(float2*)&Cdst[(size_t)gr1*C2A + c] = make_float2(acc[j][2], acc[j][3]);
    }
}

// ---------------- K: gated GEMM over COMPACT live rows ----------------------
#define PA 72
#define PC 68
// dyn smem layout (bytes):
//  0      Ahi 13824
//  13824  Alo -> 27648
//  27648  union{ Bhi 9216 + Blo 9216 ; Cs 96*68*4 = 26112 } -> 53760
//  53760  Red 6*128*4 = 3072 -> 56832
//  56832  biasS 256 -> 57088
//  57088  liveS 96*4 -> 57472
//  57472  nbS 96*4 -> 57856
//  57856  nS 96*4 -> 58240
#define SM_TOTAL 58240
__global__ __launch_bounds__(192) void gemm_gated_tc(const float* __restrict__ nbr,
                                                     const float* __restrict__ W,
                                                     const float* __restrict__ bfc,
                                                     const int*   __restrict__ idx,
                                                     int bx0) {
    extern __shared__ __align__(16) char smraw[];
    __nv_bfloat16* Ahi = (__nv_bfloat16*)(smraw);
    __nv_bfloat16* Alo = (__nv_bfloat16*)(smraw + 13824);
    __nv_bfloat16* Bhi = (__nv_bfloat16*)(smraw + 27648);
    __nv_bfloat16* Blo = (__nv_bfloat16*)(smraw + 27648 + 9216);
    float* Cs   = (float*)(smraw + 27648);
    float* Red  = (float*)(smraw + 53760);
    float* biasS= (float*)(smraw + 56832);
    int*   liveS= (int*)  (smraw + 57088);
    int*   nbS  = (int*)  (smraw + 57472);
    int*   nS   = (int*)  (smraw + 57856);

    const int tid = threadIdx.x;
    const int bx = blockIdx.x + bx0;
    const int nlive = g_nlive;

    if (bx*96 >= nlive) {          // dead tile: zero stats partials, exit
        for (int i = tid; i < C2A; i += 192) {
            g_psum[(size_t)bx*C2A + i] = 0.f;
            g_psq [(size_t)bx*C2A + i] = 0.f;
        }
        return;
    }
    const int rem = min(96, nlive - bx*96);

    const int w = tid >> 5, lane = tid & 31, g = lane >> 2, tig = lane & 3;
    const float* W3 = W + 256*C2A;
    const int m4 = lane >> 3, lr = lane & 7;

    const uint32_t aHi0 = (uint32_t)__cvta_generic_to_shared(Ahi)
                        + ((w*16 + (m4 & 1)*8 + lr) * PA + (m4 >> 1)*8) * 2;
    const uint32_t aLo0 = (uint32_t)__cvta_generic_to_shared(Alo)
                        + ((w*16 + (m4 & 1)*8 + lr) * PA + (m4 >> 1)*8) * 2;
    const uint32_t bHi0 = (uint32_t)__cvta_generic_to_shared(Bhi)
                        + (((m4 >> 1)*8 + lr) * PA + (m4 & 1)*8) * 2;
    const uint32_t bLo0 = (uint32_t)__cvta_generic_to_shared(Blo)
                        + (((m4 >> 1)*8 + lr) * PA + (m4 & 1)*8) * 2;

    // Stage row metadata
    if (tid < 96) {
        int li = bx*96 + tid;
        int r = (li < nlive) ? g_live[li] : -1;
        liveS[tid] = r;
        nbS[tid] = (r >= 0) ? idx[r] : 0;
        nS[tid]  = (r >= 0) ? r / MNBR : 0;
    }
    __syncthreads();

    // A tile 96x64 gathered through live list, packed bf16x2 split stores
    for (int i = tid; i < 96*16; i += 192) {
        int r = i >> 4, c4 = (i & 15) * 4;
        int src = liveS[r];
        float4 v = (src >= 0) ? *(const float4*)&nbr[(size_t)src*64 + c4]
                              : make_float4(0.f, 0.f, 0.f, 0.f);
        __nv_bfloat16 h0,l0,h1,l1,h2,l2,h3,l3;
        bsplit(v.x, h0, l0); bsplit(v.y, h1, l1);
        bsplit(v.z, h2, l2); bsplit(v.w, h3, l3);
        *(__nv_bfloat162*)&Ahi[r*PA + c4]     = __nv_bfloat162(h0, h1);
        *(__nv_bfloat162*)&Ahi[r*PA + c4 + 2] = __nv_bfloat162(h2, h3);
        *(__nv_bfloat162*)&Alo[r*PA + c4]     = __nv_bfloat162(l0, l1);
        *(__nv_bfloat162*)&Alo[r*PA + c4 + 2] = __nv_bfloat162(l2, l3);
    }

    const int q = tid & 15;
    const int rsub = tid >> 4;

    for (int by = 0; by < 4; by++) {
        __syncthreads();
        for (int i = tid; i < 64*32; i += 192) {
            int k2 = i >> 6, n = i & 63;
            float x0 = W3[(size_t)(2*k2)  *C2A + by*64 + n];
            float x1 = W3[(size_t)(2*k2+1)*C2A + by*64 + n];
            __nv_bfloat16 h0,l0,h1,l1;
            bsplit(x0, h0, l0); bsplit(x1, h1, l1);
            *(__nv_bfloat162*)&Bhi[n*PA + 2*k2] = __nv_bfloat162(h0, h1);
            *(__nv_bfloat162*)&Blo[n*PA + 2*k2] = __nv_bfloat162(l0, l1);
        }
        if (tid < 16)
            *(float4*)&biasS[tid*4] = *(const float4*)&bfc[by*64 + tid*4];
        __syncthreads();

        float acc[8][4];
        #pragma unroll
        for (int j = 0; j < 8; j++) { acc[j][0]=0.f; acc[j][1]=0.f; acc[j][2]=0.f; acc[j][3]=0.f; }

        #pragma unroll
        for (int ks = 0; ks < 4; ks++) {
            const uint32_t koff = ks * 16 * 2;
            uint32_t ah[4], al[4];
            ldsm_x4(aHi0 + koff, ah[0], ah[1], ah[2], ah[3]);
            ldsm_x4(aLo0 + koff, al[0], al[1], al[2], al[3]);
            #pragma unroll
            for (int jp = 0; jp < 4; jp++) {
                const uint32_t boff = (uint32_t)(jp*16*PA*2) + koff;
                uint32_t bh0, bh1, bh2, bh3, bl0, bl1, bl2, bl3;
                ldsm_x4(bHi0 + boff, bh0, bh1, bh2, bh3);
                ldsm_x4(bLo0 + boff, bl0, bl1, bl2, bl3);
                mma_bf16(acc[2*jp],   ah, bh0, bh1);
                mma_bf16(acc[2*jp],   ah, bl0, bl1);
                mma_bf16(acc[2*jp],   al, bh0, bh1);
                mma_bf16(acc[2*jp+1], ah, bh2, bh3);
                mma_bf16(acc[2*jp+1], ah, bl2, bl3);
                mma_bf16(acc[2*jp+1], al, bh2, bh3);
            }
        }

        __syncthreads();   // B reads done; region becomes Cs
        {
            const int rl0 = w*16 + g, rl1 = rl0 + 8;
            #pragma unroll
            for (int j = 0; j < 8; j++) {
                const int c = j*8 + 2*tig;
                *(float2*)&Cs[rl0*PC + c] = make_float2(acc[j][0], acc[j][1]);
                *(float2*)&Cs[rl1*PC + c] = make_float2(acc[j][2], acc[j][3]);
            }
        }
        __syncthreads();

        // Coalesced epilogue over compact live rows
        float s0=0.f,s1=0.f,s2=0.f,s3=0.f, q0=0.f,q1=0.f,q2=0.f,q3=0.f;
        #pragma unroll
        for (int it = 0; it < 8; it++) {
            const int r = it*12 + rsub;
            if (r < rem) {
                float4 cv = *(const float4*)&Cs[r*PC + q*4];
                float4 p1 = *(const float4*)&g_P1[(size_t)nS[r]*C2A + by*64 + q*4];
                float4 p2 = *(const float4*)&g_P2[(size_t)nbS[r]*C2A + by*64 + q*4];
                float4 bb = *(const float4*)&biasS[q*4];
                float4 v;
                v.x = cv.x + p1.x + p2.x + bb.x;
                v.y = cv.y + p1.y + p2.y + bb.y;
                v.z = cv.z + p1.z + p2.z + bb.z;
                v.w = cv.w + p1.w + p2.w + bb.w;
                *(float4*)&g_gated[((size_t)(bx*96 + r))*C2A + by*64 + q*4] = v;
                s0 += v.x; s1 += v.y; s2 += v.z; s3 += v.w;
                q0 += v.x*v.x; q1 += v.y*v.y; q2 += v.z*v.z; q3 += v.w*v.w;
            }
        }

        s0 += __shfl_xor_sync(0xffffffffu, s0, 16);
        s1 += __shfl_xor_sync(0xffffffffu, s1, 16);
        s2 += __shfl_xor_sync(0xffffffffu, s2, 16);
        s3 += __shfl_xor_sync(0xffffffffu, s3, 16);
        q0 += __shfl_xor_sync(0xffffffffu, q0, 16);
        q1 += __shfl_xor_sync(0xffffffffu, q1, 16);
        q2 += __shfl_xor_sync(0xffffffffu, q2, 16);
        q3 += __shfl_xor_sync(0xffffffffu, q3, 16);
        if (lane < 16) {
            float* d = &Red[w*128 + lane*8];
            d[0]=s0; d[1]=s1; d[2]=s2; d[3]=s3;
            d[4]=q0; d[5]=q1; d[6]=q2; d[7]=q3;
        }
        __syncthreads();
        if (tid < 64) {
            float ts = 0.f, tq = 0.f;
            const int o = (tid >> 2)*8 + (tid & 3);
            #pragma unroll
            for (int w2 = 0; w2 < 6; w2++) {
                ts += Red[w2*128 + o];
                tq += Red[w2*128 + o + 4];
            }
            g_psum[(size_t)bx*C2A + by*64 + tid] = ts;
            g_psq [(size_t)bx*C2A + by*64 + tid] = tq;
        }
    }
}

// ---------------- K: reduce partials -> column sums -------------------------
__global__ __launch_bounds__(256) void reduce_cols() {
    __shared__ float sm[256];
    const int b = blockIdx.x, tid = threadIdx.x;
    float s = 0.f;
    if (b < 256) {
        for (int i = tid; i < GTILES; i += 256) s += g_psum[(size_t)i * C2A + b];
    } else {
        int c = b - 256;
        for (int i = tid; i < GTILES; i += 256) s += g_psq[(size_t)i * C2A + c];
    }
    sm[tid] = s; __syncthreads();
    for (int off = 128; off > 0; off >>= 1) {
        if (tid < off) sm[tid] += sm[tid + off];
        __syncthreads();
    }
    if (tid == 0) {
        if (b < 256) g_colsum[b] = sm[0];
        else         g_colsq[b - 256] = sm[0];
    }
}

// ---------------- K: BN1-apply + gate + per-atom sum (compact rows) ---------
__global__ __launch_bounds__(256) void gate_apply(const float* __restrict__ gamma1,
                                                  const float* __restrict__ beta1) {
    __shared__ float s1s[C2A], s1b[C2A];
    __shared__ int sA[9];
    const int tid = threadIdx.x;
    const int bx = blockIdx.x;

    {
        float cnt = g_cntf;
        float mean = g_colsum[tid] / cnt;
        float var  = g_colsq[tid] / cnt - mean * mean;
        float sc   = rsqrtf(var + EPSV) * gamma1[tid];
        s1s[tid] = sc;
        s1b[tid] = beta1[tid] - mean * sc;
    }
    if (tid < 9) {
        int i9 = (bx*8 + tid) * MNBR;
        sA[tid] = (i9 < NM) ? g_pos[i9] : g_nlive;
    }
    __syncthreads();

    const int c2 = (tid & 63) * 2;
    const int ag = tid >> 6;
    const float sf0 = s1s[c2],     sf1 = s1s[c2+1];
    const float bf0 = s1b[c2],     bf1 = s1b[c2+1];
    const float sc0 = s1s[128+c2], sc1 = s1s[128+c2+1];
    const float bc0 = s1b[128+c2], bc1 = s1b[128+c2+1];

    #pragma unroll
    for (int aa = 0; aa < 2; aa++) {
        const int a = ag + aa*4;
        const int atom = bx*8 + a;
        const int start = sA[a], end = sA[a+1];
        float sx = 0.f, sy = 0.f;
        for (int row = start; row < end; row++) {
            float2 f = *(const float2*)&g_gated[(size_t)row*C2A + c2];
            float2 c = *(const float2*)&g_gated[(size_t)row*C2A + 128 + c2];
            float fx = f.x * sf0 + bf0, fy = f.y * sf1 + bf1;
            float cx = c.x * sc0 + bc0, cy = c.y * sc1 + bc1;
            sx += fast_sigmoid(fx) * fast_softplus(cx);
            sy += fast_sigmoid(fy) * fast_softplus(cy);
        }
        *(float2*)&g_ns[(size_t)atom*AFEA + c2] = make_float2(sx, sy);
    }
}

// ---------------- K: BN2 stats + affine -------------------------------------
__global__ __launch_bounds__(256) void reduce2(const float* __restrict__ gamma2,
                                               const float* __restrict__ beta2) {
    __shared__ float ss[256], sq[256];
    const int c = blockIdx.x, tid = threadIdx.x;
    float s = 0.f, q = 0.f;
    for (int r = tid; r < NATOM; r += 256) {
        float v = g_ns[(size_t)r * AFEA + c];
        s += v; q += v * v;
    }
    ss[tid] = s; sq[tid] = q; __syncthreads();
    for (int off = 128; off > 0; off >>= 1) {
        if (tid < off) { ss[tid] += ss[tid + off]; sq[tid] += sq[tid + off]; }
        __syncthreads();
    }
    if (tid == 0) {
        float mean = ss[0] / (float)NATOM;
        float var  = sq[0] / (float)NATOM - mean * mean;
        float sc   = rsqrtf(var + EPSV) * gamma2[c];
        g_scale2[c] = sc;
        g_shift2[c] = beta2[c] - mean * sc;
    }
}

// ---------------- K: out = softplus(atom + BN2(nbr_sumed)) ------------------
__global__ __launch_bounds__(256) void out_k(const float* __restrict__ atom,
                                             float* __restrict__ out) {
    int i = blockIdx.x * 256 + threadIdx.x;
    if (i < NATOM * AFEA) {
        int c = i & 127;
        float v = atom[i] + g_ns[i] * g_scale2[c] + g_shift2[c];
        out[i] = fmaxf(v, 0.f) + __logf(1.f + __expf(-fabsf(v)));
    }
}

// ---------------- launch ----------------------------------------------------
extern "C" void kernel_launch(void* const* d_in, const int* in_sizes, int n_in,
                              void* d_out, int out_size) {
    const float* atom  = (const float*)d_in[0];
    const float* nbr   = (const float*)d_in[1];
    const int*   idx   = (const int*)  d_in[2];
    const float* mask  = (const float*)d_in[3];
    const float* W     = (const float*)d_in[4];
    const float* bfc   = (const float*)d_in[5];
    const float* g1    = (const float*)d_in[6];
    const float* b1    = (const float*)d_in[7];
    const float* g2    = (const float*)d_in[8];
    const float* b2    = (const float*)d_in[9];
    float* out = (float*)d_out;

    cudaFuncSetAttribute(gemm_gated_tc, cudaFuncAttributeMaxDynamicSharedMemorySize, SM_TOTAL);

    scan1        <<<NSC, 256>>>(mask);                                         // 0
    scan2        <<<1, 1024>>>();                                              // 1
    scan3        <<<NSC, 256>>>(mask);                                         // 2
    gemm_p12_tc  <<<dim3((NATOM + 127) / 128, 4), 256>>>(atom, W);             // 3 (profiled)
    gemm_gated_tc<<<GTILES/2, 192, SM_TOTAL>>>(nbr, W, bfc, idx, 0);           // 4
    gemm_gated_tc<<<GTILES/2, 192, SM_TOTAL>>>(nbr, W, bfc, idx, GTILES/2);    // 5
    reduce_cols  <<<512, 256>>>();                                             // 6
    gate_apply   <<<GTILES, 256>>>(g1, b1);                                    // 7
    reduce2      <<<AFEA, 256>>>(g2, b2);                                      // 8
    out_k        <<<(NATOM * AFEA + 255) / 256, 256>>>(atom, out);             // 9
}

// round 7
// speedup vs baseline: 2.1237x; 1.1074x over previous
#include <cuda_runtime.h>
#include <cuda_bf16.h>
#include <math.h>
#include <stdint.h>

// Problem constants
#define NATOM 50000
#define MNBR  12
#define AFEA  128
#define NBRF  64
#define NM    (NATOM*MNBR)     // 600000
#define C2A   256
#define EPSV  1e-5f
#define GTILES (NM/96)         // 6250 worst-case row tiles of 96
#define SCB   1024
#define NSC   ((NM + SCB - 1) / SCB)   // 586

// ---------------- scratch (device globals) ----------------------------------
__device__ float g_P1[(size_t)NATOM*C2A];
__device__ float g_P2[(size_t)NATOM*C2A];
__device__ float g_gated[(size_t)NM*C2A];     // compact rows used: [0, nlive)
__device__ float g_psum[(size_t)GTILES*C2A];
__device__ float g_psq [(size_t)GTILES*C2A];
__device__ float g_ns[NATOM*AFEA];
__device__ float g_colsum[C2A];
__device__ float g_colsq[C2A];
__device__ float g_cntf;
__device__ int   g_nlive;
__device__ int   g_bcnt[NSC];
__device__ int   g_boff[NSC];
__device__ int   g_pos[NM];                   // exclusive live-count before item i
__device__ int   g_live[NM];                  // compact -> original row
__device__ float g_scale2[AFEA], g_shift2[AFEA];

// ---------------- helpers ----------------------------------------------------
__device__ __forceinline__ void bsplit(float x, __nv_bfloat16& h, __nv_bfloat16& l) {
    h = __float2bfloat16(x);
    l = __float2bfloat16(x - __bfloat162float(h));
}

__device__ __forceinline__ void mma_bf16(float* c, const uint32_t* a,
                                         uint32_t b0, uint32_t b1) {
    asm volatile(
        "mma.sync.aligned.m16n8k16.row.col.f32.bf16.bf16.f32 "
        "{%0,%1,%2,%3}, {%4,%5,%6,%7}, {%8,%9}, {%0,%1,%2,%3};\n"
        : "+f"(c[0]), "+f"(c[1]), "+f"(c[2]), "+f"(c[3])
        : "r"(a[0]), "r"(a[1]), "r"(a[2]), "r"(a[3]), "r"(b0), "r"(b1));
}

__device__ __forceinline__ void ldsm_x4(uint32_t addr, uint32_t& r0, uint32_t& r1,
                                        uint32_t& r2, uint32_t& r3) {
    asm volatile("ldmatrix.sync.aligned.m8n8.x4.shared.b16 {%0,%1,%2,%3}, [%4];"
                 : "=r"(r0), "=r"(r1), "=r"(r2), "=r"(r3) : "r"(addr));
}

__device__ __forceinline__ float fast_sigmoid(float x) {
    return __fdividef(1.f, 1.f + __expf(-x));
}
__device__ __forceinline__ float fast_softplus(float x) {
    return fmaxf(x, 0.f) + __logf(1.f + __expf(-fabsf(x)));
}

// ---------------- scan kernels (deterministic int compaction) ---------------
__global__ __launch_bounds__(256) void scan1(const float* __restrict__ mask) {
    __shared__ int sw[8];
    const int b = blockIdx.x, tid = threadIdx.x;
    const int base = b * SCB;
    int c = 0;
    #pragma unroll
    for (int k = 0; k < 4; k++) {
        int i = base + tid*4 + k;
        if (i < NM) c += (mask[i] != 0.f);
    }
    int v = c;
    #pragma unroll
    for (int off = 16; off > 0; off >>= 1) v += __shfl_xor_sync(0xffffffffu, v, off);
    if ((tid & 31) == 0) sw[tid >> 5] = v;
    __syncthreads();
    if (tid == 0) {
        int t = 0;
        #pragma unroll
        for (int i = 0; i < 8; i++) t += sw[i];
        g_bcnt[b] = t;
    }
}

__global__ __launch_bounds__(1024) void scan2() {
    __shared__ int s[1024];
    const int tid = threadIdx.x;
    int v = (tid < NSC) ? g_bcnt[tid] : 0;
    s[tid] = v;
    __syncthreads();
    for (int off = 1; off < 1024; off <<= 1) {
        int t = (tid >= off) ? s[tid - off] : 0;
        __syncthreads();
        s[tid] += t;
        __syncthreads();
    }
    if (tid < NSC) g_boff[tid] = s[tid] - v;   // exclusive
    if (tid == 1023) {
        g_nlive = s[1023];
        g_cntf  = (float)s[1023];
    }
}

__global__ __launch_bounds__(256) void scan3(const float* __restrict__ mask) {
    __shared__ int s[256];
    const int b = blockIdx.x, tid = threadIdx.x;
    const int base = b * SCB;
    int c = 0;
    #pragma unroll
    for (int k = 0; k < 4; k++) {
        int i = base + tid*4 + k;
        if (i < NM) c += (mask[i] != 0.f);
    }
    s[tid] = c;
    __syncthreads();
    for (int off = 1; off < 256; off <<= 1) {
        int t = (tid >= off) ? s[tid - off] : 0;
        __syncthreads();
        s[tid] += t;
        __syncthreads();
    }
    int p = g_boff[b] + s[tid] - c;   // exclusive position for first item
    #pragma unroll
    for (int k = 0; k < 4; k++) {
        int i = base + tid*4 + k;
        if (i < NM) {
            g_pos[i] = p;
            if (mask[i] != 0.f) { g_live[p] = i; p++; }
        }
    }
}

// ---------------- K: P1 or P2 64-col slice per block (occupancy fix) --------
#define PA2 40
__global__ __launch_bounds__(256) void gemm_p12_tc(const float* __restrict__ atom,
                                                   const float* __restrict__ W) {
    __shared__ __align__(16) __nv_bfloat16 Ahi[128*PA2], Alo[128*PA2];
    __shared__ __align__(16) __nv_bfloat16 Bhi[64*PA2],  Blo[64*PA2];

    const int tid = threadIdx.x;
    const int bx = blockIdx.x, by = blockIdx.y;   // by 0..7
    const int w = tid >> 5, lane = tid & 31, g = lane >> 2, tig = lane & 3;
    const int cb = (by & 3) * 64;
    const float* Bsrc = W + ((by >= 4) ? 128*C2A : 0);
    float* Cdst = (by >= 4) ? g_P2 : g_P1;
    const int m4 = lane >> 3, lr = lane & 7;

    const uint32_t aHi0 = (uint32_t)__cvta_generic_to_shared(Ahi)
                        + ((w*16 + (m4 & 1)*8 + lr) * PA2 + (m4 >> 1)*8) * 2;
    const uint32_t aLo0 = (uint32_t)__cvta_generic_to_shared(Alo)
                        + ((w*16 + (m4 & 1)*8 + lr) * PA2 + (m4 >> 1)*8) * 2;
    const uint32_t bHi0 = (uint32_t)__cvta_generic_to_shared(Bhi)
                        + (((m4 >> 1)*8 + lr) * PA2 + (m4 & 1)*8) * 2;
    const uint32_t bLo0 = (uint32_t)__cvta_generic_to_shared(Blo)
                        + (((m4 >> 1)*8 + lr) * PA2 + (m4 & 1)*8) * 2;

    float acc[8][4];
    #pragma unroll
    for (int j = 0; j < 8; j++) { acc[j][0]=0.f; acc[j][1]=0.f; acc[j][2]=0.f; acc[j][3]=0.f; }

    for (int kc = 0; kc < 4; kc++) {
        __syncthreads();
        // A chunk 128x32, packed bf16x2 stores (float4 gmem reads)
        for (int i = tid; i < 128*8; i += 256) {
            int r = i >> 3, c4 = (i & 7) * 4;
            int gr = bx*128 + r;
            float4 v = (gr < NATOM)
                ? *(const float4*)&atom[(size_t)gr*128 + kc*32 + c4]
                : make_float4(0.f, 0.f, 0.f, 0.f);
            __nv_bfloat16 h0,l0,h1,l1,h2,l2,h3,l3;
            bsplit(v.x, h0, l0); bsplit(v.y, h1, l1);
            bsplit(v.z, h2, l2); bsplit(v.w, h3, l3);
            *(__nv_bfloat162*)&Ahi[r*PA2 + c4]     = __nv_bfloat162(h0, h1);
            *(__nv_bfloat162*)&Ahi[r*PA2 + c4 + 2] = __nv_bfloat162(h2, h3);
            *(__nv_bfloat162*)&Alo[r*PA2 + c4]     = __nv_bfloat162(l0, l1);
            *(__nv_bfloat162*)&Alo[r*PA2 + c4 + 2] = __nv_bfloat162(l2, l3);
        }
        // B chunk 32x64 -> [n][k], packed bf16x2 (coalesced over n)
        for (int i = tid; i < 64*16; i += 256) {
            int k2 = i >> 6, n = i & 63;
            float x0 = Bsrc[(size_t)(kc*32 + 2*k2)  *C2A + cb + n];
            float x1 = Bsrc[(size_t)(kc*32 + 2*k2+1)*C2A + cb + n];
            __nv_bfloat16 h0,l0,h1,l1;
            bsplit(x0, h0, l0); bsplit(x1, h1, l1);
            *(__nv_bfloat162*)&Bhi[n*PA2 + 2*k2] = __nv_bfloat162(h0, h1);
            *(__nv_bfloat162*)&Blo[n*PA2 + 2*k2] = __nv_bfloat162(l0, l1);
        }
        __syncthreads();

        #pragma unroll
        for (int ks = 0; ks < 2; ks++) {
            const uint32_t koff = ks * 16 * 2;
            uint32_t ah[4], al[4];
            ldsm_x4(aHi0 + koff, ah[0], ah[1], ah[2], ah[3]);
            ldsm_x4(aLo0 + koff, al[0], al[1], al[2], al[3]);
            #pragma unroll
            for (int jp = 0; jp < 4; jp++) {
                const uint32_t boff = (uint32_t)(jp*16*PA2*2) + koff;
                uint32_t bh0, bh1, bh2, bh3, bl0, bl1, bl2, bl3;
                ldsm_x4(bHi0 + boff, bh0, bh1, bh2, bh3);
                ldsm_x4(bLo0 + boff, bl0, bl1, bl2, bl3);
                mma_bf16(acc[2*jp],   ah, bh0, bh1);
                mma_bf16(acc[2*jp],   ah, bl0, bl1);
                mma_bf16(acc[2*jp],   al, bh0, bh1);
                mma_bf16(acc[2*jp+1], ah, bh2, bh3);
                mma_bf16(acc[2*jp+1], ah, bl2, bl3);
                mma_bf16(acc[2*jp+1], al, bh2, bh3);
            }
        }
    }

    const int gr0 = bx*128 + w*16 + g;
    const int gr1 = gr0 + 8;
    #pragma unroll
    for (int j = 0; j < 8; j++) {
        const int c = cb + j*8 + 2*tig;
        if (gr0 < NATOM)
            *(float2*)&Cdst[(size_t)gr0*C2A + c] = make_float2(acc[j][0], acc[j][1]);
        if (gr1 < NATOM)
            *(float2*)&Cdst[(size_t)gr1*C2A + c] = make_float2(acc[j][2], acc[j][3]);
    }
}

// ---------------- K: gated GEMM over COMPACT live rows ----------------------
#define PA 72
#define PC 68
#define SM_TOTAL 58240
__global__ __launch_bounds__(192) void gemm_gated_tc(const float* __restrict__ nbr,
                                                     const float* __restrict__ W,
                                                     const float* __restrict__ bfc,
                                                     const int*   __restrict__ idx,
                                                     int bx0) {
    extern __shared__ __align__(16) char smraw[];
    __nv_bfloat16* Ahi = (__nv_bfloat16*)(smraw);
    __nv_bfloat16* Alo = (__nv_bfloat16*)(smraw + 13824);
    __nv_bfloat16* Bhi = (__nv_bfloat16*)(smraw + 27648);
    __nv_bfloat16* Blo = (__nv_bfloat16*)(smraw + 27648 + 9216);
    float* Cs   = (float*)(smraw + 27648);
    float* Red  = (float*)(smraw + 53760);
    float* biasS= (float*)(smraw + 56832);
    int*   liveS= (int*)  (smraw + 57088);
    int*   nbS  = (int*)  (smraw + 57472);
    int*   nS   = (int*)  (smraw + 57856);

    const int tid = threadIdx.x;
    const int bx = blockIdx.x + bx0;
    const int nlive = g_nlive;

    if (bx*96 >= nlive) {
        for (int i = tid; i < C2A; i += 192) {
            g_psum[(size_t)bx*C2A + i] = 0.f;
            g_psq [(size_t)bx*C2A + i] = 0.f;
        }
        return;
    }
    const int rem = min(96, nlive - bx*96);

    const int w = tid >> 5, lane = tid & 31, g = lane >> 2, tig = lane & 3;
    const float* W3 = W + 256*C2A;
    const int m4 = lane >> 3, lr = lane & 7;

    const uint32_t aHi0 = (uint32_t)__cvta_generic_to_shared(Ahi)
                        + ((w*16 + (m4 & 1)*8 + lr) * PA + (m4 >> 1)*8) * 2;
    const uint32_t aLo0 = (uint32_t)__cvta_generic_to_shared(Alo)
                        + ((w*16 + (m4 & 1)*8 + lr) * PA + (m4 >> 1)*8) * 2;
    const uint32_t bHi0 = (uint32_t)__cvta_generic_to_shared(Bhi)
                        + (((m4 >> 1)*8 + lr) * PA + (m4 & 1)*8) * 2;
    const uint32_t bLo0 = (uint32_t)__cvta_generic_to_shared(Blo)
                        + (((m4 >> 1)*8 + lr) * PA + (m4 & 1)*8) * 2;

    if (tid < 96) {
        int li = bx*96 + tid;
        int r = (li < nlive) ? g_live[li] : -1;
        liveS[tid] = r;
        nbS[tid] = (r >= 0) ? idx[r] : 0;
        nS[tid]  = (r >= 0) ? r / MNBR : 0;
    }
    __syncthreads();

    for (int i = tid; i < 96*16; i += 192) {
        int r = i >> 4, c4 = (i & 15) * 4;
        int src = liveS[r];
        float4 v = (src >= 0) ? *(const float4*)&nbr[(size_t)src*64 + c4]
                              : make_float4(0.f, 0.f, 0.f, 0.f);
        __nv_bfloat16 h0,l0,h1,l1,h2,l2,h3,l3;
        bsplit(v.x, h0, l0); bsplit(v.y, h1, l1);
        bsplit(v.z, h2, l2); bsplit(v.w, h3, l3);
        *(__nv_bfloat162*)&Ahi[r*PA + c4]     = __nv_bfloat162(h0, h1);
        *(__nv_bfloat162*)&Ahi[r*PA + c4 + 2] = __nv_bfloat162(h2, h3);
        *(__nv_bfloat162*)&Alo[r*PA + c4]     = __nv_bfloat162(l0, l1);
        *(__nv_bfloat162*)&Alo[r*PA + c4 + 2] = __nv_bfloat162(l2, l3);
    }

    const int q = tid & 15;
    const int rsub = tid >> 4;

    for (int by = 0; by < 4; by++) {
        __syncthreads();
        for (int i = tid; i < 64*32; i += 192) {
            int k2 = i >> 6, n = i & 63;
            float x0 = W3[(size_t)(2*k2)  *C2A + by*64 + n];
            float x1 = W3[(size_t)(2*k2+1)*C2A + by*64 + n];
            __nv_bfloat16 h0,l0,h1,l1;
            bsplit(x0, h0, l0); bsplit(x1, h1, l1);
            *(__nv_bfloat162*)&Bhi[n*PA + 2*k2] = __nv_bfloat162(h0, h1);
            *(__nv_bfloat162*)&Blo[n*PA + 2*k2] = __nv_bfloat162(l0, l1);
        }
        if (tid < 16)
            *(float4*)&biasS[tid*4] = *(const float4*)&bfc[by*64 + tid*4];
        __syncthreads();

        float acc[8][4];
        #pragma unroll
        for (int j = 0; j < 8; j++) { acc[j][0]=0.f; acc[j][1]=0.f; acc[j][2]=0.f; acc[j][3]=0.f; }

        #pragma unroll
        for (int ks = 0; ks < 4; ks++) {
            const uint32_t koff = ks * 16 * 2;
            uint32_t ah[4], al[4];
            ldsm_x4(aHi0 + koff, ah[0], ah[1], ah[2], ah[3]);
            ldsm_x4(aLo0 + koff, al[0], al[1], al[2], al[3]);
            #pragma unroll
            for (int jp = 0; jp < 4; jp++) {
                const uint32_t boff = (uint32_t)(jp*16*PA*2) + koff;
                uint32_t bh0, bh1, bh2, bh3, bl0, bl1, bl2, bl3;
                ldsm_x4(bHi0 + boff, bh0, bh1, bh2, bh3);
                ldsm_x4(bLo0 + boff, bl0, bl1, bl2, bl3);
                mma_bf16(acc[2*jp],   ah, bh0, bh1);
                mma_bf16(acc[2*jp],   ah, bl0, bl1);
                mma_bf16(acc[2*jp],   al, bh0, bh1);
                mma_bf16(acc[2*jp+1], ah, bh2, bh3);
                mma_bf16(acc[2*jp+1], ah, bl2, bl3);
                mma_bf16(acc[2*jp+1], al, bh2, bh3);
            }
        }

        __syncthreads();
        {
            const int rl0 = w*16 + g, rl1 = rl0 + 8;
            #pragma unroll
            for (int j = 0; j < 8; j++) {
                const int c = j*8 + 2*tig;
                *(float2*)&Cs[rl0*PC + c] = make_float2(acc[j][0], acc[j][1]);
                *(float2*)&Cs[rl1*PC + c] = make_float2(acc[j][2], acc[j][3]);
            }
        }
        __syncthreads();

        float s0=0.f,s1=0.f,s2=0.f,s3=0.f, q0=0.f,q1=0.f,q2=0.f,q3=0.f;
        #pragma unroll
        for (int it = 0; it < 8; it++) {
            const int r = it*12 + rsub;
            if (r < rem) {
                float4 cv = *(const float4*)&Cs[r*PC + q*4];
                float4 p1 = *(const float4*)&g_P1[(size_t)nS[r]*C2A + by*64 + q*4];
                float4 p2 = *(const float4*)&g_P2[(size_t)nbS[r]*C2A + by*64 + q*4];
                float4 bb = *(const float4*)&biasS[q*4];
                float4 v;
                v.x = cv.x + p1.x + p2.x + bb.x;
                v.y = cv.y + p1.y + p2.y + bb.y;
                v.z = cv.z + p1.z + p2.z + bb.z;
                v.w = cv.w + p1.w + p2.w + bb.w;
                *(float4*)&g_gated[((size_t)(bx*96 + r))*C2A + by*64 + q*4] = v;
                s0 += v.x; s1 += v.y; s2 += v.z; s3 += v.w;
                q0 += v.x*v.x; q1 += v.y*v.y; q2 += v.z*v.z; q3 += v.w*v.w;
            }
        }

        s0 += __shfl_xor_sync(0xffffffffu, s0, 16);
        s1 += __shfl_xor_sync(0xffffffffu, s1, 16);
        s2 += __shfl_xor_sync(0xffffffffu, s2, 16);
        s3 += __shfl_xor_sync(0xffffffffu, s3, 16);
        q0 += __shfl_xor_sync(0xffffffffu, q0, 16);
        q1 += __shfl_xor_sync(0xffffffffu, q1, 16);
        q2 += __shfl_xor_sync(0xffffffffu, q2, 16);
        q3 += __shfl_xor_sync(0xffffffffu, q3, 16);
        if (lane < 16) {
            float* d = &Red[w*128 + lane*8];
            d[0]=s0; d[1]=s1; d[2]=s2; d[3]=s3;
            d[4]=q0; d[5]=q1; d[6]=q2; d[7]=q3;
        }
        __syncthreads();
        if (tid < 64) {
            float ts = 0.f, tq = 0.f;
            const int o = (tid >> 2)*8 + (tid & 3);
            #pragma unroll
            for (int w2 = 0; w2 < 6; w2++) {
                ts += Red[w2*128 + o];
                tq += Red[w2*128 + o + 4];
            }
            g_psum[(size_t)bx*C2A + by*64 + tid] = ts;
            g_psq [(size_t)bx*C2A + by*64 + tid] = tq;
        }
    }
}

// ---------------- K: reduce partials -> column sums -------------------------
__global__ __launch_bounds__(256) void reduce_cols() {
    __shared__ float sm[256];
    const int b = blockIdx.x, tid = threadIdx.x;
    float s = 0.f;
    if (b < 256) {
        for (int i = tid; i < GTILES; i += 256) s += g_psum[(size_t)i * C2A + b];
    } else {
        int c = b - 256;
        for (int i = tid; i < GTILES; i += 256) s += g_psq[(size_t)i * C2A + c];
    }
    sm[tid] = s; __syncthreads();
    for (int off = 128; off > 0; off >>= 1) {
        if (tid < off) sm[tid] += sm[tid + off];
        __syncthreads();
    }
    if (tid == 0) {
        if (b < 256) g_colsum[b] = sm[0];
        else         g_colsq[b - 256] = sm[0];
    }
}

// ---------------- K: BN1-apply + gate + per-atom sum (compact rows) ---------
__global__ __launch_bounds__(256) void gate_apply(const float* __restrict__ gamma1,
                                                  const float* __restrict__ beta1) {
    __shared__ float s1s[C2A], s1b[C2A];
    __shared__ int sA[9];
    const int tid = threadIdx.x;
    const int bx = blockIdx.x;

    {
        float cnt = g_cntf;
        float mean = g_colsum[tid] / cnt;
        float var  = g_colsq[tid] / cnt - mean * mean;
        float sc   = rsqrtf(var + EPSV) * gamma1[tid];
        s1s[tid] = sc;
        s1b[tid] = beta1[tid] - mean * sc;
    }
    if (tid < 9) {
        int i9 = (bx*8 + tid) * MNBR;
        sA[tid] = (i9 < NM) ? g_pos[i9] : g_nlive;
    }
    __syncthreads();

    const int c2 = (tid & 63) * 2;
    const int ag = tid >> 6;
    const float sf0 = s1s[c2],     sf1 = s1s[c2+1];
    const float bf0 = s1b[c2],     bf1 = s1b[c2+1];
    const float sc0 = s1s[128+c2], sc1 = s1s[128+c2+1];
    const float bc0 = s1b[128+c2], bc1 = s1b[128+c2+1];

    #pragma unroll
    for (int aa = 0; aa < 2; aa++) {
        const int a = ag + aa*4;
        const int atom = bx*8 + a;
        const int start = sA[a], end = sA[a+1];
        float sx = 0.f, sy = 0.f;
        for (int row = start; row < end; row++) {
            float2 f = *(const float2*)&g_gated[(size_t)row*C2A + c2];
            float2 c = *(const float2*)&g_gated[(size_t)row*C2A + 128 + c2];
            float fx = f.x * sf0 + bf0, fy = f.y * sf1 + bf1;
            float cx = c.x * sc0 + bc0, cy = c.y * sc1 + bc1;
            sx += fast_sigmoid(fx) * fast_softplus(cx);
            sy += fast_sigmoid(fy) * fast_softplus(cy);
        }
        *(float2*)&g_ns[(size_t)atom*AFEA + c2] = make_float2(sx, sy);
    }
}

// ---------------- K: BN2 stats + affine -------------------------------------
__global__ __launch_bounds__(256) void reduce2(const float* __restrict__ gamma2,
                                               const float* __restrict__ beta2) {
    __shared__ float ss[256], sq[256];
    const int c = blockIdx.x, tid = threadIdx.x;
    float s = 0.f, q = 0.f;
    for (int r = tid; r < NATOM; r += 256) {
        float v = g_ns[(size_t)r * AFEA + c];
        s += v; q += v * v;
    }
    ss[tid] = s; sq[tid] = q; __syncthreads();
    for (int off = 128; off > 0; off >>= 1) {
        if (tid < off) { ss[tid] += ss[tid + off]; sq[tid] += sq[tid + off]; }
        __syncthreads();
    }
    if (tid == 0) {
        float mean = ss[0] / (float)NATOM;
        float var  = sq[0] / (float)NATOM - mean * mean;
        float sc   = rsqrtf(var + EPSV) * gamma2[c];
        g_scale2[c] = sc;
        g_shift2[c] = beta2[c] - mean * sc;
    }
}

// ---------------- K: out = softplus(atom + BN2(nbr_sumed)) ------------------
__global__ __launch_bounds__(256) void out_k(const float* __restrict__ atom,
                                             float* __restrict__ out) {
    int i = blockIdx.x * 256 + threadIdx.x;
    if (i < NATOM * AFEA) {
        int c = i & 127;
        float v = atom[i] + g_ns[i] * g_scale2[c] + g_shift2[c];
        out[i] = fmaxf(v, 0.f) + __logf(1.f + __expf(-fabsf(v)));
    }
}

// ---------------- launch ----------------------------------------------------
extern "C" void kernel_launch(void* const* d_in, const int* in_sizes, int n_in,
                              void* d_out, int out_size) {
    const float* atom  = (const float*)d_in[0];
    const float* nbr   = (const float*)d_in[1];
    const int*   idx   = (const int*)  d_in[2];
    const float* mask  = (const float*)d_in[3];
    const float* W     = (const float*)d_in[4];
    const float* bfc   = (const float*)d_in[5];
    const float* g1    = (const float*)d_in[6];
    const float* b1    = (const float*)d_in[7];
    const float* g2    = (const float*)d_in[8];
    const float* b2    = (const float*)d_in[9];
    float* out = (float*)d_out;

    cudaFuncSetAttribute(gemm_gated_tc, cudaFuncAttributeMaxDynamicSharedMemorySize, SM_TOTAL);

    scan1        <<<NSC, 256>>>(mask);                                         // 0
    scan2        <<<1, 1024>>>();                                              // 1
    scan3        <<<NSC, 256>>>(mask);                                         // 2
    gemm_p12_tc  <<<dim3((NATOM + 127) / 128, 8), 256>>>(atom, W);             // 3 (profiled)
    gemm_gated_tc<<<GTILES/2, 192, SM_TOTAL>>>(nbr, W, bfc, idx, 0);           // 4
    gemm_gated_tc<<<GTILES/2, 192, SM_TOTAL>>>(nbr, W, bfc, idx, GTILES/2);    // 5
    reduce_cols  <<<512, 256>>>();                                             // 6
    gate_apply   <<<GTILES, 256>>>(g1, b1);                                    // 7
    reduce2      <<<AFEA, 256>>>(g2, b2);                                      // 8
    out_k        <<<(NATOM * AFEA + 255) / 256, 256>>>(atom, out);             // 9
}

// round 9
// speedup vs baseline: 2.5387x; 1.1954x over previous
#include <cuda_runtime.h>
#include <cuda_bf16.h>
#include <cuda_fp16.h>
#include <math.h>
#include <stdint.h>

// Problem constants
#define NATOM 50000
#define MNBR  12
#define AFEA  128
#define NBRF  64
#define NM    (NATOM*MNBR)     // 600000
#define C2A   256
#define EPSV  1e-5f
#define GTILES (NM/96)         // 6250 row tiles of 96
#define SCB   1024
#define NSC   ((NM + SCB - 1) / SCB)   // 586
#define GA_ATOMS 32

// ---------------- scratch (device globals) ----------------------------------
__device__ float  g_P1[(size_t)NATOM*C2A];
__device__ float  g_P2[(size_t)NATOM*C2A];
__device__ __half g_gated[(size_t)NM*C2A];    // compact rows [0, nlive), fp16
__device__ float  g_psum[(size_t)GTILES*C2A];
__device__ float  g_psq [(size_t)GTILES*C2A];
__device__ float  g_ns[NATOM*AFEA];
__device__ float  g_colsum[C2A];
__device__ float  g_colsq[C2A];
__device__ float  g_cntf;
__device__ int    g_nlive;
__device__ int    g_bcnt[NSC];
__device__ int    g_boff[NSC];
__device__ int    g_pos[NM];
__device__ int    g_live[NM];
__device__ float  g_scale2[AFEA], g_shift2[AFEA];

// ---------------- helpers ----------------------------------------------------
__device__ __forceinline__ void bsplit(float x, __nv_bfloat16& h, __nv_bfloat16& l) {
    h = __float2bfloat16(x);
    l = __float2bfloat16(x - __bfloat162float(h));
}

__device__ __forceinline__ void mma_bf16(float* c, const uint32_t* a,
                                         uint32_t b0, uint32_t b1) {
    asm volatile(
        "mma.sync.aligned.m16n8k16.row.col.f32.bf16.bf16.f32 "
        "{%0,%1,%2,%3}, {%4,%5,%6,%7}, {%8,%9}, {%0,%1,%2,%3};\n"
        : "+f"(c[0]), "+f"(c[1]), "+f"(c[2]), "+f"(c[3])
        : "r"(a[0]), "r"(a[1]), "r"(a[2]), "r"(a[3]), "r"(b0), "r"(b1));
}
__device__ __forceinline__ void ldsm_x4(uint32_t addr, uint32_t& r0, uint32_t& r1,
                                        uint32_t& r2, uint32_t& r3) {
    asm volatile("ldmatrix.sync.aligned.m8n8.x4.shared.b16 {%0,%1,%2,%3}, [%4];"
                 : "=r"(r0), "=r"(r1), "=r"(r2), "=r"(r3) : "r"(addr));
}
__device__ __forceinline__ float fast_sigmoid(float x) {
    return __fdividef(1.f, 1.f + __expf(-x));
}
__device__ __forceinline__ float fast_softplus(float x) {
    return fmaxf(x, 0.f) + __logf(1.f + __expf(-fabsf(x)));
}

// ---------------- scan kernels (deterministic int compaction) ---------------
__global__ __launch_bounds__(256) void scan1(const float* __restrict__ mask) {
    __shared__ int sw[8];
    const int b = blockIdx.x, tid = threadIdx.x;
    const int base = b * SCB;
    int c = 0;
    #pragma unroll
    for (int k = 0; k < 4; k++) {
        int i = base + tid*4 + k;
        if (i < NM) c += (mask[i] != 0.f);
    }
    int v = c;
    #pragma unroll
    for (int off = 16; off > 0; off >>= 1) v += __shfl_xor_sync(0xffffffffu, v, off);
    if ((tid & 31) == 0) sw[tid >> 5] = v;
    __syncthreads();
    if (tid == 0) {
        int t = 0;
        #pragma unroll
        for (int i = 0; i < 8; i++) t += sw[i];
        g_bcnt[b] = t;
    }
}

__global__ __launch_bounds__(1024) void scan2() {
    __shared__ int s[1024];
    const int tid = threadIdx.x;
    int v = (tid < NSC) ? g_bcnt[tid] : 0;
    s[tid] = v;
    __syncthreads();
    for (int off = 1; off < 1024; off <<= 1) {
        int t = (tid >= off) ? s[tid - off] : 0;
        __syncthreads();
        s[tid] += t;
        __syncthreads();
    }
    if (tid < NSC) g_boff[tid] = s[tid] - v;
    if (tid == 1023) {
        g_nlive = s[1023];
        g_cntf  = (float)s[1023];
    }
}

__global__ __launch_bounds__(256) void scan3(const float* __restrict__ mask) {
    __shared__ int s[256];
    const int b = blockIdx.x, tid = threadIdx.x;
    const int base = b * SCB;
    int c = 0;
    #pragma unroll
    for (int k = 0; k < 4; k++) {
        int i = base + tid*4 + k;
        if (i < NM) c += (mask[i] != 0.f);
    }
    s[tid] = c;
    __syncthreads();
    for (int off = 1; off < 256; off <<= 1) {
        int t = (tid >= off) ? s[tid - off] : 0;
        __syncthreads();
        s[tid] += t;
        __syncthreads();
    }
    int p = g_boff[b] + s[tid] - c;
    #pragma unroll
    for (int k = 0; k < 4; k++) {
        int i = base + tid*4 + k;
        if (i < NM) {
            g_pos[i] = p;
            if (mask[i] != 0.f) { g_live[p] = i; p++; }
        }
    }
}

// ---------------- K: P1 or P2 64-col slice per block ------------------------
#define PA2 40
__global__ __launch_bounds__(256) void gemm_p12_tc(const float* __restrict__ atom,
                                                   const float* __restrict__ W) {
    __shared__ __align__(16) __nv_bfloat16 Ahi[128*PA2], Alo[128*PA2];
    __shared__ __align__(16) __nv_bfloat16 Bhi[64*PA2],  Blo[64*PA2];

    const int tid = threadIdx.x;
    const int bx = blockIdx.x, by = blockIdx.y;   // by 0..7
    const int w = tid >> 5, lane = tid & 31, g = lane >> 2, tig = lane & 3;
    const int cb = (by & 3) * 64;
    const float* Bsrc = W + ((by >= 4) ? 128*C2A : 0);
    float* Cdst = (by >= 4) ? g_P2 : g_P1;
    const int m4 = lane >> 3, lr = lane & 7;

    const uint32_t aHi0 = (uint32_t)__cvta_generic_to_shared(Ahi)
                        + ((w*16 + (m4 & 1)*8 + lr) * PA2 + (m4 >> 1)*8) * 2;
    const uint32_t aLo0 = (uint32_t)__cvta_generic_to_shared(Alo)
                        + ((w*16 + (m4 & 1)*8 + lr) * PA2 + (m4 >> 1)*8) * 2;
    const uint32_t bHi0 = (uint32_t)__cvta_generic_to_shared(Bhi)
                        + (((m4 >> 1)*8 + lr) * PA2 + (m4 & 1)*8) * 2;
    const uint32_t bLo0 = (uint32_t)__cvta_generic_to_shared(Blo)
                        + (((m4 >> 1)*8 + lr) * PA2 + (m4 & 1)*8) * 2;

    float acc[8][4];
    #pragma unroll
    for (int j = 0; j < 8; j++) { acc[j][0]=0.f; acc[j][1]=0.f; acc[j][2]=0.f; acc[j][3]=0.f; }

    for (int kc = 0; kc < 4; kc++) {
        __syncthreads();
        for (int i = tid; i < 128*8; i += 256) {
            int r = i >> 3, c4 = (i & 7) * 4;
            int gr = bx*128 + r;
            float4 v = (gr < NATOM)
                ? *(const float4*)&atom[(size_t)gr*128 + kc*32 + c4]
                : make_float4(0.f, 0.f, 0.f, 0.f);
            __nv_bfloat16 h0,l0,h1,l1,h2,l2,h3,l3;
            bsplit(v.x, h0, l0); bsplit(v.y, h1, l1);
            bsplit(v.z, h2, l2); bsplit(v.w, h3, l3);
            *(__nv_bfloat162*)&Ahi[r*PA2 + c4]     = __nv_bfloat162(h0, h1);
            *(__nv_bfloat162*)&Ahi[r*PA2 + c4 + 2] = __nv_bfloat162(h2, h3);
            *(__nv_bfloat162*)&Alo[r*PA2 + c4]     = __nv_bfloat162(l0, l1);
            *(__nv_bfloat162*)&Alo[r*PA2 + c4 + 2] = __nv_bfloat162(l2, l3);
        }
        for (int i = tid; i < 64*16; i += 256) {
            int k2 = i >> 6, n = i & 63;
            float x0 = Bsrc[(size_t)(kc*32 + 2*k2)  *C2A + cb + n];
            float x1 = Bsrc[(size_t)(kc*32 + 2*k2+1)*C2A + cb + n];
            __nv_bfloat16 h0,l0,h1,l1;
            bsplit(x0, h0, l0); bsplit(x1, h1, l1);
            *(__nv_bfloat162*)&Bhi[n*PA2 + 2*k2] = __nv_bfloat162(h0, h1);
            *(__nv_bfloat162*)&Blo[n*PA2 + 2*k2] = __nv_bfloat162(l0, l1);
        }
        __syncthreads();

        #pragma unroll
        for (int ks = 0; ks < 2; ks++) {
            const uint32_t koff = ks * 16 * 2;
            uint32_t ah[4], al[4];
            ldsm_x4(aHi0 + koff, ah[0], ah[1], ah[2], ah[3]);
            ldsm_x4(aLo0 + koff, al[0], al[1], al[2], al[3]);
            #pragma unroll
            for (int jp = 0; jp < 4; jp++) {
                const uint32_t boff = (uint32_t)(jp*16*PA2*2) + koff;
                uint32_t bh0, bh1, bh2, bh3, bl0, bl1, bl2, bl3;
                ldsm_x4(bHi0 + boff, bh0, bh1, bh2, bh3);
                ldsm_x4(bLo0 + boff, bl0, bl1, bl2, bl3);
                mma_bf16(acc[2*jp],   ah, bh0, bh1);
                mma_bf16(acc[2*jp],   ah, bl0, bl1);
                mma_bf16(acc[2*jp],   al, bh0, bh1);
                mma_bf16(acc[2*jp+1], ah, bh2, bh3);
                mma_bf16(acc[2*jp+1], ah, bl2, bl3);
                mma_bf16(acc[2*jp+1], al, bh2, bh3);
            }
        }
    }

    const int gr0 = bx*128 + w*16 + g;
    const int gr1 = gr0 + 8;
    #pragma unroll
    for (int j = 0; j < 8; j++) {
        const int c = cb + j*8 + 2*tig;
        if (gr0 < NATOM)
            *(float2*)&Cdst[(size_t)gr0*C2A + c] = make_float2(acc[j][0], acc[j][1]);
        if (gr1 < NATOM)
            *(float2*)&Cdst[(size_t)gr1*C2A + c] = make_float2(acc[j][2], acc[j][3]);
    }
}

// ---------------- K: gated GEMM over COMPACT live rows (fp16 output) --------
#define PA 72
#define PC 68
// dyn smem (bytes): Ahi 0(13824) Alo 13824 -> 27648
//   union{Bhi 9216 @27648 + Blo 9216 @36864 ; Cs 96*68*4=26112 @27648} -> 53760
//   Red 1536 ->55296, biasS 256 ->55552, liveS 384 ->55936, nbS 384 ->56320,
//   nS 384 ->56704
#define SM_TOTAL 56704
__global__ __launch_bounds__(192) void gemm_gated_tc(const float* __restrict__ nbr,
                                                     const float* __restrict__ W,
                                                     const float* __restrict__ bfc,
                                                     const int*   __restrict__ idx) {
    extern __shared__ __align__(16) char smraw[];
    __nv_bfloat16* Ahi = (__nv_bfloat16*)(smraw);
    __nv_bfloat16* Alo = (__nv_bfloat16*)(smraw + 13824);
    __nv_bfloat16* Bhi = (__nv_bfloat16*)(smraw + 27648);
    __nv_bfloat16* Blo = (__nv_bfloat16*)(smraw + 36864);
    float* Cs   = (float*)(smraw + 27648);
    float* Red  = (float*)(smraw + 53760);
    float* biasS= (float*)(smraw + 55296);
    int*   liveS= (int*)  (smraw + 55552);
    int*   nbS  = (int*)  (smraw + 55936);
    int*   nS   = (int*)  (smraw + 56320);

    const int tid = threadIdx.x;
    const int bx = blockIdx.x;
    const int nlive = g_nlive;

    if (bx*96 >= nlive) {
        for (int i = tid; i < C2A; i += 192) {
            g_psum[(size_t)bx*C2A + i] = 0.f;
            g_psq [(size_t)bx*C2A + i] = 0.f;
        }
        return;
    }
    const int rem = min(96, nlive - bx*96);

    const int w = tid >> 5, lane = tid & 31, g = lane >> 2, tig = lane & 3;
    const float* W3 = W + 256*C2A;
    const int m4 = lane >> 3, lr = lane & 7;

    const uint32_t aHi0 = (uint32_t)__cvta_generic_to_shared(Ahi)
                        + ((w*16 + (m4 & 1)*8 + lr) * PA + (m4 >> 1)*8) * 2;
    const uint32_t aLo0 = (uint32_t)__cvta_generic_to_shared(Alo)
                        + ((w*16 + (m4 & 1)*8 + lr) * PA + (m4 >> 1)*8) * 2;
    const uint32_t bHi0 = (uint32_t)__cvta_generic_to_shared(Bhi)
                        + (((m4 >> 1)*8 + lr) * PA + (m4 & 1)*8) * 2;
    const uint32_t bLo0 = (uint32_t)__cvta_generic_to_shared(Blo)
                        + (((m4 >> 1)*8 + lr) * PA + (m4 & 1)*8) * 2;

    if (tid < 96) {
        int li = bx*96 + tid;
        int r = (li < nlive) ? g_live[li] : -1;
        liveS[tid] = r;
        nbS[tid] = (r >= 0) ? idx[r] : 0;
        nS[tid]  = (r >= 0) ? r / MNBR : 0;
    }
    __syncthreads();

    for (int i = tid; i < 96*16; i += 192) {
        int r = i >> 4, c4 = (i & 15) * 4;
        int src = liveS[r];
        float4 v = (src >= 0) ? *(const float4*)&nbr[(size_t)src*64 + c4]
                              : make_float4(0.f, 0.f, 0.f, 0.f);
        __nv_bfloat16 h0,l0,h1,l1,h2,l2,h3,l3;
        bsplit(v.x, h0, l0); bsplit(v.y, h1, l1);
        bsplit(v.z, h2, l2); bsplit(v.w, h3, l3);
        *(__nv_bfloat162*)&Ahi[r*PA + c4]     = __nv_bfloat162(h0, h1);
        *(__nv_bfloat162*)&Ahi[r*PA + c4 + 2] = __nv_bfloat162(h2, h3);
        *(__nv_bfloat162*)&Alo[r*PA + c4]     = __nv_bfloat162(l0, l1);
        *(__nv_bfloat162*)&Alo[r*PA + c4 + 2] = __nv_bfloat162(l2, l3);
    }

    const int q = tid & 15;
    const int rsub = tid >> 4;

    for (int by = 0; by < 4; by++) {
        __syncthreads();
        for (int i = tid; i < 64*32; i += 192) {
            int k2 = i >> 6, n = i & 63;
            float x0 = W3[(size_t)(2*k2)  *C2A + by*64 + n];
            float x1 = W3[(size_t)(2*k2+1)*C2A + by*64 + n];
            __nv_bfloat16 h0,l0,h1,l1;
            bsplit(x0, h0, l0); bsplit(x1, h1, l1);
            *(__nv_bfloat162*)&Bhi[n*PA + 2*k2] = __nv_bfloat162(h0, h1);
            *(__nv_bfloat162*)&Blo[n*PA + 2*k2] = __nv_bfloat162(l0, l1);
        }
        if (tid < 16)
            *(float4*)&biasS[tid*4] = *(const float4*)&bfc[by*64 + tid*4];
        __syncthreads();

        float acc[8][4];
        #pragma unroll
        for (int j = 0; j < 8; j++) { acc[j][0]=0.f; acc[j][1]=0.f; acc[j][2]=0.f; acc[j][3]=0.f; }

        #pragma unroll
        for (int ks = 0; ks < 4; ks++) {
            const uint32_t koff = ks * 16 * 2;
            uint32_t ah[4], al[4];
            ldsm_x4(aHi0 + koff, ah[0], ah[1], ah[2], ah[3]);
            ldsm_x4(aLo0 + koff, al[0], al[1], al[2], al[3]);
            #pragma unroll
            for (int jp = 0; jp < 4; jp++) {
                const uint32_t boff = (uint32_t)(jp*16*PA*2) + koff;
                uint32_t bh0, bh1, bh2, bh3, bl0, bl1, bl2, bl3;
                ldsm_x4(bHi0 + boff, bh0, bh1, bh2, bh3);
                ldsm_x4(bLo0 + boff, bl0, bl1, bl2, bl3);
                mma_bf16(acc[2*jp],   ah, bh0, bh1);
                mma_bf16(acc[2*jp],   ah, bl0, bl1);
                mma_bf16(acc[2*jp],   al, bh0, bh1);
                mma_bf16(acc[2*jp+1], ah, bh2, bh3);
                mma_bf16(acc[2*jp+1], ah, bl2, bl3);
                mma_bf16(acc[2*jp+1], al, bh2, bh3);
            }
        }

        __syncthreads();   // B reads done; region becomes Cs
        {
            const int rl0 = w*16 + g, rl1 = rl0 + 8;
            #pragma unroll
            for (int j = 0; j < 8; j++) {
                const int c = j*8 + 2*tig;
                *(float2*)&Cs[rl0*PC + c] = make_float2(acc[j][0], acc[j][1]);
                *(float2*)&Cs[rl1*PC + c] = make_float2(acc[j][2], acc[j][3]);
            }
        }
        __syncthreads();

        // Coalesced epilogue; fp16 gated store
        float s0=0.f,s1=0.f,s2=0.f,s3=0.f, q0=0.f,q1=0.f,q2=0.f,q3=0.f;
        #pragma unroll
        for (int it = 0; it < 8; it++) {
            const int r = it*12 + rsub;
            if (r < rem) {
                float4 cv = *(const float4*)&Cs[r*PC + q*4];
                float4 p1 = *(const float4*)&g_P1[(size_t)nS[r]*C2A + by*64 + q*4];
                float4 p2 = *(const float4*)&g_P2[(size_t)nbS[r]*C2A + by*64 + q*4];
                float4 bb = *(const float4*)&biasS[q*4];
                float4 v;
                v.x = cv.x + p1.x + p2.x + bb.x;
                v.y = cv.y + p1.y + p2.y + bb.y;
                v.z = cv.z + p1.z + p2.z + bb.z;
                v.w = cv.w + p1.w + p2.w + bb.w;
                __half2 h01 = __floats2half2_rn(v.x, v.y);
                __half2 h23 = __floats2half2_rn(v.z, v.w);
                *(uint2*)&g_gated[((size_t)(bx*96 + r))*C2A + by*64 + q*4] =
                    make_uint2(*(uint32_t*)&h01, *(uint32_t*)&h23);
                s0 += v.x; s1 += v.y; s2 += v.z; s3 += v.w;
                q0 += v.x*v.x; q1 += v.y*v.y; q2 += v.z*v.z; q3 += v.w*v.w;
            }
        }
        s0 += __shfl_xor_sync(0xffffffffu, s0, 16);
        s1 += __shfl_xor_sync(0xffffffffu, s1, 16);
        s2 += __shfl_xor_sync(0xffffffffu, s2, 16);
        s3 += __shfl_xor_sync(0xffffffffu, s3, 16);
        q0 += __shfl_xor_sync(0xffffffffu, q0, 16);
        q1 += __shfl_xor_sync(0xffffffffu, q1, 16);
        q2 += __shfl_xor_sync(0xffffffffu, q2, 16);
        q3 += __shfl_xor_sync(0xffffffffu, q3, 16);

        // Two-pass Red reduction (1536 B buffer): s pass, then q pass
        if (lane < 16) {
            float* d = &Red[w*64 + lane*4];
            d[0]=s0; d[1]=s1; d[2]=s2; d[3]=s3;
        }
        __syncthreads();
        if (tid < 64) {
            float ts = 0.f;
            #pragma unroll
            for (int w2 = 0; w2 < 6; w2++) ts += Red[w2*64 + tid];
            g_psum[(size_t)bx*C2A + by*64 + tid] = ts;
        }
        __syncthreads();
        if (lane < 16) {
            float* d = &Red[w*64 + lane*4];
            d[0]=q0; d[1]=q1; d[2]=q2; d[3]=q3;
        }
        __syncthreads();
        if (tid < 64) {
            float tq = 0.f;
            #pragma unroll
            for (int w2 = 0; w2 < 6; w2++) tq += Red[w2*64 + tid];
            g_psq[(size_t)bx*C2A + by*64 + tid] = tq;
        }
    }
}

// ---------------- K: reduce partials -> column sums -------------------------
__global__ __launch_bounds__(256) void reduce_cols() {
    __shared__ float sm[256];
    const int b = blockIdx.x, tid = threadIdx.x;
    float s = 0.f;
    if (b < 256) {
        for (int i = tid; i < GTILES; i += 256) s += g_psum[(size_t)i * C2A + b];
    } else {
        int c = b - 256;
        for (int i = tid; i < GTILES; i += 256) s += g_psq[(size_t)i * C2A + c];
    }
    sm[tid] = s; __syncthreads();
    for (int off = 128; off > 0; off >>= 1) {
        if (tid < off) sm[tid] += sm[tid + off];
        __syncthreads();
    }
    if (tid == 0) {
        if (b < 256) g_colsum[b] = sm[0];
        else         g_colsq[b - 256] = sm[0];
    }
}

// ---------------- K: BN1-apply + gate + per-atom sum (32 atoms/block) -------
__global__ __launch_bounds__(256) void gate_apply(const float* __restrict__ gamma1,
                                                  const float* __restrict__ beta1) {
    __shared__ float s1s[C2A], s1b[C2A];
    __shared__ int sA[GA_ATOMS + 1];
    const int tid = threadIdx.x;
    const int bx = blockIdx.x;

    {
        float cnt = g_cntf;
        float mean = g_colsum[tid] / cnt;
        float var  = g_colsq[tid] / cnt - mean * mean;
        float sc   = rsqrtf(var + EPSV) * gamma1[tid];
        s1s[tid] = sc;
        s1b[tid] = beta1[tid] - mean * sc;
    }
    if (tid <= GA_ATOMS) {
        int i9 = (bx*GA_ATOMS + tid) * MNBR;
        sA[tid] = (i9 < NM) ? g_pos[i9] : g_nlive;
    }
    __syncthreads();

    const int c2 = (tid & 63) * 2;
    const int ag = tid >> 6;                   // 0..3
    const float sf0 = s1s[c2],     sf1 = s1s[c2+1];
    const float bf0 = s1b[c2],     bf1 = s1b[c2+1];
    const float sc0 = s1s[128+c2], sc1 = s1s[128+c2+1];
    const float bc0 = s1b[128+c2], bc1 = s1b[128+c2+1];

    #pragma unroll
    for (int aa = 0; aa < GA_ATOMS/4; aa++) {
        const int a = aa*4 + ag;
        const int atom = bx*GA_ATOMS + a;
        if (atom < NATOM) {
            const int start = sA[a], end = sA[a+1];
            float sx = 0.f, sy = 0.f;
            for (int row = start; row < end; row++) {
                float2 f = __half22float2(*(const __half2*)&g_gated[(size_t)row*C2A + c2]);
                float2 c = __half22float2(*(const __half2*)&g_gated[(size_t)row*C2A + 128 + c2]);
                float fx = f.x * sf0 + bf0, fy = f.y * sf1 + bf1;
                float cx = c.x * sc0 + bc0, cy = c.y * sc1 + bc1;
                sx += fast_sigmoid(fx) * fast_softplus(cx);
                sy += fast_sigmoid(fy) * fast_softplus(cy);
            }
            *(float2*)&g_ns[(size_t)atom*AFEA + c2] = make_float2(sx, sy);
        }
    }
}

// ---------------- K: BN2 stats + affine -------------------------------------
__global__ __launch_bounds__(256) void reduce2(const float* __restrict__ gamma2,
                                               const float* __restrict__ beta2) {
    __shared__ float ss[256], sq[256];
    const int c = blockIdx.x, tid = threadIdx.x;
    float s = 0.f, q = 0.f;
    for (int r = tid; r < NATOM; r += 256) {
        float v = g_ns[(size_t)r * AFEA + c];
        s += v; q += v * v;
    }
    ss[tid] = s; sq[tid] = q; __syncthreads();
    for (int off = 128; off > 0; off >>= 1) {
        if (tid < off) { ss[tid] += ss[tid + off]; sq[tid] += sq[tid + off]; }
        __syncthreads();
    }
    if (tid == 0) {
        float mean = ss[0] / (float)NATOM;
        float var  = sq[0] / (float)NATOM - mean * mean;
        float sc   = rsqrtf(var + EPSV) * gamma2[c];
        g_scale2[c] = sc;
        g_shift2[c] = beta2[c] - mean * sc;
    }
}

// ---------------- K: out = softplus(atom + BN2(nbr_sumed)) ------------------
__global__ __launch_bounds__(256) void out_k(const float* __restrict__ atom,
                                             float* __restrict__ out) {
    int i = blockIdx.x * 256 + threadIdx.x;
    if (i < NATOM * AFEA) {
        int c = i & 127;
        float v = atom[i] + g_ns[i] * g_scale2[c] + g_shift2[c];
        out[i] = fmaxf(v, 0.f) + __logf(1.f + __expf(-fabsf(v)));
    }
}

// ---------------- launch ----------------------------------------------------
extern "C" void kernel_launch(void* const* d_in, const int* in_sizes, int n_in,
                              void* d_out, int out_size) {
    const float* atom  = (const float*)d_in[0];
    const float* nbr   = (const float*)d_in[1];
    const int*   idx   = (const int*)  d_in[2];
    const float* mask  = (const float*)d_in[3];
    const float* W     = (const float*)d_in[4];
    const float* bfc   = (const float*)d_in[5];
    const float* g1    = (const float*)d_in[6];
    const float* b1    = (const float*)d_in[7];
    const float* g2    = (const float*)d_in[8];
    const float* b2    = (const float*)d_in[9];
    float* out = (float*)d_out;

    cudaFuncSetAttribute(gemm_gated_tc, cudaFuncAttributeMaxDynamicSharedMemorySize, SM_TOTAL);

    scan1        <<<NSC, 256>>>(mask);                                   // 0
    scan2        <<<1, 1024>>>();                                        // 1
    scan3        <<<NSC, 256>>>(mask);                                   // 2
    gemm_p12_tc  <<<dim3((NATOM + 127) / 128, 8), 256>>>(atom, W);       // 3 (profiled)
    gemm_gated_tc<<<GTILES, 192, SM_TOTAL>>>(nbr, W, bfc, idx);          // 4
    reduce_cols  <<<512, 256>>>();                                       // 5
    gate_apply   <<<(NATOM + GA_ATOMS - 1)/GA_ATOMS, 256>>>(g1, b1);     // 6
    reduce2      <<<AFEA, 256>>>(g2, b2);                                // 7
    out_k        <<<(NATOM * AFEA + 255) / 256, 256>>>(atom, out);       // 8
}

// round 10
// speedup vs baseline: 2.7002x; 1.0636x over previous
#include <cuda_runtime.h>
#include <cuda_bf16.h>
#include <cuda_fp16.h>
#include <math.h>
#include <stdint.h>

// Problem constants
#define NATOM 50000
#define MNBR  12
#define AFEA  128
#define NBRF  64
#define NM    (NATOM*MNBR)     // 600000
#define C2A   256
#define EPSV  1e-5f
#define GTILES (NM/96)         // 6250 row tiles of 96
#define SCB   1024
#define NSC   ((NM + SCB - 1) / SCB)   // 586
#define GA_ATOMS 32
#define PA2 40
#define PA  72
#define PC  68
#define P12_BX ((NATOM + 127)/128)     // 391

// ---------------- scratch (device globals) ----------------------------------
__device__ float  g_P1[(size_t)NATOM*C2A];
__device__ float  g_P2[(size_t)NATOM*C2A];
__device__ __half g_gated[(size_t)NM*C2A];    // compact rows [0, nlive), fp16
__device__ float  g_psum[(size_t)GTILES*C2A];
__device__ float  g_psq [(size_t)GTILES*C2A];
__device__ float  g_ns[NATOM*AFEA];
__device__ float  g_colsum[C2A];
__device__ float  g_colsq[C2A];
__device__ float  g_cntf;
__device__ int    g_nlive;
__device__ int    g_bcnt[NSC];
__device__ int    g_boff[NSC];
__device__ int    g_pos[NM];
__device__ int    g_live[NM];
__device__ float  g_scale2[AFEA], g_shift2[AFEA];
// pre-split operands
__device__ __align__(16) __nv_bfloat16 g_atHi[(size_t)NATOM*128];
__device__ __align__(16) __nv_bfloat16 g_atLo[(size_t)NATOM*128];
__device__ __align__(16) __nv_bfloat16 g_wspHi[8*4*64*PA2];   // p12 B image
__device__ __align__(16) __nv_bfloat16 g_wspLo[8*4*64*PA2];
__device__ __align__(16) __nv_bfloat16 g_w3Hi[4*64*PA];       // gated B image
__device__ __align__(16) __nv_bfloat16 g_w3Lo[4*64*PA];

// ---------------- helpers ----------------------------------------------------
__device__ __forceinline__ void bsplit(float x, __nv_bfloat16& h, __nv_bfloat16& l) {
    h = __float2bfloat16(x);
    l = __float2bfloat16(x - __bfloat162float(h));
}
__device__ __forceinline__ uint32_t bpack(__nv_bfloat16 a, __nv_bfloat16 b) {
    __nv_bfloat162 t(a, b);
    return *(uint32_t*)&t;
}
__device__ __forceinline__ void mma_bf16(float* c, const uint32_t* a,
                                         uint32_t b0, uint32_t b1) {
    asm volatile(
        "mma.sync.aligned.m16n8k16.row.col.f32.bf16.bf16.f32 "
        "{%0,%1,%2,%3}, {%4,%5,%6,%7}, {%8,%9}, {%0,%1,%2,%3};\n"
        : "+f"(c[0]), "+f"(c[1]), "+f"(c[2]), "+f"(c[3])
        : "r"(a[0]), "r"(a[1]), "r"(a[2]), "r"(a[3]), "r"(b0), "r"(b1));
}
__device__ __forceinline__ void ldsm_x4(uint32_t addr, uint32_t& r0, uint32_t& r1,
                                        uint32_t& r2, uint32_t& r3) {
    asm volatile("ldmatrix.sync.aligned.m8n8.x4.shared.b16 {%0,%1,%2,%3}, [%4];"
                 : "=r"(r0), "=r"(r1), "=r"(r2), "=r"(r3) : "r"(addr));
}
__device__ __forceinline__ float fast_sigmoid(float x) {
    return __fdividef(1.f, 1.f + __expf(-x));
}
__device__ __forceinline__ float fast_softplus(float x) {
    return fmaxf(x, 0.f) + __logf(1.f + __expf(-fabsf(x)));
}

// ---------------- K0: mega kernel — scan1 + atom split + weight splits ------
// blocks [0,586): scan1; [586,6836): atom split; [6836,6964): W1/W2 image;
// [6964,6996): W3 image
__global__ __launch_bounds__(256) void mega_split(const float* __restrict__ mask,
                                                  const float* __restrict__ atom,
                                                  const float* __restrict__ W) {
    const int b = blockIdx.x, tid = threadIdx.x;
    if (b < NSC) {
        // scan1
        __shared__ int sw[8];
        const int base = b * SCB;
        int c = 0;
        #pragma unroll
        for (int k = 0; k < 4; k++) {
            int i = base + tid*4 + k;
            if (i < NM) c += (mask[i] != 0.f);
        }
        int v = c;
        #pragma unroll
        for (int off = 16; off > 0; off >>= 1) v += __shfl_xor_sync(0xffffffffu, v, off);
        if ((tid & 31) == 0) sw[tid >> 5] = v;
        __syncthreads();
        if (tid == 0) {
            int t = 0;
            #pragma unroll
            for (int i = 0; i < 8; i++) t += sw[i];
            g_bcnt[b] = t;
        }
    } else if (b < NSC + 6250) {
        // atom split: one float4 per thread
        size_t t = (size_t)(b - NSC)*256 + tid;
        if (t < (size_t)NATOM*32) {
            float4 v = *(const float4*)&atom[t*4];
            __nv_bfloat16 h0,l0,h1,l1,h2,l2,h3,l3;
            bsplit(v.x, h0, l0); bsplit(v.y, h1, l1);
            bsplit(v.z, h2, l2); bsplit(v.w, h3, l3);
            ((uint2*)g_atHi)[t] = make_uint2(bpack(h0,h1), bpack(h2,h3));
            ((uint2*)g_atLo)[t] = make_uint2(bpack(l0,l1), bpack(l2,l3));
        }
    } else if (b < NSC + 6250 + 128) {
        // W1/W2 smem image: t -> (by, kc, n, k2)
        int t = (b - NSC - 6250)*256 + tid;     // < 32768
        int by = t >> 12, kc = (t >> 10) & 3, n = (t >> 4) & 63, k2 = t & 15;
        int wrow = ((by >= 4) ? 128 : 0) + kc*32 + 2*k2;
        int col  = (by & 3)*64 + n;
        float x0 = W[(size_t)wrow*C2A + col];
        float x1 = W[(size_t)(wrow+1)*C2A + col];
        __nv_bfloat16 h0,l0,h1,l1;
        bsplit(x0, h0, l0); bsplit(x1, h1, l1);
        int o = ((by*4 + kc)*64 + n)*PA2 + 2*k2;
        *(uint32_t*)&g_wspHi[o] = bpack(h0, h1);
        *(uint32_t*)&g_wspLo[o] = bpack(l0, l1);
    } else {
        // W3 smem image: t -> (by, n, k2)
        int t = (b - NSC - 6250 - 128)*256 + tid;   // < 8192
        int by = t >> 11, n = (t >> 5) & 63, k2 = t & 31;
        const float* W3 = W + 256*C2A;
        float x0 = W3[(size_t)(2*k2)  *C2A + by*64 + n];
        float x1 = W3[(size_t)(2*k2+1)*C2A + by*64 + n];
        __nv_bfloat16 h0,l0,h1,l1;
        bsplit(x0, h0, l0); bsplit(x1, h1, l1);
        int o = (by*64 + n)*PA + 2*k2;
        *(uint32_t*)&g_w3Hi[o] = bpack(h0, h1);
        *(uint32_t*)&g_w3Lo[o] = bpack(l0, l1);
    }
}

// ---------------- K1: top-level scan ----------------------------------------
__global__ __launch_bounds__(1024) void scan2() {
    __shared__ int s[1024];
    const int tid = threadIdx.x;
    int v = (tid < NSC) ? g_bcnt[tid] : 0;
    s[tid] = v;
    __syncthreads();
    for (int off = 1; off < 1024; off <<= 1) {
        int t = (tid >= off) ? s[tid - off] : 0;
        __syncthreads();
        s[tid] += t;
        __syncthreads();
    }
    if (tid < NSC) g_boff[tid] = s[tid] - v;
    if (tid == 1023) {
        g_nlive = s[1023];
        g_cntf  = (float)s[1023];
    }
}

// ---------------- K2: scan3 + p12 (merged; disjoint block ranges) -----------
__global__ __launch_bounds__(256) void scan3_p12(const float* __restrict__ mask) {
    __shared__ __align__(16) __nv_bfloat16 Ahi[128*PA2], Alo[128*PA2];
    __shared__ __align__(16) __nv_bfloat16 Bhi[64*PA2],  Blo[64*PA2];
    __shared__ int sS[256];

    const int bb = blockIdx.x, tid = threadIdx.x;
    if (bb < NSC) {
        // ---- scan3 ----
        const int base = bb * SCB;
        int c = 0;
        #pragma unroll
        for (int k = 0; k < 4; k++) {
            int i = base + tid*4 + k;
            if (i < NM) c += (mask[i] != 0.f);
        }
        sS[tid] = c;
        __syncthreads();
        for (int off = 1; off < 256; off <<= 1) {
            int t = (tid >= off) ? sS[tid - off] : 0;
            __syncthreads();
            sS[tid] += t;
            __syncthreads();
        }
        int p = g_boff[bb] + sS[tid] - c;
        #pragma unroll
        for (int k = 0; k < 4; k++) {
            int i = base + tid*4 + k;
            if (i < NM) {
                g_pos[i] = p;
                if (mask[i] != 0.f) { g_live[p] = i; p++; }
            }
        }
        return;
    }

    // ---- p12 ----
    const int lin = bb - NSC;
    const int bx = lin % P12_BX;
    const int by = lin / P12_BX;              // 0..7
    const int w = tid >> 5, lane = tid & 31, g = lane >> 2, tig = lane & 3;
    const int cb = (by & 3) * 64;
    float* Cdst = (by >= 4) ? g_P2 : g_P1;
    const int m4 = lane >> 3, lr = lane & 7;

    const uint32_t aHi0 = (uint32_t)__cvta_generic_to_shared(Ahi)
                        + ((w*16 + (m4 & 1)*8 + lr) * PA2 + (m4 >> 1)*8) * 2;
    const uint32_t aLo0 = (uint32_t)__cvta_generic_to_shared(Alo)
                        + ((w*16 + (m4 & 1)*8 + lr) * PA2 + (m4 >> 1)*8) * 2;
    const uint32_t bHi0 = (uint32_t)__cvta_generic_to_shared(Bhi)
                        + (((m4 >> 1)*8 + lr) * PA2 + (m4 & 1)*8) * 2;
    const uint32_t bLo0 = (uint32_t)__cvta_generic_to_shared(Blo)
                        + (((m4 >> 1)*8 + lr) * PA2 + (m4 & 1)*8) * 2;

    float acc[8][4];
    #pragma unroll
    for (int j = 0; j < 8; j++) { acc[j][0]=0.f; acc[j][1]=0.f; acc[j][2]=0.f; acc[j][3]=0.f; }

    for (int kc = 0; kc < 4; kc++) {
        __syncthreads();
        // A: pure copies from pre-split atom (128 rows x 32 bf16, hi+lo)
        for (int i = tid; i < 1024; i += 256) {
            int a = i >> 9;
            int j = i & 511; int r = j >> 2, u = j & 3;
            int gr = bx*128 + r;
            uint4 v = make_uint4(0, 0, 0, 0);
            if (gr < NATOM) {
                const __nv_bfloat16* src = a ? g_atLo : g_atHi;
                v = ((const uint4*)&src[(size_t)gr*128 + kc*32])[u];
            }
            uint4* dst = (uint4*)(a ? Alo : Ahi);
            dst[r*5 + u] = v;
        }
        // B: pure copies from precomputed image (64 x PA2, hi+lo)
        {
            const uint4* sh = (const uint4*)&g_wspHi[(size_t)((by*4 + kc)*64) * PA2];
            const uint4* sl = (const uint4*)&g_wspLo[(size_t)((by*4 + kc)*64) * PA2];
            uint4* dh = (uint4*)Bhi;
            uint4* dl = (uint4*)Blo;
            for (int i = tid; i < 320; i += 256) { dh[i] = sh[i]; dl[i] = sl[i]; }
        }
        __syncthreads();

        #pragma unroll
        for (int ks = 0; ks < 2; ks++) {
            const uint32_t koff = ks * 16 * 2;
            uint32_t ah[4], al[4];
            ldsm_x4(aHi0 + koff, ah[0], ah[1], ah[2], ah[3]);
            ldsm_x4(aLo0 + koff, al[0], al[1], al[2], al[3]);
            #pragma unroll
            for (int jp = 0; jp < 4; jp++) {
                const uint32_t boff = (uint32_t)(jp*16*PA2*2) + koff;
                uint32_t bh0, bh1, bh2, bh3, bl0, bl1, bl2, bl3;
                ldsm_x4(bHi0 + boff, bh0, bh1, bh2, bh3);
                ldsm_x4(bLo0 + boff, bl0, bl1, bl2, bl3);
                mma_bf16(acc[2*jp],   ah, bh0, bh1);
                mma_bf16(acc[2*jp],   ah, bl0, bl1);
                mma_bf16(acc[2*jp],   al, bh0, bh1);
                mma_bf16(acc[2*jp+1], ah, bh2, bh3);
                mma_bf16(acc[2*jp+1], ah, bl2, bl3);
                mma_bf16(acc[2*jp+1], al, bh2, bh3);
            }
        }
    }

    const int gr0 = bx*128 + w*16 + g;
    const int gr1 = gr0 + 8;
    #pragma unroll
    for (int j = 0; j < 8; j++) {
        const int c = cb + j*8 + 2*tig;
        if (gr0 < NATOM)
            *(float2*)&Cdst[(size_t)gr0*C2A + c] = make_float2(acc[j][0], acc[j][1]);
        if (gr1 < NATOM)
            *(float2*)&Cdst[(size_t)gr1*C2A + c] = make_float2(acc[j][2], acc[j][3]);
    }
}

// ---------------- K3: gated GEMM over COMPACT live rows (fp16 out) ----------
// dyn smem (bytes): Ahi 0(13824) Alo 13824 -> 27648
//   union{Bhi 9216 @27648 + Blo 9216 @36864 ; Cs 96*68*4=26112 @27648} -> 53760
//   Red 1536 ->55296, biasS 256 ->55552, liveS 384 ->55936, nbS 384 ->56320,
//   nS 384 ->56704
#define SM_TOTAL 56704
__global__ __launch_bounds__(192) void gemm_gated_tc(const float* __restrict__ nbr,
                                                     const float* __restrict__ bfc,
                                                     const int*   __restrict__ idx) {
    extern __shared__ __align__(16) char smraw[];
    __nv_bfloat16* Ahi = (__nv_bfloat16*)(smraw);
    __nv_bfloat16* Alo = (__nv_bfloat16*)(smraw + 13824);
    __nv_bfloat16* Bhi = (__nv_bfloat16*)(smraw + 27648);
    __nv_bfloat16* Blo = (__nv_bfloat16*)(smraw + 36864);
    float* Cs   = (float*)(smraw + 27648);
    float* Red  = (float*)(smraw + 53760);
    float* biasS= (float*)(smraw + 55296);
    int*   liveS= (int*)  (smraw + 55552);
    int*   nbS  = (int*)  (smraw + 55936);
    int*   nS   = (int*)  (smraw + 56320);

    const int tid = threadIdx.x;
    const int bx = blockIdx.x;
    const int nlive = g_nlive;

    if (bx*96 >= nlive) {
        for (int i = tid; i < C2A; i += 192) {
            g_psum[(size_t)bx*C2A + i] = 0.f;
            g_psq [(size_t)bx*C2A + i] = 0.f;
        }
        return;
    }
    const int rem = min(96, nlive - bx*96);

    const int w = tid >> 5, lane = tid & 31, g = lane >> 2, tig = lane & 3;
    const int m4 = lane >> 3, lr = lane & 7;

    const uint32_t aHi0 = (uint32_t)__cvta_generic_to_shared(Ahi)
                        + ((w*16 + (m4 & 1)*8 + lr) * PA + (m4 >> 1)*8) * 2;
    const uint32_t aLo0 = (uint32_t)__cvta_generic_to_shared(Alo)
                        + ((w*16 + (m4 & 1)*8 + lr) * PA + (m4 >> 1)*8) * 2;
    const uint32_t bHi0 = (uint32_t)__cvta_generic_to_shared(Bhi)
                        + (((m4 >> 1)*8 + lr) * PA + (m4 & 1)*8) * 2;
    const uint32_t bLo0 = (uint32_t)__cvta_generic_to_shared(Blo)
                        + (((m4 >> 1)*8 + lr) * PA + (m4 & 1)*8) * 2;

    if (tid < 96) {
        int li = bx*96 + tid;
        int r = (li < nlive) ? g_live[li] : -1;
        liveS[tid] = r;
        nbS[tid] = (r >= 0) ? idx[r] : 0;
        nS[tid]  = (r >= 0) ? r / MNBR : 0;
    }
    __syncthreads();

    for (int i = tid; i < 96*16; i += 192) {
        int r = i >> 4, c4 = (i & 15) * 4;
        int src = liveS[r];
        float4 v = (src >= 0) ? *(const float4*)&nbr[(size_t)src*64 + c4]
                              : make_float4(0.f, 0.f, 0.f, 0.f);
        __nv_bfloat16 h0,l0,h1,l1,h2,l2,h3,l3;
        bsplit(v.x, h0, l0); bsplit(v.y, h1, l1);
        bsplit(v.z, h2, l2); bsplit(v.w, h3, l3);
        *(__nv_bfloat162*)&Ahi[r*PA + c4]     = __nv_bfloat162(h0, h1);
        *(__nv_bfloat162*)&Ahi[r*PA + c4 + 2] = __nv_bfloat162(h2, h3);
        *(__nv_bfloat162*)&Alo[r*PA + c4]     = __nv_bfloat162(l0, l1);
        *(__nv_bfloat162*)&Alo[r*PA + c4 + 2] = __nv_bfloat162(l2, l3);
    }

    const int q = tid & 15;
    const int rsub = tid >> 4;

    for (int by = 0; by < 4; by++) {
        __syncthreads();
        // B: pure copies from precomputed W3 image
        {
            const uint4* sh = (const uint4*)&g_w3Hi[(size_t)(by*64) * PA];
            const uint4* sl = (const uint4*)&g_w3Lo[(size_t)(by*64) * PA];
            uint4* dh = (uint4*)Bhi;
            uint4* dl = (uint4*)Blo;
            for (int i = tid; i < 576; i += 192) { dh[i] = sh[i]; dl[i] = sl[i]; }
        }
        if (tid < 16)
            *(float4*)&biasS[tid*4] = *(const float4*)&bfc[by*64 + tid*4];
        __syncthreads();

        float acc[8][4];
        #pragma unroll
        for (int j = 0; j < 8; j++) { acc[j][0]=0.f; acc[j][1]=0.f; acc[j][2]=0.f; acc[j][3]=0.f; }

        #pragma unroll
        for (int ks = 0; ks < 4; ks++) {
            const uint32_t koff = ks * 16 * 2;
            uint32_t ah[4], al[4];
            ldsm_x4(aHi0 + koff, ah[0], ah[1], ah[2], ah[3]);
            ldsm_x4(aLo0 + koff, al[0], al[1], al[2], al[3]);
            #pragma unroll
            for (int jp = 0; jp < 4; jp++) {
                const uint32_t boff = (uint32_t)(jp*16*PA*2) + koff;
                uint32_t bh0, bh1, bh2, bh3, bl0, bl1, bl2, bl3;
                ldsm_x4(bHi0 + boff, bh0, bh1, bh2, bh3);
                ldsm_x4(bLo0 + boff, bl0, bl1, bl2, bl3);
                mma_bf16(acc[2*jp],   ah, bh0, bh1);
                mma_bf16(acc[2*jp],   ah, bl0, bl1);
                mma_bf16(acc[2*jp],   al, bh0, bh1);
                mma_bf16(acc[2*jp+1], ah, bh2, bh3);
                mma_bf16(acc[2*jp+1], ah, bl2, bl3);
                mma_bf16(acc[2*jp+1], al, bh2, bh3);
            }
        }

        __syncthreads();
        {
            const int rl0 = w*16 + g, rl1 = rl0 + 8;
            #pragma unroll
            for (int j = 0; j < 8; j++) {
                const int c = j*8 + 2*tig;
                *(float2*)&Cs[rl0*PC + c] = make_float2(acc[j][0], acc[j][1]);
                *(float2*)&Cs[rl1*PC + c] = make_float2(acc[j][2], acc[j][3]);
            }
        }
        __syncthreads();

        float s0=0.f,s1=0.f,s2=0.f,s3=0.f, q0=0.f,q1=0.f,q2=0.f,q3=0.f;
        #pragma unroll
        for (int it = 0; it < 8; it++) {
            const int r = it*12 + rsub;
            if (r < rem) {
                float4 cv = *(const float4*)&Cs[r*PC + q*4];
                float4 p1 = *(const float4*)&g_P1[(size_t)nS[r]*C2A + by*64 + q*4];
                float4 p2 = *(const float4*)&g_P2[(size_t)nbS[r]*C2A + by*64 + q*4];
                float4 bb = *(const float4*)&biasS[q*4];
                float4 v;
                v.x = cv.x + p1.x + p2.x + bb.x;
                v.y = cv.y + p1.y + p2.y + bb.y;
                v.z = cv.z + p1.z + p2.z + bb.z;
                v.w = cv.w + p1.w + p2.w + bb.w;
                __half2 h01 = __floats2half2_rn(v.x, v.y);
                __half2 h23 = __floats2half2_rn(v.z, v.w);
                *(uint2*)&g_gated[((size_t)(bx*96 + r))*C2A + by*64 + q*4] =
                    make_uint2(*(uint32_t*)&h01, *(uint32_t*)&h23);
                s0 += v.x; s1 += v.y; s2 += v.z; s3 += v.w;
                q0 += v.x*v.x; q1 += v.y*v.y; q2 += v.z*v.z; q3 += v.w*v.w;
            }
        }
        s0 += __shfl_xor_sync(0xffffffffu, s0, 16);
        s1 += __shfl_xor_sync(0xffffffffu, s1, 16);
        s2 += __shfl_xor_sync(0xffffffffu, s2, 16);
        s3 += __shfl_xor_sync(0xffffffffu, s3, 16);
        q0 += __shfl_xor_sync(0xffffffffu, q0, 16);
        q1 += __shfl_xor_sync(0xffffffffu, q1, 16);
        q2 += __shfl_xor_sync(0xffffffffu, q2, 16);
        q3 += __shfl_xor_sync(0xffffffffu, q3, 16);

        if (lane < 16) {
            float* d = &Red[w*64 + lane*4];
            d[0]=s0; d[1]=s1; d[2]=s2; d[3]=s3;
        }
        __syncthreads();
        if (tid < 64) {
            float ts = 0.f;
            #pragma unroll
            for (int w2 = 0; w2 < 6; w2++) ts += Red[w2*64 + tid];
            g_psum[(size_t)bx*C2A + by*64 + tid] = ts;
        }
        __syncthreads();
        if (lane < 16) {
            float* d = &Red[w*64 + lane*4];
            d[0]=q0; d[1]=q1; d[2]=q2; d[3]=q3;
        }
        __syncthreads();
        if (tid < 64) {
            float tq = 0.f;
            #pragma unroll
            for (int w2 = 0; w2 < 6; w2++) tq += Red[w2*64 + tid];
            g_psq[(size_t)bx*C2A + by*64 + tid] = tq;
        }
    }
}

// ---------------- K4: reduce partials -> column sums ------------------------
__global__ __launch_bounds__(256) void reduce_cols() {
    __shared__ float sm[256];
    const int b = blockIdx.x, tid = threadIdx.x;
    float s = 0.f;
    if (b < 256) {
        for (int i = tid; i < GTILES; i += 256) s += g_psum[(size_t)i * C2A + b];
    } else {
        int c = b - 256;
        for (int i = tid; i < GTILES; i += 256) s += g_psq[(size_t)i * C2A + c];
    }
    sm[tid] = s; __syncthreads();
    for (int off = 128; off > 0; off >>= 1) {
        if (tid < off) sm[tid] += sm[tid + off];
        __syncthreads();
    }
    if (tid == 0) {
        if (b < 256) g_colsum[b] = sm[0];
        else         g_colsq[b - 256] = sm[0];
    }
}

// ---------------- K5: BN1-apply + gate + per-atom sum (32 atoms/block) ------
__global__ __launch_bounds__(256) void gate_apply(const float* __restrict__ gamma1,
                                                  const float* __restrict__ beta1) {
    __shared__ float s1s[C2A], s1b[C2A];
    __shared__ int sA[GA_ATOMS + 1];
    const int tid = threadIdx.x;
    const int bx = blockIdx.x;

    {
        float cnt = g_cntf;
        float mean = g_colsum[tid] / cnt;
        float var  = g_colsq[tid] / cnt - mean * mean;
        float sc   = rsqrtf(var + EPSV) * gamma1[tid];
        s1s[tid] = sc;
        s1b[tid] = beta1[tid] - mean * sc;
    }
    if (tid <= GA_ATOMS) {
        int i9 = (bx*GA_ATOMS + tid) * MNBR;
        sA[tid] = (i9 < NM) ? g_pos[i9] : g_nlive;
    }
    __syncthreads();

    const int c2 = (tid & 63) * 2;
    const int ag = tid >> 6;
    const float sf0 = s1s[c2],     sf1 = s1s[c2+1];
    const float bf0 = s1b[c2],     bf1 = s1b[c2+1];
    const float sc0 = s1s[128+c2], sc1 = s1s[128+c2+1];
    const float bc0 = s1b[128+c2], bc1 = s1b[128+c2+1];

    #pragma unroll
    for (int aa = 0; aa < GA_ATOMS/4; aa++) {
        const int a = aa*4 + ag;
        const int atom = bx*GA_ATOMS + a;
        if (atom < NATOM) {
            const int start = sA[a], end = sA[a+1];
            float sx = 0.f, sy = 0.f;
            for (int row = start; row < end; row++) {
                float2 f = __half22float2(*(const __half2*)&g_gated[(size_t)row*C2A + c2]);
                float2 c = __half22float2(*(const __half2*)&g_gated[(size_t)row*C2A + 128 + c2]);
                float fx = f.x * sf0 + bf0, fy = f.y * sf1 + bf1;
                float cx = c.x * sc0 + bc0, cy = c.y * sc1 + bc1;
                sx += fast_sigmoid(fx) * fast_softplus(cx);
                sy += fast_sigmoid(fy) * fast_softplus(cy);
            }
            *(float2*)&g_ns[(size_t)atom*AFEA + c2] = make_float2(sx, sy);
        }
    }
}

// ---------------- K6: BN2 stats + affine ------------------------------------
__global__ __launch_bounds__(256) void reduce2(const float* __restrict__ gamma2,
                                               const float* __restrict__ beta2) {
    __shared__ float ss[256], sq[256];
    const int c = blockIdx.x, tid = threadIdx.x;
    float s = 0.f, q = 0.f;
    for (int r = tid; r < NATOM; r += 256) {
        float v = g_ns[(size_t)r * AFEA + c];
        s += v; q += v * v;
    }
    ss[tid] = s; sq[tid] = q; __syncthreads();
    for (int off = 128; off > 0; off >>= 1) {
        if (tid < off) { ss[tid] += ss[tid + off]; sq[tid] += sq[tid + off]; }
        __syncthreads();
    }
    if (tid == 0) {
        float mean = ss[0] / (float)NATOM;
        float var  = sq[0] / (float)NATOM - mean * mean;
        float sc   = rsqrtf(var + EPSV) * gamma2[c];
        g_scale2[c] = sc;
        g_shift2[c] = beta2[c] - mean * sc;
    }
}

// ---------------- K7: out = softplus(atom + BN2(nbr_sumed)) -----------------
__global__ __launch_bounds__(256) void out_k(const float* __restrict__ atom,
                                             float* __restrict__ out) {
    int i = blockIdx.x * 256 + threadIdx.x;
    if (i < NATOM * AFEA) {
        int c = i & 127;
        float v = atom[i] + g_ns[i] * g_scale2[c] + g_shift2[c];
        out[i] = fmaxf(v, 0.f) + __logf(1.f + __expf(-fabsf(v)));
    }
}

// ---------------- launch ----------------------------------------------------
extern "C" void kernel_launch(void* const* d_in, const int* in_sizes, int n_in,
                              void* d_out, int out_size) {
    const float* atom  = (const float*)d_in[0];
    const float* nbr   = (const float*)d_in[1];
    const int*   idx   = (const int*)  d_in[2];
    const float* mask  = (const float*)d_in[3];
    const float* W     = (const float*)d_in[4];
    const float* bfc   = (const float*)d_in[5];
    const float* g1    = (const float*)d_in[6];
    const float* b1    = (const float*)d_in[7];
    const float* g2    = (const float*)d_in[8];
    const float* b2    = (const float*)d_in[9];
    float* out = (float*)d_out;

    cudaFuncSetAttribute(gemm_gated_tc, cudaFuncAttributeMaxDynamicSharedMemorySize, SM_TOTAL);

    mega_split   <<<NSC + 6250 + 128 + 32, 256>>>(mask, atom, W);        // 0
    scan2        <<<1, 1024>>>();                                        // 1
    scan3_p12    <<<NSC + P12_BX*8, 256>>>(mask);                        // 2
    gemm_gated_tc<<<GTILES, 192, SM_TOTAL>>>(nbr, bfc, idx);             // 3 (profiled)
    reduce_cols  <<<512, 256>>>();                                       // 4
    gate_apply   <<<(NATOM + GA_ATOMS - 1)/GA_ATOMS, 256>>>(g1, b1);     // 5
    reduce2      <<<AFEA, 256>>>(g2, b2);                                // 6
    out_k        <<<(NATOM * AFEA + 255) / 256, 256>>>(atom, out);       // 7
}

// round 11
// speedup vs baseline: 2.8510x; 1.0558x over previous
#include <cuda_runtime.h>
#include <cuda_bf16.h>
#include <cuda_fp16.h>
#include <math.h>
#include <stdint.h>

// Problem constants
#define NATOM 50000
#define MNBR  12
#define AFEA  128
#define NBRF  64
#define NM    (NATOM*MNBR)     // 600000
#define C2A   256
#define EPSV  1e-5f
#define GTILES (NM/96)         // 6250 row tiles of 96
#define SCB   1024
#define NSC   ((NM + SCB - 1) / SCB)   // 586
#define GA_ATOMS 32
#define PA2 40
#define PA  72
#define PC  68
#define P12_BX ((NATOM + 127)/128)     // 391

// ---------------- scratch (device globals) ----------------------------------
__device__ __half g_P1[(size_t)NATOM*C2A];    // fp16 precomputed projections
__device__ __half g_P2[(size_t)NATOM*C2A];
__device__ __half g_gated[(size_t)NM*C2A];    // compact rows [0, nlive), fp16
__device__ float  g_psum[(size_t)GTILES*C2A];
__device__ float  g_psq [(size_t)GTILES*C2A];
__device__ float  g_ns[NATOM*AFEA];
__device__ float  g_colsum[C2A];
__device__ float  g_colsq[C2A];
__device__ float  g_cntf;
__device__ int    g_nlive;
__device__ int    g_bcnt[NSC];
__device__ int    g_boff[NSC];
__device__ int    g_pos[NM];
__device__ int    g_live[NM];
__device__ float  g_scale2[AFEA], g_shift2[AFEA];
// pre-split operands
__device__ __align__(16) __nv_bfloat16 g_atHi[(size_t)NATOM*128];
__device__ __align__(16) __nv_bfloat16 g_atLo[(size_t)NATOM*128];
__device__ __align__(16) __nv_bfloat16 g_wspHi[8*4*64*PA2];   // p12 B image
__device__ __align__(16) __nv_bfloat16 g_wspLo[8*4*64*PA2];
__device__ __align__(16) __nv_bfloat16 g_w3Hi[4*64*PA];       // gated B image
__device__ __align__(16) __nv_bfloat16 g_w3Lo[4*64*PA];

// ---------------- helpers ----------------------------------------------------
__device__ __forceinline__ void bsplit(float x, __nv_bfloat16& h, __nv_bfloat16& l) {
    h = __float2bfloat16(x);
    l = __float2bfloat16(x - __bfloat162float(h));
}
__device__ __forceinline__ uint32_t bpack(__nv_bfloat16 a, __nv_bfloat16 b) {
    __nv_bfloat162 t(a, b);
    return *(uint32_t*)&t;
}
__device__ __forceinline__ void mma_bf16(float* c, const uint32_t* a,
                                         uint32_t b0, uint32_t b1) {
    asm volatile(
        "mma.sync.aligned.m16n8k16.row.col.f32.bf16.bf16.f32 "
        "{%0,%1,%2,%3}, {%4,%5,%6,%7}, {%8,%9}, {%0,%1,%2,%3};\n"
        : "+f"(c[0]), "+f"(c[1]), "+f"(c[2]), "+f"(c[3])
        : "r"(a[0]), "r"(a[1]), "r"(a[2]), "r"(a[3]), "r"(b0), "r"(b1));
}
__device__ __forceinline__ void ldsm_x4(uint32_t addr, uint32_t& r0, uint32_t& r1,
                                        uint32_t& r2, uint32_t& r3) {
    asm volatile("ldmatrix.sync.aligned.m8n8.x4.shared.b16 {%0,%1,%2,%3}, [%4];"
                 : "=r"(r0), "=r"(r1), "=r"(r2), "=r"(r3) : "r"(addr));
}
__device__ __forceinline__ float fast_sigmoid(float x) {
    return __fdividef(1.f, 1.f + __expf(-x));
}
__device__ __forceinline__ float fast_softplus(float x) {
    return fmaxf(x, 0.f) + __logf(1.f + __expf(-fabsf(x)));
}

// ---------------- K0: mega kernel — scan1 + atom split + weight splits ------
__global__ __launch_bounds__(256) void mega_split(const float* __restrict__ mask,
                                                  const float* __restrict__ atom,
                                                  const float* __restrict__ W) {
    const int b = blockIdx.x, tid = threadIdx.x;
    if (b < NSC) {
        __shared__ int sw[8];
        const int base = b * SCB;
        int c = 0;
        #pragma unroll
        for (int k = 0; k < 4; k++) {
            int i = base + tid*4 + k;
            if (i < NM) c += (mask[i] != 0.f);
        }
        int v = c;
        #pragma unroll
        for (int off = 16; off > 0; off >>= 1) v += __shfl_xor_sync(0xffffffffu, v, off);
        if ((tid & 31) == 0) sw[tid >> 5] = v;
        __syncthreads();
        if (tid == 0) {
            int t = 0;
            #pragma unroll
            for (int i = 0; i < 8; i++) t += sw[i];
            g_bcnt[b] = t;
        }
    } else if (b < NSC + 6250) {
        size_t t = (size_t)(b - NSC)*256 + tid;
        if (t < (size_t)NATOM*32) {
            float4 v = *(const float4*)&atom[t*4];
            __nv_bfloat16 h0,l0,h1,l1,h2,l2,h3,l3;
            bsplit(v.x, h0, l0); bsplit(v.y, h1, l1);
            bsplit(v.z, h2, l2); bsplit(v.w, h3, l3);
            ((uint2*)g_atHi)[t] = make_uint2(bpack(h0,h1), bpack(h2,h3));
            ((uint2*)g_atLo)[t] = make_uint2(bpack(l0,l1), bpack(l2,l3));
        }
    } else if (b < NSC + 6250 + 128) {
        int t = (b - NSC - 6250)*256 + tid;     // < 32768
        int by = t >> 12, kc = (t >> 10) & 3, n = (t >> 4) & 63, k2 = t & 15;
        int wrow = ((by >= 4) ? 128 : 0) + kc*32 + 2*k2;
        int col  = (by & 3)*64 + n;
        float x0 = W[(size_t)wrow*C2A + col];
        float x1 = W[(size_t)(wrow+1)*C2A + col];
        __nv_bfloat16 h0,l0,h1,l1;
        bsplit(x0, h0, l0); bsplit(x1, h1, l1);
        int o = ((by*4 + kc)*64 + n)*PA2 + 2*k2;
        *(uint32_t*)&g_wspHi[o] = bpack(h0, h1);
        *(uint32_t*)&g_wspLo[o] = bpack(l0, l1);
    } else {
        int t = (b - NSC - 6250 - 128)*256 + tid;   // < 8192
        int by = t >> 11, n = (t >> 5) & 63, k2 = t & 31;
        const float* W3 = W + 256*C2A;
        float x0 = W3[(size_t)(2*k2)  *C2A + by*64 + n];
        float x1 = W3[(size_t)(2*k2+1)*C2A + by*64 + n];
        __nv_bfloat16 h0,l0,h1,l1;
        bsplit(x0, h0, l0); bsplit(x1, h1, l1);
        int o = (by*64 + n)*PA + 2*k2;
        *(uint32_t*)&g_w3Hi[o] = bpack(h0, h1);
        *(uint32_t*)&g_w3Lo[o] = bpack(l0, l1);
    }
}

// ---------------- K1: top-level scan ----------------------------------------
__global__ __launch_bounds__(1024) void scan2() {
    __shared__ int s[1024];
    const int tid = threadIdx.x;
    int v = (tid < NSC) ? g_bcnt[tid] : 0;
    s[tid] = v;
    __syncthreads();
    for (int off = 1; off < 1024; off <<= 1) {
        int t = (tid >= off) ? s[tid - off] : 0;
        __syncthreads();
        s[tid] += t;
        __syncthreads();
    }
    if (tid < NSC) g_boff[tid] = s[tid] - v;
    if (tid == 1023) {
        g_nlive = s[1023];
        g_cntf  = (float)s[1023];
    }
}

// ---------------- K2: scan3 + p12 (merged; disjoint block ranges) -----------
__global__ __launch_bounds__(256) void scan3_p12(const float* __restrict__ mask) {
    __shared__ __align__(16) __nv_bfloat16 Ahi[128*PA2], Alo[128*PA2];
    __shared__ __align__(16) __nv_bfloat16 Bhi[64*PA2],  Blo[64*PA2];
    __shared__ int sS[256];

    const int bb = blockIdx.x, tid = threadIdx.x;
    if (bb < NSC) {
        const int base = bb * SCB;
        int c = 0;
        #pragma unroll
        for (int k = 0; k < 4; k++) {
            int i = base + tid*4 + k;
            if (i < NM) c += (mask[i] != 0.f);
        }
        sS[tid] = c;
        __syncthreads();
        for (int off = 1; off < 256; off <<= 1) {
            int t = (tid >= off) ? sS[tid - off] : 0;
            __syncthreads();
            sS[tid] += t;
            __syncthreads();
        }
        int p = g_boff[bb] + sS[tid] - c;
        #pragma unroll
        for (int k = 0; k < 4; k++) {
            int i = base + tid*4 + k;
            if (i < NM) {
                g_pos[i] = p;
                if (mask[i] != 0.f) { g_live[p] = i; p++; }
            }
        }
        return;
    }

    // ---- p12 ----
    const int lin = bb - NSC;
    const int bx = lin % P12_BX;
    const int by = lin / P12_BX;              // 0..7
    const int w = tid >> 5, lane = tid & 31, g = lane >> 2, tig = lane & 3;
    const int cb = (by & 3) * 64;
    __half* Cdst = (by >= 4) ? g_P2 : g_P1;
    const int m4 = lane >> 3, lr = lane & 7;

    const uint32_t aHi0 = (uint32_t)__cvta_generic_to_shared(Ahi)
                        + ((w*16 + (m4 & 1)*8 + lr) * PA2 + (m4 >> 1)*8) * 2;
    const uint32_t aLo0 = (uint32_t)__cvta_generic_to_shared(Alo)
                        + ((w*16 + (m4 & 1)*8 + lr) * PA2 + (m4 >> 1)*8) * 2;
    const uint32_t bHi0 = (uint32_t)__cvta_generic_to_shared(Bhi)
                        + (((m4 >> 1)*8 + lr) * PA2 + (m4 & 1)*8) * 2;
    const uint32_t bLo0 = (uint32_t)__cvta_generic_to_shared(Blo)
                        + (((m4 >> 1)*8 + lr) * PA2 + (m4 & 1)*8) * 2;

    float acc[8][4];
    #pragma unroll
    for (int j = 0; j < 8; j++) { acc[j][0]=0.f; acc[j][1]=0.f; acc[j][2]=0.f; acc[j][3]=0.f; }

    for (int kc = 0; kc < 4; kc++) {
        __syncthreads();
        for (int i = tid; i < 1024; i += 256) {
            int a = i >> 9;
            int j = i & 511; int r = j >> 2, u = j & 3;
            int gr = bx*128 + r;
            uint4 v = make_uint4(0, 0, 0, 0);
            if (gr < NATOM) {
                const __nv_bfloat16* src = a ? g_atLo : g_atHi;
                v = ((const uint4*)&src[(size_t)gr*128 + kc*32])[u];
            }
            uint4* dst = (uint4*)(a ? Alo : Ahi);
            dst[r*5 + u] = v;
        }
        {
            const uint4* sh = (const uint4*)&g_wspHi[(size_t)((by*4 + kc)*64) * PA2];
            const uint4* sl = (const uint4*)&g_wspLo[(size_t)((by*4 + kc)*64) * PA2];
            uint4* dh = (uint4*)Bhi;
            uint4* dl = (uint4*)Blo;
            for (int i = tid; i < 320; i += 256) { dh[i] = sh[i]; dl[i] = sl[i]; }
        }
        __syncthreads();

        #pragma unroll
        for (int ks = 0; ks < 2; ks++) {
            const uint32_t koff = ks * 16 * 2;
            uint32_t ah[4], al[4];
            ldsm_x4(aHi0 + koff, ah[0], ah[1], ah[2], ah[3]);
            ldsm_x4(aLo0 + koff, al[0], al[1], al[2], al[3]);
            #pragma unroll
            for (int jp = 0; jp < 4; jp++) {
                const uint32_t boff = (uint32_t)(jp*16*PA2*2) + koff;
                uint32_t bh0, bh1, bh2, bh3, bl0, bl1, bl2, bl3;
                ldsm_x4(bHi0 + boff, bh0, bh1, bh2, bh3);
                ldsm_x4(bLo0 + boff, bl0, bl1, bl2, bl3);
                mma_bf16(acc[2*jp],   ah, bh0, bh1);
                mma_bf16(acc[2*jp],   ah, bl0, bl1);
                mma_bf16(acc[2*jp],   al, bh0, bh1);
                mma_bf16(acc[2*jp+1], ah, bh2, bh3);
                mma_bf16(acc[2*jp+1], ah, bl2, bl3);
                mma_bf16(acc[2*jp+1], al, bh2, bh3);
            }
        }
    }

    const int gr0 = bx*128 + w*16 + g;
    const int gr1 = gr0 + 8;
    #pragma unroll
    for (int j = 0; j < 8; j++) {
        const int c = cb + j*8 + 2*tig;
        if (gr0 < NATOM) {
            __half2 h = __floats2half2_rn(acc[j][0], acc[j][1]);
            *(uint32_t*)&Cdst[(size_t)gr0*C2A + c] = *(uint32_t*)&h;
        }
        if (gr1 < NATOM) {
            __half2 h = __floats2half2_rn(acc[j][2], acc[j][3]);
            *(uint32_t*)&Cdst[(size_t)gr1*C2A + c] = *(uint32_t*)&h;
        }
    }
}

// ---------------- K3: gated GEMM over COMPACT live rows (fp16 out) ----------
#define SM_TOTAL 56704
__global__ __launch_bounds__(192) void gemm_gated_tc(const float* __restrict__ nbr,
                                                     const float* __restrict__ bfc,
                                                     const int*   __restrict__ idx) {
    extern __shared__ __align__(16) char smraw[];
    __nv_bfloat16* Ahi = (__nv_bfloat16*)(smraw);
    __nv_bfloat16* Alo = (__nv_bfloat16*)(smraw + 13824);
    __nv_bfloat16* Bhi = (__nv_bfloat16*)(smraw + 27648);
    __nv_bfloat16* Blo = (__nv_bfloat16*)(smraw + 36864);
    float* Cs   = (float*)(smraw + 27648);
    float* Red  = (float*)(smraw + 53760);
    float* biasS= (float*)(smraw + 55296);
    int*   liveS= (int*)  (smraw + 55552);
    int*   nbS  = (int*)  (smraw + 55936);
    int*   nS   = (int*)  (smraw + 56320);

    const int tid = threadIdx.x;
    const int bx = blockIdx.x;
    const int nlive = g_nlive;

    if (bx*96 >= nlive) {
        for (int i = tid; i < C2A; i += 192) {
            g_psum[(size_t)bx*C2A + i] = 0.f;
            g_psq [(size_t)bx*C2A + i] = 0.f;
        }
        return;
    }
    const int rem = min(96, nlive - bx*96);

    const int w = tid >> 5, lane = tid & 31, g = lane >> 2, tig = lane & 3;
    const int m4 = lane >> 3, lr = lane & 7;

    const uint32_t aHi0 = (uint32_t)__cvta_generic_to_shared(Ahi)
                        + ((w*16 + (m4 & 1)*8 + lr) * PA + (m4 >> 1)*8) * 2;
    const uint32_t aLo0 = (uint32_t)__cvta_generic_to_shared(Alo)
                        + ((w*16 + (m4 & 1)*8 + lr) * PA + (m4 >> 1)*8) * 2;
    const uint32_t bHi0 = (uint32_t)__cvta_generic_to_shared(Bhi)
                        + (((m4 >> 1)*8 + lr) * PA + (m4 & 1)*8) * 2;
    const uint32_t bLo0 = (uint32_t)__cvta_generic_to_shared(Blo)
                        + (((m4 >> 1)*8 + lr) * PA + (m4 & 1)*8) * 2;

    if (tid < 96) {
        int li = bx*96 + tid;
        int r = (li < nlive) ? g_live[li] : -1;
        liveS[tid] = r;
        nbS[tid] = (r >= 0) ? idx[r] : 0;
        nS[tid]  = (r >= 0) ? r / MNBR : 0;
    }
    __syncthreads();

    for (int i = tid; i < 96*16; i += 192) {
        int r = i >> 4, c4 = (i & 15) * 4;
        int src = liveS[r];
        float4 v = (src >= 0) ? *(const float4*)&nbr[(size_t)src*64 + c4]
                              : make_float4(0.f, 0.f, 0.f, 0.f);
        __nv_bfloat16 h0,l0,h1,l1,h2,l2,h3,l3;
        bsplit(v.x, h0, l0); bsplit(v.y, h1, l1);
        bsplit(v.z, h2, l2); bsplit(v.w, h3, l3);
        *(__nv_bfloat162*)&Ahi[r*PA + c4]     = __nv_bfloat162(h0, h1);
        *(__nv_bfloat162*)&Ahi[r*PA + c4 + 2] = __nv_bfloat162(h2, h3);
        *(__nv_bfloat162*)&Alo[r*PA + c4]     = __nv_bfloat162(l0, l1);
        *(__nv_bfloat162*)&Alo[r*PA + c4 + 2] = __nv_bfloat162(l2, l3);
    }

    const int q = tid & 15;
    const int rsub = tid >> 4;

    for (int by = 0; by < 4; by++) {
        __syncthreads();
        {
            const uint4* sh = (const uint4*)&g_w3Hi[(size_t)(by*64) * PA];
            const uint4* sl = (const uint4*)&g_w3Lo[(size_t)(by*64) * PA];
            uint4* dh = (uint4*)Bhi;
            uint4* dl = (uint4*)Blo;
            for (int i = tid; i < 576; i += 192) { dh[i] = sh[i]; dl[i] = sl[i]; }
        }
        if (tid < 16)
            *(float4*)&biasS[tid*4] = *(const float4*)&bfc[by*64 + tid*4];
        __syncthreads();

        float acc[8][4];
        #pragma unroll
        for (int j = 0; j < 8; j++) { acc[j][0]=0.f; acc[j][1]=0.f; acc[j][2]=0.f; acc[j][3]=0.f; }

        #pragma unroll
        for (int ks = 0; ks < 4; ks++) {
            const uint32_t koff = ks * 16 * 2;
            uint32_t ah[4], al[4];
            ldsm_x4(aHi0 + koff, ah[0], ah[1], ah[2], ah[3]);
            ldsm_x4(aLo0 + koff, al[0], al[1], al[2], al[3]);
            #pragma unroll
            for (int jp = 0; jp < 4; jp++) {
                const uint32_t boff = (uint32_t)(jp*16*PA*2) + koff;
                uint32_t bh0, bh1, bh2, bh3, bl0, bl1, bl2, bl3;
                ldsm_x4(bHi0 + boff, bh0, bh1, bh2, bh3);
                ldsm_x4(bLo0 + boff, bl0, bl1, bl2, bl3);
                mma_bf16(acc[2*jp],   ah, bh0, bh1);
                mma_bf16(acc[2*jp],   ah, bl0, bl1);
                mma_bf16(acc[2*jp],   al, bh0, bh1);
                mma_bf16(acc[2*jp+1], ah, bh2, bh3);
                mma_bf16(acc[2*jp+1], ah, bl2, bl3);
                mma_bf16(acc[2*jp+1], al, bh2, bh3);
            }
        }

        __syncthreads();
        {
            const int rl0 = w*16 + g, rl1 = rl0 + 8;
            #pragma unroll
            for (int j = 0; j < 8; j++) {
                const int c = j*8 + 2*tig;
                *(float2*)&Cs[rl0*PC + c] = make_float2(acc[j][0], acc[j][1]);
                *(float2*)&Cs[rl1*PC + c] = make_float2(acc[j][2], acc[j][3]);
            }
        }
        __syncthreads();

        float s0=0.f,s1=0.f,s2=0.f,s3=0.f, q0=0.f,q1=0.f,q2=0.f,q3=0.f;
        #pragma unroll
        for (int it = 0; it < 8; it++) {
            const int r = it*12 + rsub;
            if (r < rem) {
                float4 cv = *(const float4*)&Cs[r*PC + q*4];
                uint2 u1 = *(const uint2*)&g_P1[(size_t)nS[r]*C2A + by*64 + q*4];
                uint2 u2 = *(const uint2*)&g_P2[(size_t)nbS[r]*C2A + by*64 + q*4];
                float2 p1a = __half22float2(*(__half2*)&u1.x);
                float2 p1b = __half22float2(*(__half2*)&u1.y);
                float2 p2a = __half22float2(*(__half2*)&u2.x);
                float2 p2b = __half22float2(*(__half2*)&u2.y);
                float4 bb = *(const float4*)&biasS[q*4];
                float4 v;
                v.x = cv.x + p1a.x + p2a.x + bb.x;
                v.y = cv.y + p1a.y + p2a.y + bb.y;
                v.z = cv.z + p1b.x + p2b.x + bb.z;
                v.w = cv.w + p1b.y + p2b.y + bb.w;
                __half2 h01 = __floats2half2_rn(v.x, v.y);
                __half2 h23 = __floats2half2_rn(v.z, v.w);
                *(uint2*)&g_gated[((size_t)(bx*96 + r))*C2A + by*64 + q*4] =
                    make_uint2(*(uint32_t*)&h01, *(uint32_t*)&h23);
                s0 += v.x; s1 += v.y; s2 += v.z; s3 += v.w;
                q0 += v.x*v.x; q1 += v.y*v.y; q2 += v.z*v.z; q3 += v.w*v.w;
            }
        }
        s0 += __shfl_xor_sync(0xffffffffu, s0, 16);
        s1 += __shfl_xor_sync(0xffffffffu, s1, 16);
        s2 += __shfl_xor_sync(0xffffffffu, s2, 16);
        s3 += __shfl_xor_sync(0xffffffffu, s3, 16);
        q0 += __shfl_xor_sync(0xffffffffu, q0, 16);
        q1 += __shfl_xor_sync(0xffffffffu, q1, 16);
        q2 += __shfl_xor_sync(0xffffffffu, q2, 16);
        q3 += __shfl_xor_sync(0xffffffffu, q3, 16);

        if (lane < 16) {
            float* d = &Red[w*64 + lane*4];
            d[0]=s0; d[1]=s1; d[2]=s2; d[3]=s3;
        }
        __syncthreads();
        if (tid < 64) {
            float ts = 0.f;
            #pragma unroll
            for (int w2 = 0; w2 < 6; w2++) ts += Red[w2*64 + tid];
            g_psum[(size_t)bx*C2A + by*64 + tid] = ts;
        }
        __syncthreads();
        if (lane < 16) {
            float* d = &Red[w*64 + lane*4];
            d[0]=q0; d[1]=q1; d[2]=q2; d[3]=q3;
        }
        __syncthreads();
        if (tid < 64) {
            float tq = 0.f;
            #pragma unroll
            for (int w2 = 0; w2 < 6; w2++) tq += Red[w2*64 + tid];
            g_psq[(size_t)bx*C2A + by*64 + tid] = tq;
        }
    }
}

// ---------------- K4: reduce partials -> column sums ------------------------
__global__ __launch_bounds__(256) void reduce_cols() {
    __shared__ float sm[256];
    const int b = blockIdx.x, tid = threadIdx.x;
    float s = 0.f;
    if (b < 256) {
        for (int i = tid; i < GTILES; i += 256) s += g_psum[(size_t)i * C2A + b];
    } else {
        int c = b - 256;
        for (int i = tid; i < GTILES; i += 256) s += g_psq[(size_t)i * C2A + c];
    }
    sm[tid] = s; __syncthreads();
    for (int off = 128; off > 0; off >>= 1) {
        if (tid < off) sm[tid] += sm[tid + off];
        __syncthreads();
    }
    if (tid == 0) {
        if (b < 256) g_colsum[b] = sm[0];
        else         g_colsq[b - 256] = sm[0];
    }
}

// ---------------- K5: BN1-apply + gate + per-atom sum (32 atoms/block) ------
__global__ __launch_bounds__(256) void gate_apply(const float* __restrict__ gamma1,
                                                  const float* __restrict__ beta1) {
    __shared__ float s1s[C2A], s1b[C2A];
    __shared__ int sA[GA_ATOMS + 1];
    const int tid = threadIdx.x;
    const int bx = blockIdx.x;

    {
        float cnt = g_cntf;
        float mean = g_colsum[tid] / cnt;
        float var  = g_colsq[tid] / cnt - mean * mean;
        float sc   = rsqrtf(var + EPSV) * gamma1[tid];
        s1s[tid] = sc;
        s1b[tid] = beta1[tid] - mean * sc;
    }
    if (tid <= GA_ATOMS) {
        int i9 = (bx*GA_ATOMS + tid) * MNBR;
        sA[tid] = (i9 < NM) ? g_pos[i9] : g_nlive;
    }
    __syncthreads();

    const int c2 = (tid & 63) * 2;
    const int ag = tid >> 6;
    const float sf0 = s1s[c2],     sf1 = s1s[c2+1];
    const float bf0 = s1b[c2],     bf1 = s1b[c2+1];
    const float sc0 = s1s[128+c2], sc1 = s1s[128+c2+1];
    const float bc0 = s1b[128+c2], bc1 = s1b[128+c2+1];

    #pragma unroll
    for (int aa = 0; aa < GA_ATOMS/4; aa++) {
        const int a = aa*4 + ag;
        const int atom = bx*GA_ATOMS + a;
        if (atom < NATOM) {
            const int start = sA[a], end = sA[a+1];
            float sx = 0.f, sy = 0.f;
            for (int row = start; row < end; row++) {
                float2 f = __half22float2(*(const __half2*)&g_gated[(size_t)row*C2A + c2]);
                float2 c = __half22float2(*(const __half2*)&g_gated[(size_t)row*C2A + 128 + c2]);
                float fx = f.x * sf0 + bf0, fy = f.y * sf1 + bf1;
                float cx = c.x * sc0 + bc0, cy = c.y * sc1 + bc1;
                sx += fast_sigmoid(fx) * fast_softplus(cx);
                sy += fast_sigmoid(fy) * fast_softplus(cy);
            }
            *(float2*)&g_ns[(size_t)atom*AFEA + c2] = make_float2(sx, sy);
        }
    }
}

// ---------------- K6: BN2 stats + affine ------------------------------------
__global__ __launch_bounds__(256) void reduce2(const float* __restrict__ gamma2,
                                               const float* __restrict__ beta2) {
    __shared__ float ss[256], sq[256];
    const int c = blockIdx.x, tid = threadIdx.x;
    float s = 0.f, q = 0.f;
    for (int r = tid; r < NATOM; r += 256) {
        float v = g_ns[(size_t)r * AFEA + c];
        s += v; q += v * v;
    }
    ss[tid] = s; sq[tid] = q; __syncthreads();
    for (int off = 128; off > 0; off >>= 1) {
        if (tid < off) { ss[tid] += ss[tid + off]; sq[tid] += sq[tid + off]; }
        __syncthreads();
    }
    if (tid == 0) {
        float mean = ss[0] / (float)NATOM;
        float var  = sq[0] / (float)NATOM - mean * mean;
        float sc   = rsqrtf(var + EPSV) * gamma2[c];
        g_scale2[c] = sc;
        g_shift2[c] = beta2[c] - mean * sc;
    }
}

// ---------------- K7: out = softplus(atom + BN2(nbr_sumed)) -----------------
__global__ __launch_bounds__(256) void out_k(const float* __restrict__ atom,
                                             float* __restrict__ out) {
    int i = blockIdx.x * 256 + threadIdx.x;
    if (i < NATOM * AFEA) {
        int c = i & 127;
        float v = atom[i] + g_ns[i] * g_scale2[c] + g_shift2[c];
        out[i] = fmaxf(v, 0.f) + __logf(1.f + __expf(-fabsf(v)));
    }
}

// ---------------- launch ----------------------------------------------------
extern "C" void kernel_launch(void* const* d_in, const int* in_sizes, int n_in,
                              void* d_out, int out_size) {
    const float* atom  = (const float*)d_in[0];
    const float* nbr   = (const float*)d_in[1];
    const int*   idx   = (const int*)  d_in[2];
    const float* mask  = (const float*)d_in[3];
    const float* W     = (const float*)d_in[4];
    const float* bfc   = (const float*)d_in[5];
    const float* g1    = (const float*)d_in[6];
    const float* b1    = (const float*)d_in[7];
    const float* g2    = (const float*)d_in[8];
    const float* b2    = (const float*)d_in[9];
    float* out = (float*)d_out;

    cudaFuncSetAttribute(gemm_gated_tc, cudaFuncAttributeMaxDynamicSharedMemorySize, SM_TOTAL);

    mega_split   <<<NSC + 6250 + 128 + 32, 256>>>(mask, atom, W);        // 0
    scan2        <<<1, 1024>>>();                                        // 1
    scan3_p12    <<<NSC + P12_BX*8, 256>>>(mask);                        // 2
    gemm_gated_tc<<<GTILES, 192, SM_TOTAL>>>(nbr, bfc, idx);             // 3 (profiled)
    reduce_cols  <<<512, 256>>>();                                       // 4
    gate_apply   <<<(NATOM + GA_ATOMS - 1)/GA_ATOMS, 256>>>(g1, b1);     // 5
    reduce2      <<<AFEA, 256>>>(g2, b2);                                // 6
    out_k        <<<(NATOM * AFEA + 255) / 256, 256>>>(atom, out);       // 7
}

// round 14
// speedup vs baseline: 3.0825x; 1.0812x over previous
#include <cuda_runtime.h>
#include <cuda_bf16.h>
#include <cuda_fp16.h>
#include <math.h>
#include <stdint.h>

// Problem constants
#define NATOM 50000
#define MNBR  12
#define AFEA  128
#define NBRF  64
#define NM    (NATOM*MNBR)     // 600000
#define C2A   256
#define EPSV  1e-5f
#define GTILES (NM/96)         // 6250 row tiles of 96
#define SCB   1024
#define NSC   ((NM + SCB - 1) / SCB)   // 586
#define GA_ATOMS 32
#define PA2 40
#define P12_BX ((NATOM + 127)/128)     // 391

// ---------------- scratch (device globals) ----------------------------------
__device__ __half g_P1[(size_t)NATOM*C2A];
__device__ __half g_P2[(size_t)NATOM*C2A];
__device__ __half g_gated[(size_t)NM*C2A];
__device__ float  g_psum[(size_t)GTILES*C2A];
__device__ float  g_psq [(size_t)GTILES*C2A];
__device__ float  g_ns[NATOM*AFEA];
__device__ float  g_colsum[C2A];
__device__ float  g_colsq[C2A];
__device__ float  g_cntf;
__device__ int    g_nlive;
__device__ int    g_bcnt[NSC];
__device__ int    g_boff[NSC];
__device__ int    g_pos[NM];
__device__ int    g_live[NM];
__device__ float  g_scale2[AFEA], g_shift2[AFEA];
// pre-split operands
__device__ __align__(16) __nv_bfloat16 g_atHi[(size_t)NATOM*128];
__device__ __align__(16) __nv_bfloat16 g_atLo[(size_t)NATOM*128];
__device__ __align__(16) __nv_bfloat16 g_wspHi[8*4*64*PA2];          // p12 B image
__device__ __align__(16) __nv_bfloat16 g_wspLo[8*4*64*PA2];
__device__ __align__(16) char g_w3Hi[4*8192];   // gated B image, SW128 swizzled
__device__ __align__(16) char g_w3Lo[4*8192];

// ---------------- helpers ----------------------------------------------------
__device__ __forceinline__ void bsplit(float x, __nv_bfloat16& h, __nv_bfloat16& l) {
    h = __float2bfloat16(x);
    l = __float2bfloat16(x - __bfloat162float(h));
}
__device__ __forceinline__ uint32_t bpack(__nv_bfloat16 a, __nv_bfloat16 b) {
    __nv_bfloat162 t(a, b);
    return *(uint32_t*)&t;
}
__device__ __forceinline__ uint32_t swz128(uint32_t o) {
    return o ^ ((o >> 3) & 0x70);
}
__device__ __forceinline__ void mma_bf16(float* c, const uint32_t* a,
                                         uint32_t b0, uint32_t b1) {
    asm volatile(
        "mma.sync.aligned.m16n8k16.row.col.f32.bf16.bf16.f32 "
        "{%0,%1,%2,%3}, {%4,%5,%6,%7}, {%8,%9}, {%0,%1,%2,%3};\n"
        : "+f"(c[0]), "+f"(c[1]), "+f"(c[2]), "+f"(c[3])
        : "r"(a[0]), "r"(a[1]), "r"(a[2]), "r"(a[3]), "r"(b0), "r"(b1));
}
__device__ __forceinline__ void ldsm_x4(uint32_t addr, uint32_t& r0, uint32_t& r1,
                                        uint32_t& r2, uint32_t& r3) {
    asm volatile("ldmatrix.sync.aligned.m8n8.x4.shared.b16 {%0,%1,%2,%3}, [%4];"
                 : "=r"(r0), "=r"(r1), "=r"(r2), "=r"(r3) : "r"(addr));
}
__device__ __forceinline__ float fast_sigmoid(float x) {
    return __fdividef(1.f, 1.f + __expf(-x));
}
__device__ __forceinline__ float fast_softplus(float x) {
    return fmaxf(x, 0.f) + __logf(1.f + __expf(-fabsf(x)));
}

// ---------------- K0: mega kernel — scan1 + atom split + weight splits ------
__global__ __launch_bounds__(256) void mega_split(const float* __restrict__ mask,
                                                  const float* __restrict__ atom,
                                                  const float* __restrict__ W) {
    const int b = blockIdx.x, tid = threadIdx.x;
    if (b < NSC) {
        __shared__ int sw[8];
        const int base = b * SCB;
        int c = 0;
        #pragma unroll
        for (int k = 0; k < 4; k++) {
            int i = base + tid*4 + k;
            if (i < NM) c += (mask[i] != 0.f);
        }
        int v = c;
        #pragma unroll
        for (int off = 16; off > 0; off >>= 1) v += __shfl_xor_sync(0xffffffffu, v, off);
        if ((tid & 31) == 0) sw[tid >> 5] = v;
        __syncthreads();
        if (tid == 0) {
            int t = 0;
            #pragma unroll
            for (int i = 0; i < 8; i++) t += sw[i];
            g_bcnt[b] = t;
        }
    } else if (b < NSC + 6250) {
        size_t t = (size_t)(b - NSC)*256 + tid;
        if (t < (size_t)NATOM*32) {
            float4 v = *(const float4*)&atom[t*4];
            __nv_bfloat16 h0,l0,h1,l1,h2,l2,h3,l3;
            bsplit(v.x, h0, l0); bsplit(v.y, h1, l1);
            bsplit(v.z, h2, l2); bsplit(v.w, h3, l3);
            ((uint2*)g_atHi)[t] = make_uint2(bpack(h0,h1), bpack(h2,h3));
            ((uint2*)g_atLo)[t] = make_uint2(bpack(l0,l1), bpack(l2,l3));
        }
    } else if (b < NSC + 6250 + 128) {
        int t = (b - NSC - 6250)*256 + tid;     // < 32768
        int by = t >> 12, kc = (t >> 10) & 3, n = (t >> 4) & 63, k2 = t & 15;
        int wrow = ((by >= 4) ? 128 : 0) + kc*32 + 2*k2;
        int col  = (by & 3)*64 + n;
        float x0 = W[(size_t)wrow*C2A + col];
        float x1 = W[(size_t)(wrow+1)*C2A + col];
        __nv_bfloat16 h0,l0,h1,l1;
        bsplit(x0, h0, l0); bsplit(x1, h1, l1);
        int o = ((by*4 + kc)*64 + n)*PA2 + 2*k2;
        *(uint32_t*)&g_wspHi[o] = bpack(h0, h1);
        *(uint32_t*)&g_wspLo[o] = bpack(l0, l1);
    } else {
        // W3 swizzled image: t -> (by, n, c8); 8 k-values per thread (16B)
        int t = (b - NSC - 6250 - 128)*256 + tid;   // < 2048
        int by = t >> 9, n = (t >> 3) & 63, c8 = t & 7;
        const float* W3 = W + 256*C2A;
        uint32_t hi[4], lo[4];
        #pragma unroll
        for (int j = 0; j < 4; j++) {
            float x0 = W3[(size_t)(c8*8 + 2*j)  *C2A + by*64 + n];
            float x1 = W3[(size_t)(c8*8 + 2*j+1)*C2A + by*64 + n];
            __nv_bfloat16 h0,l0,h1,l1;
            bsplit(x0, h0, l0); bsplit(x1, h1, l1);
            hi[j] = bpack(h0, h1);
            lo[j] = bpack(l0, l1);
        }
        uint32_t off = swz128((uint32_t)(n*128 + c8*16));
        *(uint4*)&g_w3Hi[by*8192 + off] = make_uint4(hi[0], hi[1], hi[2], hi[3]);
        *(uint4*)&g_w3Lo[by*8192 + off] = make_uint4(lo[0], lo[1], lo[2], lo[3]);
    }
}

// ---------------- K1: top-level scan ----------------------------------------
__global__ __launch_bounds__(1024) void scan2() {
    __shared__ int s[1024];
    const int tid = threadIdx.x;
    int v = (tid < NSC) ? g_bcnt[tid] : 0;
    s[tid] = v;
    __syncthreads();
    for (int off = 1; off < 1024; off <<= 1) {
        int t = (tid >= off) ? s[tid - off] : 0;
        __syncthreads();
        s[tid] += t;
        __syncthreads();
    }
    if (tid < NSC) g_boff[tid] = s[tid] - v;
    if (tid == 1023) {
        g_nlive = s[1023];
        g_cntf  = (float)s[1023];
    }
}

// ---------------- K2: scan3 + p12 (merged; disjoint block ranges) -----------
__global__ __launch_bounds__(256, 4) void scan3_p12(const float* __restrict__ mask) {
    __shared__ __align__(16) __nv_bfloat16 Ahi[128*PA2], Alo[128*PA2];
    __shared__ __align__(16) __nv_bfloat16 Bhi[64*PA2],  Blo[64*PA2];
    __shared__ int sS[256];

    const int bb = blockIdx.x, tid = threadIdx.x;
    if (bb < NSC) {
        const int base = bb * SCB;
        int c = 0;
        #pragma unroll
        for (int k = 0; k < 4; k++) {
            int i = base + tid*4 + k;
            if (i < NM) c += (mask[i] != 0.f);
        }
        sS[tid] = c;
        __syncthreads();
        for (int off = 1; off < 256; off <<= 1) {
            int t = (tid >= off) ? sS[tid - off] : 0;
            __syncthreads();
            sS[tid] += t;
            __syncthreads();
        }
        int p = g_boff[bb] + sS[tid] - c;
        #pragma unroll
        for (int k = 0; k < 4; k++) {
            int i = base + tid*4 + k;
            if (i < NM) {
                g_pos[i] = p;
                if (mask[i] != 0.f) { g_live[p] = i; p++; }
            }
        }
        return;
    }

    // ---- p12 ----
    const int lin = bb - NSC;
    const int bx = lin % P12_BX;
    const int by = lin / P12_BX;              // 0..7
    const int w = tid >> 5, lane = tid & 31, g = lane >> 2, tig = lane & 3;
    const int cb = (by & 3) * 64;
    __half* Cdst = (by >= 4) ? g_P2 : g_P1;
    const int m4 = lane >> 3, lr = lane & 7;

    const uint32_t aHi0 = (uint32_t)__cvta_generic_to_shared(Ahi)
                        + ((w*16 + (m4 & 1)*8 + lr) * PA2 + (m4 >> 1)*8) * 2;
    const uint32_t aLo0 = (uint32_t)__cvta_generic_to_shared(Alo)
                        + ((w*16 + (m4 & 1)*8 + lr) * PA2 + (m4 >> 1)*8) * 2;
    const uint32_t bHi0 = (uint32_t)__cvta_generic_to_shared(Bhi)
                        + (((m4 >> 1)*8 + lr) * PA2 + (m4 & 1)*8) * 2;
    const uint32_t bLo0 = (uint32_t)__cvta_generic_to_shared(Blo)
                        + (((m4 >> 1)*8 + lr) * PA2 + (m4 & 1)*8) * 2;

    float acc[8][4];
    #pragma unroll
    for (int j = 0; j < 8; j++) { acc[j][0]=0.f; acc[j][1]=0.f; acc[j][2]=0.f; acc[j][3]=0.f; }

    for (int kc = 0; kc < 4; kc++) {
        __syncthreads();
        for (int i = tid; i < 1024; i += 256) {
            int a = i >> 9;
            int j = i & 511; int r = j >> 2, u = j & 3;
            int gr = bx*128 + r;
            uint4 v = make_uint4(0, 0, 0, 0);
            if (gr < NATOM) {
                const __nv_bfloat16* src = a ? g_atLo : g_atHi;
                v = ((const uint4*)&src[(size_t)gr*128 + kc*32])[u];
            }
            uint4* dst = (uint4*)(a ? Alo : Ahi);
            dst[r*5 + u] = v;
        }
        {
            const uint4* sh = (const uint4*)&g_wspHi[(size_t)((by*4 + kc)*64) * PA2];
            const uint4* sl = (const uint4*)&g_wspLo[(size_t)((by*4 + kc)*64) * PA2];
            uint4* dh = (uint4*)Bhi;
            uint4* dl = (uint4*)Blo;
            for (int i = tid; i < 320; i += 256) { dh[i] = sh[i]; dl[i] = sl[i]; }
        }
        __syncthreads();

        #pragma unroll
        for (int ks = 0; ks < 2; ks++) {
            const uint32_t koff = ks * 16 * 2;
            uint32_t ah[4], al[4];
            ldsm_x4(aHi0 + koff, ah[0], ah[1], ah[2], ah[3]);
            ldsm_x4(aLo0 + koff, al[0], al[1], al[2], al[3]);
            #pragma unroll
            for (int jp = 0; jp < 4; jp++) {
                const uint32_t boff = (uint32_t)(jp*16*PA2*2) + koff;
                uint32_t bh0, bh1, bh2, bh3, bl0, bl1, bl2, bl3;
                ldsm_x4(bHi0 + boff, bh0, bh1, bh2, bh3);
                ldsm_x4(bLo0 + boff, bl0, bl1, bl2, bl3);
                mma_bf16(acc[2*jp],   ah, bh0, bh1);
                mma_bf16(acc[2*jp],   ah, bl0, bl1);
                mma_bf16(acc[2*jp],   al, bh0, bh1);
                mma_bf16(acc[2*jp+1], ah, bh2, bh3);
                mma_bf16(acc[2*jp+1], ah, bl2, bl3);
                mma_bf16(acc[2*jp+1], al, bh2, bh3);
            }
        }
    }

    const int gr0 = bx*128 + w*16 + g;
    const int gr1 = gr0 + 8;
    #pragma unroll
    for (int j = 0; j < 8; j++) {
        const int c = cb + j*8 + 2*tig;
        if (gr0 < NATOM) {
            __half2 h = __floats2half2_rn(acc[j][0], acc[j][1]);
            *(uint32_t*)&Cdst[(size_t)gr0*C2A + c] = *(uint32_t*)&h;
        }
        if (gr1 < NATOM) {
            __half2 h = __floats2half2_rn(acc[j][2], acc[j][3]);
            *(uint32_t*)&Cdst[(size_t)gr1*C2A + c] = *(uint32_t*)&h;
        }
    }
}

// ---------------- K3: gated GEMM, SW128 smem, fp16 Cs, 5 blocks/SM ----------
// dyn smem (bytes):
//   Ahi 0..12288, Alo 12288..24576
//   union{ Bhi 24576..32768, Blo 32768..40960 ; CsH (fp16, pitch 68) 24576..37632 }
//   Red 40960..42496, biasS 42496..42752, liveS 42752..43136,
//   nbS 43136..43520, nS 43520..43904
#define SM_TOTAL 43904
__global__ __launch_bounds__(192, 5) void gemm_gated_tc(const float* __restrict__ nbr,
                                                        const float* __restrict__ bfc,
                                                        const int*   __restrict__ idx) {
    extern __shared__ __align__(128) char smraw[];
    char*  AhiB = smraw;
    char*  AloB = smraw + 12288;
    __half* CsH = (__half*)(smraw + 24576);
    float* Red  = (float*)(smraw + 40960);
    float* biasS= (float*)(smraw + 42496);
    int*   liveS= (int*)  (smraw + 42752);
    int*   nbS  = (int*)  (smraw + 43136);
    int*   nS   = (int*)  (smraw + 43520);
    const uint32_t smbase = (uint32_t)__cvta_generic_to_shared(smraw);

    const int tid = threadIdx.x;
    const int bx = blockIdx.x;
    const int nlive = g_nlive;

    if (bx*96 >= nlive) {
        for (int i = tid; i < C2A; i += 192) {
            g_psum[(size_t)bx*C2A + i] = 0.f;
            g_psq [(size_t)bx*C2A + i] = 0.f;
        }
        return;
    }
    const int rem = min(96, nlive - bx*96);

    const int w = tid >> 5, lane = tid & 31, g = lane >> 2, tig = lane & 3;
    const int m4 = lane >> 3, lr = lane & 7;

    // ldmatrix SW128 addressing. A: row = w*16 + (m4&1)*8 + lr, col = (m4>>1)*16B
    //                            B: row = (m4>>1)*8 + lr,       col = (m4&1)*16B
    // swizzle XOR for both = (row&7)<<4 = lr<<4, applied to the column bits.
    const uint32_t xorv   = (uint32_t)(lr << 4);
    const uint32_t aCoff0 = (uint32_t)((m4 >> 1) * 16);
    const uint32_t bCoff0 = (uint32_t)((m4 & 1) * 16);
    const uint32_t aRow   = (uint32_t)((w*16 + (m4 & 1)*8 + lr) * 128);
    const uint32_t aHiB0  = smbase + 0     + aRow;
    const uint32_t aLoB0  = smbase + 12288 + aRow;
    const uint32_t bRow0  = smbase + 24576 + (uint32_t)(((m4 >> 1)*8 + lr) * 128);

    if (tid < 96) {
        int li = bx*96 + tid;
        int r = (li < nlive) ? g_live[li] : -1;
        liveS[tid] = r;
        nbS[tid] = (r >= 0) ? idx[r] : 0;
        nS[tid]  = (r >= 0) ? r / MNBR : 0;
    }
    __syncthreads();

    // A tile: gather live rows, split, store SW128-swizzled (16B chunks)
    for (int i = tid; i < 96*8; i += 192) {
        int r = i >> 3, ch = i & 7;
        int src = liveS[r];
        float4 v0, v1;
        if (src >= 0) {
            v0 = *(const float4*)&nbr[(size_t)src*64 + ch*8];
            v1 = *(const float4*)&nbr[(size_t)src*64 + ch*8 + 4];
        } else {
            v0 = make_float4(0.f,0.f,0.f,0.f); v1 = v0;
        }
        __nv_bfloat16 h[8], l[8];
        bsplit(v0.x, h[0], l[0]); bsplit(v0.y, h[1], l[1]);
        bsplit(v0.z, h[2], l[2]); bsplit(v0.w, h[3], l[3]);
        bsplit(v1.x, h[4], l[4]); bsplit(v1.y, h[5], l[5]);
        bsplit(v1.z, h[6], l[6]); bsplit(v1.w, h[7], l[7]);
        uint32_t off = swz128((uint32_t)(r*128 + ch*16));
        *(uint4*)(AhiB + off) = make_uint4(bpack(h[0],h[1]), bpack(h[2],h[3]),
                                           bpack(h[4],h[5]), bpack(h[6],h[7]));
        *(uint4*)(AloB + off) = make_uint4(bpack(l[0],l[1]), bpack(l[2],l[3]),
                                           bpack(l[4],l[5]), bpack(l[6],l[7]));
    }

    const int q = tid & 15;
    const int rsub = tid >> 4;

    for (int by = 0; by < 4; by++) {
        __syncthreads();   // prior epilogue done; Cs/B region free
        {   // stage B: 16B copies of swizzled image (8KB hi + 8KB lo)
            const uint4* sh = (const uint4*)(g_w3Hi + by*8192);
            const uint4* sl = (const uint4*)(g_w3Lo + by*8192);
            uint4* dh = (uint4*)(smraw + 24576);
            uint4* dl = (uint4*)(smraw + 32768);
            #pragma unroll
            for (int i = 0; i < 3; i++) {
                int o = tid + i*192;
                if (o < 512) { dh[o] = sh[o]; dl[o] = sl[o]; }
            }
        }
        if (tid < 16)
            *(float4*)&biasS[tid*4] = *(const float4*)&bfc[by*64 + tid*4];
        __syncthreads();

        float acc[8][4];
        #pragma unroll
        for (int j = 0; j < 8; j++) { acc[j][0]=0.f; acc[j][1]=0.f; acc[j][2]=0.f; acc[j][3]=0.f; }

        #pragma unroll
        for (int ks = 0; ks < 4; ks++) {
            const uint32_t kxa = (aCoff0 + ks*32) ^ xorv;
            const uint32_t kxb = (bCoff0 + ks*32) ^ xorv;
            uint32_t ah[4], al[4];
            ldsm_x4(aHiB0 + kxa, ah[0], ah[1], ah[2], ah[3]);
            ldsm_x4(aLoB0 + kxa, al[0], al[1], al[2], al[3]);
            #pragma unroll
            for (int jp = 0; jp < 4; jp++) {
                const uint32_t bb = bRow0 + (uint32_t)(jp*2048) + kxb;
                uint32_t bh0, bh1, bh2, bh3, bl0, bl1, bl2, bl3;
                ldsm_x4(bb,        bh0, bh1, bh2, bh3);
                ldsm_x4(bb + 8192, bl0, bl1, bl2, bl3);
                mma_bf16(acc[2*jp],   ah, bh0, bh1);
                mma_bf16(acc[2*jp],   ah, bl0, bl1);
                mma_bf16(acc[2*jp],   al, bh0, bh1);
                mma_bf16(acc[2*jp+1], ah, bh2, bh3);
                mma_bf16(acc[2*jp+1], ah, bl2, bl3);
                mma_bf16(acc[2*jp+1], al, bh2, bh3);
            }
        }

        __syncthreads();   // B reads done; region becomes CsH
        {
            const int rl0 = w*16 + g, rl1 = rl0 + 8;
            #pragma unroll
            for (int j = 0; j < 8; j++) {
                const int c = j*8 + 2*tig;
                __half2 h0 = __floats2half2_rn(acc[j][0], acc[j][1]);
                __half2 h1 = __floats2half2_rn(acc[j][2], acc[j][3]);
                *(__half2*)&CsH[rl0*68 + c] = h0;
                *(__half2*)&CsH[rl1*68 + c] = h1;
            }
        }
        __syncthreads();

        float s0=0.f,s1=0.f,s2=0.f,s3=0.f, q0=0.f,q1=0.f,q2=0.f,q3=0.f;
        #pragma unroll
        for (int it = 0; it < 8; it++) {
            const int r = it*12 + rsub;
            if (r < rem) {
                uint2 uc = *(const uint2*)&CsH[r*68 + q*4];
                float2 c01 = __half22float2(*(__half2*)&uc.x);
                float2 c23 = __half22float2(*(__half2*)&uc.y);
                uint2 u1 = *(const uint2*)&g_P1[(size_t)nS[r]*C2A + by*64 + q*4];
                uint2 u2 = *(const uint2*)&g_P2[(size_t)nbS[r]*C2A + by*64 + q*4];
                float2 p1a = __half22float2(*(__half2*)&u1.x);
                float2 p1b = __half22float2(*(__half2*)&u1.y);
                float2 p2a = __half22float2(*(__half2*)&u2.x);
                float2 p2b = __half22float2(*(__half2*)&u2.y);
                float4 bb = *(const float4*)&biasS[q*4];
                float4 v;
                v.x = c01.x + p1a.x + p2a.x + bb.x;
                v.y = c01.y + p1a.y + p2a.y + bb.y;
                v.z = c23.x + p1b.x + p2b.x + bb.z;
                v.w = c23.y + p1b.y + p2b.y + bb.w;
                __half2 h01 = __floats2half2_rn(v.x, v.y);
                __half2 h23 = __floats2half2_rn(v.z, v.w);
                *(uint2*)&g_gated[((size_t)(bx*96 + r))*C2A + by*64 + q*4] =
                    make_uint2(*(uint32_t*)&h01, *(uint32_t*)&h23);
                s0 += v.x; s1 += v.y; s2 += v.z; s3 += v.w;
                q0 += v.x*v.x; q1 += v.y*v.y; q2 += v.z*v.z; q3 += v.w*v.w;
            }
        }
        s0 += __shfl_xor_sync(0xffffffffu, s0, 16);
        s1 += __shfl_xor_sync(0xffffffffu, s1, 16);
        s2 += __shfl_xor_sync(0xffffffffu, s2, 16);
        s3 += __shfl_xor_sync(0xffffffffu, s3, 16);
        q0 += __shfl_xor_sync(0xffffffffu, q0, 16);
        q1 += __shfl_xor_sync(0xffffffffu, q1, 16);
        q2 += __shfl_xor_sync(0xffffffffu, q2, 16);
        q3 += __shfl_xor_sync(0xffffffffu, q3, 16);

        if (lane < 16) {
            float* d = &Red[w*64 + lane*4];
            d[0]=s0; d[1]=s1; d[2]=s2; d[3]=s3;
        }
        __syncthreads();
        if (tid < 64) {
            float ts = 0.f;
            #pragma unroll
            for (int w2 = 0; w2 < 6; w2++) ts += Red[w2*64 + tid];
            g_psum[(size_t)bx*C2A + by*64 + tid] = ts;
        }
        __syncthreads();
        if (lane < 16) {
            float* d = &Red[w*64 + lane*4];
            d[0]=q0; d[1]=q1; d[2]=q2; d[3]=q3;
        }
        __syncthreads();
        if (tid < 64) {
            float tq = 0.f;
            #pragma unroll
            for (int w2 = 0; w2 < 6; w2++) tq += Red[w2*64 + tid];
            g_psq[(size_t)bx*C2A + by*64 + tid] = tq;
        }
    }
}

// ---------------- K4: reduce partials -> column sums ------------------------
__global__ __launch_bounds__(256) void reduce_cols() {
    __shared__ float sm[256];
    const int b = blockIdx.x, tid = threadIdx.x;
    float s = 0.f;
    if (b < 256) {
        for (int i = tid; i < GTILES; i += 256) s += g_psum[(size_t)i * C2A + b];
    } else {
        int c = b - 256;
        for (int i = tid; i < GTILES; i += 256) s += g_psq[(size_t)i * C2A + c];
    }
    sm[tid] = s; __syncthreads();
    for (int off = 128; off > 0; off >>= 1) {
        if (tid < off) sm[tid] += sm[tid + off];
        __syncthreads();
    }
    if (tid == 0) {
        if (b < 256) g_colsum[b] = sm[0];
        else         g_colsq[b - 256] = sm[0];
    }
}

// ---------------- K5: BN1-apply + gate + per-atom sum (32 atoms/block) ------
__global__ __launch_bounds__(256) void gate_apply(const float* __restrict__ gamma1,
                                                  const float* __restrict__ beta1) {
    __shared__ float s1s[C2A], s1b[C2A];
    __shared__ int sA[GA_ATOMS + 1];
    const int tid = threadIdx.x;
    const int bx = blockIdx.x;

    {
        float cnt = g_cntf;
        float mean = g_colsum[tid] / cnt;
        float var  = g_colsq[tid] / cnt - mean * mean;
        float sc   = rsqrtf(var + EPSV) * gamma1[tid];
        s1s[tid] = sc;
        s1b[tid] = beta1[tid] - mean * sc;
    }
    if (tid <= GA_ATOMS) {
        int i9 = (bx*GA_ATOMS + tid) * MNBR;
        sA[tid] = (i9 < NM) ? g_pos[i9] : g_nlive;
    }
    __syncthreads();

    const int c2 = (tid & 63) * 2;
    const int ag = tid >> 6;
    const float sf0 = s1s[c2],     sf1 = s1s[c2+1];
    const float bf0 = s1b[c2],     bf1 = s1b[c2+1];
    const float sc0 = s1s[128+c2], sc1 = s1s[128+c2+1];
    const float bc0 = s1b[128+c2], bc1 = s1b[128+c2+1];

    #pragma unroll
    for (int aa = 0; aa < GA_ATOMS/4; aa++) {
        const int a = aa*4 + ag;
        const int atom = bx*GA_ATOMS + a;
        if (atom < NATOM) {
            const int start = sA[a], end = sA[a+1];
            float sx = 0.f, sy = 0.f;
            for (int row = start; row < end; row++) {
                float2 f = __half22float2(*(const __half2*)&g_gated[(size_t)row*C2A + c2]);
                float2 c = __half22float2(*(const __half2*)&g_gated[(size_t)row*C2A + 128 + c2]);
                float fx = f.x * sf0 + bf0, fy = f.y * sf1 + bf1;
                float cx = c.x * sc0 + bc0, cy = c.y * sc1 + bc1;
                sx += fast_sigmoid(fx) * fast_softplus(cx);
                sy += fast_sigmoid(fy) * fast_softplus(cy);
            }
            *(float2*)&g_ns[(size_t)atom*AFEA + c2] = make_float2(sx, sy);
        }
    }
}

// ---------------- K6: BN2 stats + affine ------------------------------------
__global__ __launch_bounds__(256) void reduce2(const float* __restrict__ gamma2,
                                               const float* __restrict__ beta2) {
    __shared__ float ss[256], sq[256];
    const int c = blockIdx.x, tid = threadIdx.x;
    float s = 0.f, q = 0.f;
    for (int r = tid; r < NATOM; r += 256) {
        float v = g_ns[(size_t)r * AFEA + c];
        s += v; q += v * v;
    }
    ss[tid] = s; sq[tid] = q; __syncthreads();
    for (int off = 128; off > 0; off >>= 1) {
        if (tid < off) { ss[tid] += ss[tid + off]; sq[tid] += sq[tid + off]; }
        __syncthreads();
    }
    if (tid == 0) {
        float mean = ss[0] / (float)NATOM;
        float var  = sq[0] / (float)NATOM - mean * mean;
        float sc   = rsqrtf(var + EPSV) * gamma2[c];
        g_scale2[c] = sc;
        g_shift2[c] = beta2[c] - mean * sc;
    }
}

// ---------------- K7: out = softplus(atom + BN2(nbr_sumed)) -----------------
__global__ __launch_bounds__(256) void out_k(const float* __restrict__ atom,
                                             float* __restrict__ out) {
    int i = blockIdx.x * 256 + threadIdx.x;
    if (i < NATOM * AFEA) {
        int c = i & 127;
        float v = atom[i] + g_ns[i] * g_scale2[c] + g_shift2[c];
        out[i] = fmaxf(v, 0.f) + __logf(1.f + __expf(-fabsf(v)));
    }
}

// ---------------- launch ----------------------------------------------------
extern "C" void kernel_launch(void* const* d_in, const int* in_sizes, int n_in,
                              void* d_out, int out_size) {
    const float* atom  = (const float*)d_in[0];
    const float* nbr   = (const float*)d_in[1];
    const int*   idx   = (const int*)  d_in[2];
    const float* mask  = (const float*)d_in[3];
    const float* W     = (const float*)d_in[4];
    const float* bfc   = (const float*)d_in[5];
    const float* g1    = (const float*)d_in[6];
    const float* b1    = (const float*)d_in[7];
    const float* g2    = (const float*)d_in[8];
    const float* b2    = (const float*)d_in[9];
    float* out = (float*)d_out;

    cudaFuncSetAttribute(gemm_gated_tc, cudaFuncAttributeMaxDynamicSharedMemorySize, SM_TOTAL);

    mega_split   <<<NSC + 6250 + 128 + 8, 256>>>(mask, atom, W);         // 0
    scan2        <<<1, 1024>>>();                                        // 1
    scan3_p12    <<<NSC + P12_BX*8, 256>>>(mask);                        // 2
    gemm_gated_tc<<<GTILES, 192, SM_TOTAL>>>(nbr, bfc, idx);             // 3 (profiled)
    reduce_cols  <<<512, 256>>>();                                       // 4
    gate_apply   <<<(NATOM + GA_ATOMS - 1)/GA_ATOMS, 256>>>(g1, b1);     // 5
    reduce2      <<<AFEA, 256>>>(g2, b2);                                // 6
    out_k        <<<(NATOM * AFEA + 255) / 256, 256>>>(atom, out);       // 7
}